// round 1
// baseline (speedup 1.0000x reference)
#include <cuda_runtime.h>
#include <math.h>

#define V_SZ 32000
#define D_SZ 512
#define S_SZ 2048
#define H_SZ 8
#define HS_SZ 64
#define B_SZ 4
#define M_SZ (B_SZ * S_SZ)   // 8192 rows

// ---------------- scratch (device globals; no runtime allocation) ----------
__device__ float g_x[M_SZ * D_SZ];                       // embeddings  [B*S, D]
__device__ float g_q[B_SZ * H_SZ * S_SZ * HS_SZ];        // [B,H,S,HS]
__device__ float g_k[B_SZ * H_SZ * S_SZ * HS_SZ];
__device__ float g_v[B_SZ * H_SZ * S_SZ * HS_SZ];
__device__ float g_attn[M_SZ * D_SZ];                    // concat heads [B*S, D]
__device__ float g_rowloss[M_SZ];

// ---------------- 1) embeddings -------------------------------------------
__global__ void embed_kernel(const int* __restrict__ index,
                             const float* __restrict__ tok_emb,
                             const float* __restrict__ pos_emb) {
    int m = blockIdx.x;               // 0..M-1
    int s = m % S_SZ;
    int tok = index[m];
    const float4* te = (const float4*)(tok_emb + (size_t)tok * D_SZ);
    const float4* pe = (const float4*)(pos_emb + (size_t)s * D_SZ);
    float4* xo = (float4*)(g_x + (size_t)m * D_SZ);
    int i = threadIdx.x;              // 128 threads, 128 float4
    float4 a = te[i], b = pe[i];
    a.x += b.x; a.y += b.y; a.z += b.z; a.w += b.w;
    xo[i] = a;
}

// ---------------- 2) QKV projections ---------------------------------------
// grid: (M/64, H, 3), block 256. Computes 64 rows x 64 cols (one head).
__global__ void qkv_kernel(const float* __restrict__ Wq,
                           const float* __restrict__ Wk,
                           const float* __restrict__ Wv) {
    __shared__ float Xs[16][64];
    __shared__ float Ws[16][64];

    int row0 = blockIdx.x * 64;
    int h = blockIdx.y;
    int which = blockIdx.z;
    const float* W = (which == 0 ? Wq : which == 1 ? Wk : Wv) + (size_t)h * D_SZ * HS_SZ;
    float* out = (which == 0 ? g_q : which == 1 ? g_k : g_v);

    int tid = threadIdx.x;
    int tm = (tid / 16) * 4;
    int tn = (tid % 16) * 4;

    float acc[4][4];
#pragma unroll
    for (int i = 0; i < 4; i++)
#pragma unroll
        for (int j = 0; j < 4; j++) acc[i][j] = 0.f;

    int xr = tid / 4;
    int xk = (tid % 4) * 4;
    int wk = tid / 16;
    int we = (tid % 16) * 4;

    for (int k0 = 0; k0 < D_SZ; k0 += 16) {
        float4 xv = *(const float4*)&g_x[(size_t)(row0 + xr) * D_SZ + k0 + xk];
        Xs[xk + 0][xr] = xv.x;
        Xs[xk + 1][xr] = xv.y;
        Xs[xk + 2][xr] = xv.z;
        Xs[xk + 3][xr] = xv.w;
        *(float4*)&Ws[wk][we] = *(const float4*)&W[(size_t)(k0 + wk) * HS_SZ + we];
        __syncthreads();
#pragma unroll
        for (int kk = 0; kk < 16; kk++) {
            float a[4], b[4];
#pragma unroll
            for (int i = 0; i < 4; i++) a[i] = Xs[kk][tm + i];
#pragma unroll
            for (int j = 0; j < 4; j++) b[j] = Ws[kk][tn + j];
#pragma unroll
            for (int i = 0; i < 4; i++)
#pragma unroll
                for (int j = 0; j < 4; j++) acc[i][j] += a[i] * b[j];
        }
        __syncthreads();
    }

#pragma unroll
    for (int i = 0; i < 4; i++) {
        int m = row0 + tm + i;
        int b = m / S_SZ, s = m % S_SZ;
        size_t base = ((size_t)(b * H_SZ + h) * S_SZ + s) * HS_SZ;
        float4 r = make_float4(acc[i][0], acc[i][1], acc[i][2], acc[i][3]);
        *(float4*)&out[base + tn] = r;
    }
}

// ---------------- 3) causal attention (flash-style, fp32) ------------------
// grid: (S/64, H, B), block 64. Each thread owns one query row.
__global__ void attn_kernel() {
    __shared__ float Ksh[32][68];
    __shared__ float Vsh[32][68];

    int qt = blockIdx.x, h = blockIdx.y, b = blockIdx.z;
    int t = threadIdx.x;
    size_t base = (size_t)(b * H_SZ + h) * S_SZ * HS_SZ;
    int qrow = qt * 64 + t;

    float qreg[64];
#pragma unroll
    for (int e = 0; e < 64; e += 4) {
        float4 qv = *(const float4*)&g_q[base + (size_t)qrow * HS_SZ + e];
        qreg[e] = qv.x; qreg[e + 1] = qv.y; qreg[e + 2] = qv.z; qreg[e + 3] = qv.w;
    }
    float o[64];
#pragma unroll
    for (int e = 0; e < 64; e++) o[e] = 0.f;
    float mval = -1e30f, l = 0.f;

    int ntiles = qt * 2 + 2;  // 32-wide key tiles covering keys <= qt*64+63
    for (int kt = 0; kt < ntiles; kt++) {
        int krow0 = kt * 32;
        // cooperative load: 32 rows x 64 = 512 float4, 64 threads x 8
#pragma unroll
        for (int it = 0; it < 8; it++) {
            int f = it * 64 + t;
            int r = f >> 4;
            int e4 = (f & 15) * 4;
            *(float4*)&Ksh[r][e4] = *(const float4*)&g_k[base + (size_t)(krow0 + r) * HS_SZ + e4];
            *(float4*)&Vsh[r][e4] = *(const float4*)&g_v[base + (size_t)(krow0 + r) * HS_SZ + e4];
        }
        __syncthreads();

        float sreg[32];
        float tmax = -1e30f;
#pragma unroll
        for (int j = 0; j < 32; j++) {
            float s0 = 0.f, s1 = 0.f, s2 = 0.f, s3 = 0.f;
#pragma unroll
            for (int d = 0; d < 64; d += 4) {
                s0 += qreg[d + 0] * Ksh[j][d + 0];
                s1 += qreg[d + 1] * Ksh[j][d + 1];
                s2 += qreg[d + 2] * Ksh[j][d + 2];
                s3 += qreg[d + 3] * Ksh[j][d + 3];
            }
            float s = ((s0 + s1) + (s2 + s3)) * 0.125f;  // HS^-0.5
            if (krow0 + j > qrow) s = -1e30f;
            sreg[j] = s;
            tmax = fmaxf(tmax, s);
        }
        float newm = fmaxf(mval, tmax);
        float factor = __expf(mval - newm);
        l *= factor;
#pragma unroll
        for (int e = 0; e < 64; e++) o[e] *= factor;
#pragma unroll
        for (int j = 0; j < 32; j++) {
            float p = __expf(sreg[j] - newm);
            l += p;
#pragma unroll
            for (int e = 0; e < 64; e++) o[e] += p * Vsh[j][e];
        }
        mval = newm;
        __syncthreads();
    }

    float inv = 1.f / l;
    int bq = b * S_SZ + qrow;
    float* dst = g_attn + (size_t)bq * D_SZ + h * HS_SZ;
#pragma unroll
    for (int e = 0; e < 64; e += 4) {
        float4 r = make_float4(o[e] * inv, o[e + 1] * inv, o[e + 2] * inv, o[e + 3] * inv);
        *(float4*)&dst[e] = r;
    }
}

// ---------------- 4) logits GEMM: [M,512] x [512,V] -> d_out ---------------
// 128x128 tile, BK=8, 256 threads, 8x8 per thread
__global__ void logits_gemm_kernel(const float* __restrict__ Wout,
                                   float* __restrict__ C) {
    __shared__ float As[8][128];
    __shared__ float Bs[8][128];

    int col0 = blockIdx.x * 128;
    int row0 = blockIdx.y * 128;
    int tid = threadIdx.x;
    int tm = (tid / 16) * 8;
    int tn = (tid % 16) * 8;

    float acc[8][8];
#pragma unroll
    for (int i = 0; i < 8; i++)
#pragma unroll
        for (int j = 0; j < 8; j++) acc[i][j] = 0.f;

    int ar = tid / 2;
    int ak = (tid % 2) * 4;
    int bk = tid / 32;
    int bc = (tid % 32) * 4;

    for (int k0 = 0; k0 < D_SZ; k0 += 8) {
        float4 av = *(const float4*)&g_attn[(size_t)(row0 + ar) * D_SZ + k0 + ak];
        As[ak + 0][ar] = av.x;
        As[ak + 1][ar] = av.y;
        As[ak + 2][ar] = av.z;
        As[ak + 3][ar] = av.w;
        *(float4*)&Bs[bk][bc] = *(const float4*)&Wout[(size_t)(k0 + bk) * V_SZ + col0 + bc];
        __syncthreads();
#pragma unroll
        for (int kk = 0; kk < 8; kk++) {
            float a[8], bb[8];
            float4 a0 = *(float4*)&As[kk][tm];
            float4 a1 = *(float4*)&As[kk][tm + 4];
            float4 b0 = *(float4*)&Bs[kk][tn];
            float4 b1 = *(float4*)&Bs[kk][tn + 4];
            a[0] = a0.x; a[1] = a0.y; a[2] = a0.z; a[3] = a0.w;
            a[4] = a1.x; a[5] = a1.y; a[6] = a1.z; a[7] = a1.w;
            bb[0] = b0.x; bb[1] = b0.y; bb[2] = b0.z; bb[3] = b0.w;
            bb[4] = b1.x; bb[5] = b1.y; bb[6] = b1.z; bb[7] = b1.w;
#pragma unroll
            for (int i = 0; i < 8; i++)
#pragma unroll
                for (int j = 0; j < 8; j++) acc[i][j] += a[i] * bb[j];
        }
        __syncthreads();
    }

#pragma unroll
    for (int i = 0; i < 8; i++) {
        size_t off = (size_t)(row0 + tm + i) * V_SZ + col0 + tn;
        float4 r0 = make_float4(acc[i][0], acc[i][1], acc[i][2], acc[i][3]);
        float4 r1 = make_float4(acc[i][4], acc[i][5], acc[i][6], acc[i][7]);
        *(float4*)&C[off] = r0;
        *(float4*)&C[off + 4] = r1;
    }
}

// ---------------- 5) per-row logsumexp + target pick ----------------------
__global__ void lse_kernel(const float* __restrict__ logits,
                           const int* __restrict__ target) {
    __shared__ float red[256];
    int m = blockIdx.x;
    const float* row = logits + (size_t)m * V_SZ;
    int tid = threadIdx.x;

    float mx = -1e30f;
    for (int i = tid; i < V_SZ; i += 256) mx = fmaxf(mx, row[i]);
    red[tid] = mx;
    __syncthreads();
    for (int s = 128; s > 0; s >>= 1) {
        if (tid < s) red[tid] = fmaxf(red[tid], red[tid + s]);
        __syncthreads();
    }
    float rowmax = red[0];
    __syncthreads();

    float sum = 0.f;
    for (int i = tid; i < V_SZ; i += 256) sum += __expf(row[i] - rowmax);
    red[tid] = sum;
    __syncthreads();
    for (int s = 128; s > 0; s >>= 1) {
        if (tid < s) red[tid] += red[tid + s];
        __syncthreads();
    }
    if (tid == 0) {
        float lse = rowmax + logf(red[0]);
        g_rowloss[m] = lse - row[target[m]];
    }
}

// ---------------- 6) deterministic mean reduction --------------------------
__global__ void loss_reduce_kernel(float* __restrict__ out, int loss_idx) {
    __shared__ float red[256];
    int tid = threadIdx.x;
    float s = 0.f;
    for (int i = tid; i < M_SZ; i += 256) s += g_rowloss[i];
    red[tid] = s;
    __syncthreads();
    for (int k = 128; k > 0; k >>= 1) {
        if (tid < k) red[tid] += red[tid + k];
        __syncthreads();
    }
    if (tid == 0) out[loss_idx] = red[0] / (float)M_SZ;
}

// ---------------- launch ----------------------------------------------------
extern "C" void kernel_launch(void* const* d_in, const int* in_sizes, int n_in,
                              void* d_out, int out_size) {
    const int* index = (const int*)d_in[0];
    const int* target = (const int*)d_in[1];
    const float* tok_emb = (const float*)d_in[2];
    const float* pos_emb = (const float*)d_in[3];
    const float* Wq = (const float*)d_in[4];
    const float* Wk = (const float*)d_in[5];
    const float* Wv = (const float*)d_in[6];
    const float* Wout = (const float*)d_in[7];
    float* out = (float*)d_out;

    embed_kernel<<<M_SZ, 128>>>(index, tok_emb, pos_emb);
    qkv_kernel<<<dim3(M_SZ / 64, H_SZ, 3), 256>>>(Wq, Wk, Wv);
    attn_kernel<<<dim3(S_SZ / 64, H_SZ, B_SZ), 64>>>();
    logits_gemm_kernel<<<dim3(V_SZ / 128, M_SZ / 128), 256>>>(Wout, out);
    lse_kernel<<<M_SZ, 256>>>(out, target);
    loss_reduce_kernel<<<1, 256>>>(out, out_size - 1);
}

// round 3
// speedup vs baseline: 1.6207x; 1.6207x over previous
#include <cuda_runtime.h>
#include <cuda_bf16.h>
#include <math.h>
#include <cstdint>

#define V_SZ 32000
#define D_SZ 512
#define S_SZ 2048
#define H_SZ 8
#define HS_SZ 64
#define B_SZ 4
#define M_SZ (B_SZ * S_SZ)   // 8192 rows

// ---------------- scratch (device globals; no runtime allocation) ----------
__device__ float g_x[M_SZ * D_SZ];                       // embeddings  [B*S, D]
__device__ float g_q[B_SZ * H_SZ * S_SZ * HS_SZ];        // [B,H,S,HS]
__device__ float g_k[B_SZ * H_SZ * S_SZ * HS_SZ];
__device__ float g_v[B_SZ * H_SZ * S_SZ * HS_SZ];
__device__ float g_attn[M_SZ * D_SZ];                    // concat heads [B*S, D]
__device__ float g_rowloss[M_SZ];

// bf16-split operands for the tensor-core logits GEMM
__device__ __nv_bfloat16 g_a_hi[M_SZ * D_SZ];            // [8192, 512]
__device__ __nv_bfloat16 g_a_lo[M_SZ * D_SZ];
__device__ __nv_bfloat16 g_bt_hi[(size_t)V_SZ * D_SZ];   // W_out^T  [32000, 512]
__device__ __nv_bfloat16 g_bt_lo[(size_t)V_SZ * D_SZ];

// =================== PTX helpers (portable, compute_103-legal) =============
__device__ __forceinline__ uint32_t smem_u32(const void* p) {
    uint32_t a;
    asm("{ .reg .u64 t; cvta.to.shared.u64 t, %1; cvt.u32.u64 %0, t; }" : "=r"(a) : "l"(p));
    return a;
}
__device__ __forceinline__ void cp16(uint32_t dst, const void* src) {
    asm volatile("cp.async.cg.shared.global [%0], [%1], 16;" :: "r"(dst), "l"(src));
}
__device__ __forceinline__ void cp_commit() {
    asm volatile("cp.async.commit_group;" ::: "memory");
}
__device__ __forceinline__ void cp_wait1() {
    asm volatile("cp.async.wait_group 1;" ::: "memory");
}
__device__ __forceinline__ void cp_wait0() {
    asm volatile("cp.async.wait_group 0;" ::: "memory");
}
__device__ __forceinline__ void ldsm_x4(uint32_t* r, uint32_t addr) {
    asm volatile("ldmatrix.sync.aligned.m8n8.x4.shared.b16 {%0,%1,%2,%3}, [%4];"
                 : "=r"(r[0]), "=r"(r[1]), "=r"(r[2]), "=r"(r[3]) : "r"(addr));
}
__device__ __forceinline__ void mma16816(float* c, const uint32_t* a, const uint32_t* b) {
    asm volatile("mma.sync.aligned.m16n8k16.row.col.f32.bf16.bf16.f32 "
                 "{%0,%1,%2,%3}, {%4,%5,%6,%7}, {%8,%9}, {%0,%1,%2,%3};"
                 : "+f"(c[0]), "+f"(c[1]), "+f"(c[2]), "+f"(c[3])
                 : "r"(a[0]), "r"(a[1]), "r"(a[2]), "r"(a[3]),
                   "r"(b[0]), "r"(b[1]));
}

// ---------------- 1) embeddings -------------------------------------------
__global__ void embed_kernel(const int* __restrict__ index,
                             const float* __restrict__ tok_emb,
                             const float* __restrict__ pos_emb) {
    int m = blockIdx.x;
    int s = m % S_SZ;
    int tok = index[m];
    const float4* te = (const float4*)(tok_emb + (size_t)tok * D_SZ);
    const float4* pe = (const float4*)(pos_emb + (size_t)s * D_SZ);
    float4* xo = (float4*)(g_x + (size_t)m * D_SZ);
    int i = threadIdx.x;
    float4 a = te[i], b = pe[i];
    a.x += b.x; a.y += b.y; a.z += b.z; a.w += b.w;
    xo[i] = a;
}

// ---------------- 2) QKV projections ---------------------------------------
__global__ void qkv_kernel(const float* __restrict__ Wq,
                           const float* __restrict__ Wk,
                           const float* __restrict__ Wv) {
    __shared__ float Xs[16][64];
    __shared__ float Ws[16][64];

    int row0 = blockIdx.x * 64;
    int h = blockIdx.y;
    int which = blockIdx.z;
    const float* W = (which == 0 ? Wq : which == 1 ? Wk : Wv) + (size_t)h * D_SZ * HS_SZ;
    float* out = (which == 0 ? g_q : which == 1 ? g_k : g_v);

    int tid = threadIdx.x;
    int tm = (tid / 16) * 4;
    int tn = (tid % 16) * 4;

    float acc[4][4];
#pragma unroll
    for (int i = 0; i < 4; i++)
#pragma unroll
        for (int j = 0; j < 4; j++) acc[i][j] = 0.f;

    int xr = tid / 4;
    int xk = (tid % 4) * 4;
    int wk = tid / 16;
    int we = (tid % 16) * 4;

    for (int k0 = 0; k0 < D_SZ; k0 += 16) {
        float4 xv = *(const float4*)&g_x[(size_t)(row0 + xr) * D_SZ + k0 + xk];
        Xs[xk + 0][xr] = xv.x;
        Xs[xk + 1][xr] = xv.y;
        Xs[xk + 2][xr] = xv.z;
        Xs[xk + 3][xr] = xv.w;
        *(float4*)&Ws[wk][we] = *(const float4*)&W[(size_t)(k0 + wk) * HS_SZ + we];
        __syncthreads();
#pragma unroll
        for (int kk = 0; kk < 16; kk++) {
            float a[4], b[4];
#pragma unroll
            for (int i = 0; i < 4; i++) a[i] = Xs[kk][tm + i];
#pragma unroll
            for (int j = 0; j < 4; j++) b[j] = Ws[kk][tn + j];
#pragma unroll
            for (int i = 0; i < 4; i++)
#pragma unroll
                for (int j = 0; j < 4; j++) acc[i][j] += a[i] * b[j];
        }
        __syncthreads();
    }

#pragma unroll
    for (int i = 0; i < 4; i++) {
        int m = row0 + tm + i;
        int b = m / S_SZ, s = m % S_SZ;
        size_t base = ((size_t)(b * H_SZ + h) * S_SZ + s) * HS_SZ;
        float4 r = make_float4(acc[i][0], acc[i][1], acc[i][2], acc[i][3]);
        *(float4*)&out[base + tn] = r;
    }
}

// ---------------- 3) causal attention (flash-style, fp32) ------------------
__global__ void attn_kernel() {
    __shared__ float Ksh[32][68];
    __shared__ float Vsh[32][68];

    int qt = blockIdx.x, h = blockIdx.y, b = blockIdx.z;
    int t = threadIdx.x;
    size_t base = (size_t)(b * H_SZ + h) * S_SZ * HS_SZ;
    int qrow = qt * 64 + t;

    float qreg[64];
#pragma unroll
    for (int e = 0; e < 64; e += 4) {
        float4 qv = *(const float4*)&g_q[base + (size_t)qrow * HS_SZ + e];
        qreg[e] = qv.x; qreg[e + 1] = qv.y; qreg[e + 2] = qv.z; qreg[e + 3] = qv.w;
    }
    float o[64];
#pragma unroll
    for (int e = 0; e < 64; e++) o[e] = 0.f;
    float mval = -1e30f, l = 0.f;

    int ntiles = qt * 2 + 2;
    for (int kt = 0; kt < ntiles; kt++) {
        int krow0 = kt * 32;
#pragma unroll
        for (int it = 0; it < 8; it++) {
            int f = it * 64 + t;
            int r = f >> 4;
            int e4 = (f & 15) * 4;
            *(float4*)&Ksh[r][e4] = *(const float4*)&g_k[base + (size_t)(krow0 + r) * HS_SZ + e4];
            *(float4*)&Vsh[r][e4] = *(const float4*)&g_v[base + (size_t)(krow0 + r) * HS_SZ + e4];
        }
        __syncthreads();

        float sreg[32];
        float tmax = -1e30f;
#pragma unroll
        for (int j = 0; j < 32; j++) {
            float s0 = 0.f, s1 = 0.f, s2 = 0.f, s3 = 0.f;
#pragma unroll
            for (int d = 0; d < 64; d += 4) {
                s0 += qreg[d + 0] * Ksh[j][d + 0];
                s1 += qreg[d + 1] * Ksh[j][d + 1];
                s2 += qreg[d + 2] * Ksh[j][d + 2];
                s3 += qreg[d + 3] * Ksh[j][d + 3];
            }
            float s = ((s0 + s1) + (s2 + s3)) * 0.125f;
            if (krow0 + j > qrow) s = -1e30f;
            sreg[j] = s;
            tmax = fmaxf(tmax, s);
        }
        float newm = fmaxf(mval, tmax);
        float factor = __expf(mval - newm);
        l *= factor;
#pragma unroll
        for (int e = 0; e < 64; e++) o[e] *= factor;
#pragma unroll
        for (int j = 0; j < 32; j++) {
            float p = __expf(sreg[j] - newm);
            l += p;
#pragma unroll
            for (int e = 0; e < 64; e++) o[e] += p * Vsh[j][e];
        }
        mval = newm;
        __syncthreads();
    }

    float inv = 1.f / l;
    int bq = b * S_SZ + qrow;
    float* dst = g_attn + (size_t)bq * D_SZ + h * HS_SZ;
#pragma unroll
    for (int e = 0; e < 64; e += 4) {
        float4 r = make_float4(o[e] * inv, o[e + 1] * inv, o[e + 2] * inv, o[e + 3] * inv);
        *(float4*)&dst[e] = r;
    }
}

// ---------------- 4a) A split: g_attn fp32 -> bf16 hi/lo -------------------
__global__ void convA_kernel() {
    int m = blockIdx.x;
    int t = threadIdx.x;  // 64 threads, 8 floats each
    const float* src = g_attn + (size_t)m * D_SZ + t * 8;
    __nv_bfloat16* dh = g_a_hi + (size_t)m * D_SZ + t * 8;
    __nv_bfloat16* dl = g_a_lo + (size_t)m * D_SZ + t * 8;
#pragma unroll
    for (int i = 0; i < 8; i++) {
        float x = src[i];
        __nv_bfloat16 hi = __float2bfloat16(x);
        __nv_bfloat16 lo = __float2bfloat16(x - __bfloat162float(hi));
        dh[i] = hi;
        dl[i] = lo;
    }
}

// ---------------- 4b) B transpose+split: Wout [512,V] -> [V,512] bf16 ------
__global__ void convB_kernel(const float* __restrict__ W) {
    __shared__ float tbuf[32][33];
    int v0 = blockIdx.x * 32, k0 = blockIdx.y * 32;
    int tx = threadIdx.x & 31;
    int ty4 = (threadIdx.x >> 5) * 4;
#pragma unroll
    for (int j = 0; j < 4; j++)
        tbuf[ty4 + j][tx] = W[(size_t)(k0 + ty4 + j) * V_SZ + v0 + tx];
    __syncthreads();
#pragma unroll
    for (int j = 0; j < 4; j++) {
        float x = tbuf[tx][ty4 + j];
        __nv_bfloat16 hi = __float2bfloat16(x);
        __nv_bfloat16 lo = __float2bfloat16(x - __bfloat162float(hi));
        size_t o = (size_t)(v0 + ty4 + j) * D_SZ + k0 + tx;
        g_bt_hi[o] = hi;
        g_bt_lo[o] = lo;
    }
}

// ---------------- 4c) mma.sync bf16-split logits GEMM ----------------------
// C[8192, 32000] = sum over 3 passes (Ah*Bh, Ah*Bl, Al*Bh), fp32 accum in regs.
// Tile 128x128, BK=32, 256 threads (8 warps, 2x4), warp tile 64x32.
// SMEM rows use 80B pitch -> 8 consecutive rows start on distinct bank groups
// (row advance = 20 banks mod 32), so ldmatrix.x4 is conflict-free.
#define BM 128
#define BN 128
#define BKQ 32
#define PITCH 80
#define BUFB (BM * PITCH)     // 10240 bytes per operand buffer
#define NITER 48              // 3 passes * (512/32)

__global__ void __launch_bounds__(256, 2) gemm_mma_kernel(float* __restrict__ C) {
    __shared__ __align__(16) char sA[2][BUFB];
    __shared__ __align__(16) char sB[2][BUFB];

    const int tid = threadIdx.x;
    const int lane = tid & 31;
    const int wid = tid >> 5;
    const int row0 = blockIdx.y * BM;
    const int col0 = blockIdx.x * BN;
    const int m_base = (wid & 1) * 64;
    const int n_base = (wid >> 1) * 32;

    const uint32_t sa = smem_u32(sA);
    const uint32_t sbm = smem_u32(sB);
    // ldmatrix row addresses (lane-dependent part)
    const uint32_t a_lm = sa + (uint32_t)((m_base + (lane & 15)) * PITCH + (lane >> 4) * 16);
    const uint32_t b_lm = sbm + (uint32_t)((n_base + (lane & 15)) * PITCH + (lane >> 4) * 16);

    // cp.async chunk assignment: 512 chunks of 16B per operand tile
    const int c0r = tid >> 1;                 // rows 0..127 (it 0 -> 0..127? no: see below)
    float acc[4][4][4];
#pragma unroll
    for (int i = 0; i < 4; i++)
#pragma unroll
        for (int j = 0; j < 4; j++)
#pragma unroll
            for (int k = 0; k < 4; k++) acc[i][j][k] = 0.f;
    (void)c0r;

    auto load_tile = [&](int kt, int buf) {
        int p = kt >> 4;                     // pass
        int kk = (kt & 15) * BKQ;            // k offset in D
        const __nv_bfloat16* asrc = (p < 2) ? g_a_hi : g_a_lo;
        const __nv_bfloat16* bsrc = (p == 1) ? g_bt_lo : g_bt_hi;
#pragma unroll
        for (int it = 0; it < 2; it++) {
            int idx = it * 256 + tid;        // 0..511
            int r = idx >> 2;                // row 0..127
            int c = idx & 3;                 // 16B chunk 0..3
            uint32_t dsto = (uint32_t)(r * PITCH + c * 16);
            cp16(sa + buf * BUFB + dsto,
                 asrc + (size_t)(row0 + r) * D_SZ + kk + c * 8);
            cp16(sbm + buf * BUFB + dsto,
                 bsrc + (size_t)(col0 + r) * D_SZ + kk + c * 8);
        }
    };

    load_tile(0, 0);
    cp_commit();

    for (int kt = 0; kt < NITER; kt++) {
        int buf = kt & 1;
        if (kt + 1 < NITER) {
            load_tile(kt + 1, buf ^ 1);
            cp_commit();
            cp_wait1();
        } else {
            cp_wait0();
        }
        __syncthreads();

        uint32_t abase = a_lm + (uint32_t)(buf * BUFB);
        uint32_t bbase = b_lm + (uint32_t)(buf * BUFB);
#pragma unroll
        for (int s = 0; s < 2; s++) {        // two k16 steps per BK=32
            uint32_t afr[4][4];
            uint32_t bfr[2][4];
#pragma unroll
            for (int mf = 0; mf < 4; mf++)
                ldsm_x4(afr[mf], abase + (uint32_t)(mf * 16 * PITCH + s * 32));
#pragma unroll
            for (int nf2 = 0; nf2 < 2; nf2++)
                ldsm_x4(bfr[nf2], bbase + (uint32_t)(nf2 * 16 * PITCH + s * 32));

#pragma unroll
            for (int mf = 0; mf < 4; mf++) {
#pragma unroll
                for (int nf = 0; nf < 4; nf++) {
                    uint32_t b2[2];
                    b2[0] = bfr[nf >> 1][nf & 1];          // k0-7 half
                    b2[1] = bfr[nf >> 1][(nf & 1) + 2];    // k8-15 half
                    mma16816(acc[mf][nf], afr[mf], b2);
                }
            }
        }
        __syncthreads();
    }

    // epilogue: direct float2 stores
    const int rbase = row0 + m_base + (lane >> 2);
    const int cbase = col0 + n_base + (lane & 3) * 2;
#pragma unroll
    for (int mf = 0; mf < 4; mf++) {
#pragma unroll
        for (int nf = 0; nf < 4; nf++) {
            size_t o0 = (size_t)(rbase + mf * 16) * V_SZ + cbase + nf * 8;
            size_t o1 = o0 + (size_t)8 * V_SZ;
            *(float2*)(C + o0) = make_float2(acc[mf][nf][0], acc[mf][nf][1]);
            *(float2*)(C + o1) = make_float2(acc[mf][nf][2], acc[mf][nf][3]);
        }
    }
}

// ---------------- 5) per-row logsumexp + target pick ----------------------
__global__ void lse_kernel(const float* __restrict__ logits,
                           const int* __restrict__ target) {
    __shared__ float red[256];
    int m = blockIdx.x;
    const float* row = logits + (size_t)m * V_SZ;
    int tid = threadIdx.x;

    float mx = -1e30f;
    for (int i = tid; i < V_SZ; i += 256) mx = fmaxf(mx, row[i]);
    red[tid] = mx;
    __syncthreads();
    for (int s = 128; s > 0; s >>= 1) {
        if (tid < s) red[tid] = fmaxf(red[tid], red[tid + s]);
        __syncthreads();
    }
    float rowmax = red[0];
    __syncthreads();

    float sum = 0.f;
    for (int i = tid; i < V_SZ; i += 256) sum += __expf(row[i] - rowmax);
    red[tid] = sum;
    __syncthreads();
    for (int s = 128; s > 0; s >>= 1) {
        if (tid < s) red[tid] += red[tid + s];
        __syncthreads();
    }
    if (tid == 0) {
        float lse = rowmax + logf(red[0]);
        g_rowloss[m] = lse - row[target[m]];
    }
}

// ---------------- 6) deterministic mean reduction --------------------------
__global__ void loss_reduce_kernel(float* __restrict__ out, int loss_idx) {
    __shared__ float red[256];
    int tid = threadIdx.x;
    float s = 0.f;
    for (int i = tid; i < M_SZ; i += 256) s += g_rowloss[i];
    red[tid] = s;
    __syncthreads();
    for (int k = 128; k > 0; k >>= 1) {
        if (tid < k) red[tid] += red[tid + k];
        __syncthreads();
    }
    if (tid == 0) out[loss_idx] = red[0] / (float)M_SZ;
}

// ---------------- launch ----------------------------------------------------
extern "C" void kernel_launch(void* const* d_in, const int* in_sizes, int n_in,
                              void* d_out, int out_size) {
    const int* index = (const int*)d_in[0];
    const int* target = (const int*)d_in[1];
    const float* tok_emb = (const float*)d_in[2];
    const float* pos_emb = (const float*)d_in[3];
    const float* Wq = (const float*)d_in[4];
    const float* Wk = (const float*)d_in[5];
    const float* Wv = (const float*)d_in[6];
    const float* Wout = (const float*)d_in[7];
    float* out = (float*)d_out;

    embed_kernel<<<M_SZ, 128>>>(index, tok_emb, pos_emb);
    qkv_kernel<<<dim3(M_SZ / 64, H_SZ, 3), 256>>>(Wq, Wk, Wv);
    convB_kernel<<<dim3(V_SZ / 32, D_SZ / 32), 256>>>(Wout);
    attn_kernel<<<dim3(S_SZ / 64, H_SZ, B_SZ), 64>>>();
    convA_kernel<<<M_SZ, 64>>>();
    gemm_mma_kernel<<<dim3(V_SZ / BN, M_SZ / BM), 256>>>(out);
    lse_kernel<<<M_SZ, 256>>>(out, target);
    loss_reduce_kernel<<<1, 256>>>(out, out_size - 1);
}

// round 4
// speedup vs baseline: 2.1701x; 1.3390x over previous
#include <cuda_runtime.h>
#include <cuda_fp16.h>
#include <math.h>
#include <cstdint>

#define V_SZ 32000
#define D_SZ 512
#define S_SZ 2048
#define H_SZ 8
#define HS_SZ 64
#define B_SZ 4
#define M_SZ (B_SZ * S_SZ)   // 8192 rows
#define NQKV (3 * D_SZ)      // 1536 stacked qkv cols

// ---------------- scratch (device globals; no runtime allocation) ----------
__device__ __half g_x_hi[M_SZ * D_SZ];                   // embeddings hi  [B*S, D]
__device__ __half g_x_lo[M_SZ * D_SZ];                   // embeddings lo
__device__ __half g_wt[NQKV * D_SZ];                     // qkv weights^T [1536, 512]
__device__ float g_q[B_SZ * H_SZ * S_SZ * HS_SZ];        // [B,H,S,HS]
__device__ float g_k[B_SZ * H_SZ * S_SZ * HS_SZ];
__device__ float g_v[B_SZ * H_SZ * S_SZ * HS_SZ];
__device__ __half g_a_hi[M_SZ * D_SZ];                   // attn out hi [B*S, D]
__device__ __half g_a_lo[M_SZ * D_SZ];                   // attn out lo
__device__ __half g_bt[(size_t)V_SZ * D_SZ];             // W_out^T fp16 [32000, 512]
__device__ float g_rowloss[M_SZ];

// =================== PTX helpers (portable, compute_103-legal) =============
__device__ __forceinline__ uint32_t smem_u32(const void* p) {
    uint32_t a;
    asm("{ .reg .u64 t; cvta.to.shared.u64 t, %1; cvt.u32.u64 %0, t; }" : "=r"(a) : "l"(p));
    return a;
}
__device__ __forceinline__ void cp16(uint32_t dst, const void* src) {
    asm volatile("cp.async.cg.shared.global [%0], [%1], 16;" :: "r"(dst), "l"(src));
}
__device__ __forceinline__ void cp_commit() {
    asm volatile("cp.async.commit_group;" ::: "memory");
}
__device__ __forceinline__ void cp_wait1() {
    asm volatile("cp.async.wait_group 1;" ::: "memory");
}
__device__ __forceinline__ void cp_wait0() {
    asm volatile("cp.async.wait_group 0;" ::: "memory");
}
__device__ __forceinline__ void ldsm_x4(uint32_t* r, uint32_t addr) {
    asm volatile("ldmatrix.sync.aligned.m8n8.x4.shared.b16 {%0,%1,%2,%3}, [%4];"
                 : "=r"(r[0]), "=r"(r[1]), "=r"(r[2]), "=r"(r[3]) : "r"(addr));
}
__device__ __forceinline__ void mma16816(float* c, const uint32_t* a, const uint32_t* b) {
    asm volatile("mma.sync.aligned.m16n8k16.row.col.f32.f16.f16.f32 "
                 "{%0,%1,%2,%3}, {%4,%5,%6,%7}, {%8,%9}, {%0,%1,%2,%3};"
                 : "+f"(c[0]), "+f"(c[1]), "+f"(c[2]), "+f"(c[3])
                 : "r"(a[0]), "r"(a[1]), "r"(a[2]), "r"(a[3]),
                   "r"(b[0]), "r"(b[1]));
}

// ---------------- 1) embeddings -> fp16 hi/lo ------------------------------
__global__ void embed_kernel(const int* __restrict__ index,
                             const float* __restrict__ tok_emb,
                             const float* __restrict__ pos_emb) {
    int m = blockIdx.x;
    int s = m % S_SZ;
    int tok = index[m];
    const float4* te = (const float4*)(tok_emb + (size_t)tok * D_SZ);
    const float4* pe = (const float4*)(pos_emb + (size_t)s * D_SZ);
    int i = threadIdx.x;            // 128 threads, 4 floats each
    float4 a = te[i], b = pe[i];
    float x[4] = {a.x + b.x, a.y + b.y, a.z + b.z, a.w + b.w};
    __half h[4], l[4];
#pragma unroll
    for (int j = 0; j < 4; j++) {
        h[j] = __float2half(x[j]);
        l[j] = __float2half(x[j] - __half2float(h[j]));
    }
    size_t o = (size_t)m * D_SZ + i * 4;
    *(uint2*)(g_x_hi + o) = *(uint2*)h;
    *(uint2*)(g_x_lo + o) = *(uint2*)l;
}

// ---------------- 2) qkv weight transpose: [H,D,HS]x3 -> [1536,512] fp16 ---
__global__ void wt_kernel(const float* __restrict__ Wq,
                          const float* __restrict__ Wk,
                          const float* __restrict__ Wv) {
    int n = blockIdx.x;                       // 0..1535
    int which = n >> 9;
    int h = (n >> 6) & 7;
    int e = n & 63;
    const float* W = (which == 0 ? Wq : which == 1 ? Wk : Wv) + (size_t)h * D_SZ * HS_SZ + e;
    __half* dst = g_wt + (size_t)n * D_SZ;
    int t = threadIdx.x;                      // 128 threads, 4 k's each
#pragma unroll
    for (int j = 0; j < 4; j++) {
        int k = t * 4 + j;
        dst[k] = __float2half(W[(size_t)k * HS_SZ]);
    }
}

// ---------------- 3) W_out transpose+convert: [512,V] -> [V,512] fp16 ------
__global__ void convB_kernel(const float* __restrict__ W) {
    __shared__ float tbuf[32][33];
    int v0 = blockIdx.x * 32, k0 = blockIdx.y * 32;
    int tx = threadIdx.x & 31;
    int ty4 = (threadIdx.x >> 5) * 4;
#pragma unroll
    for (int j = 0; j < 4; j++)
        tbuf[ty4 + j][tx] = W[(size_t)(k0 + ty4 + j) * V_SZ + v0 + tx];
    __syncthreads();
#pragma unroll
    for (int j = 0; j < 4; j++)
        g_bt[(size_t)(v0 + ty4 + j) * D_SZ + k0 + tx] = __float2half(tbuf[tx][ty4 + j]);
}

// ---------------- shared GEMM machinery (fp16 2-pass: C = Ah*B + Al*B) ------
// Tile 128x128, BK=32 (64B/row), 256 threads (8 warps 2x4), warp 64x32.
// SMEM: per buffer {Ah, Al, B} each 128 rows * 80B pitch.
#define BM 128
#define BN 128
#define BKQ 32
#define PITCH 80
#define OPB (BM * PITCH)        // 10240 per operand
#define BUFB (3 * OPB)          // 30720 per stage
#define GEMM_DSMEM (2 * BUFB)   // 61440

struct GemmCore {
    uint32_t sa_h, sa_l, sb;            // smem bases (buf 0)
    uint32_t a_lm, b_lm;                // lane-dependent ldmatrix offsets
    int row0, col0, m_base, n_base, lane, wid;
    float acc[4][4][4];

    __device__ __forceinline__ void init(char* dsm) {
        int tid = threadIdx.x;
        lane = tid & 31;
        wid = tid >> 5;
        m_base = (wid & 1) * 64;
        n_base = (wid >> 1) * 32;
        uint32_t base = smem_u32(dsm);
        sa_h = base;
        sa_l = base + OPB;
        sb = base + 2 * OPB;
        a_lm = (uint32_t)((m_base + (lane & 15)) * PITCH + (lane >> 4) * 16);
        b_lm = (uint32_t)((n_base + (lane & 15)) * PITCH + (lane >> 4) * 16);
#pragma unroll
        for (int i = 0; i < 4; i++)
#pragma unroll
            for (int j = 0; j < 4; j++)
#pragma unroll
                for (int k = 0; k < 4; k++) acc[i][j][k] = 0.f;
    }

    __device__ __forceinline__ void load_tile(const __half* Ah, const __half* Al,
                                              const __half* Bt, int kk, int buf) {
        int tid = threadIdx.x;
#pragma unroll
        for (int it = 0; it < 2; it++) {
            int idx = it * 256 + tid;        // 0..511 chunks of 16B
            int r = idx >> 2;                // row 0..127
            int c = idx & 3;                 // 16B chunk
            uint32_t dsto = (uint32_t)(buf * BUFB + r * PITCH + c * 16);
            cp16(sa_h + dsto, Ah + (size_t)(row0 + r) * D_SZ + kk + c * 8);
            cp16(sa_l + dsto, Al + (size_t)(row0 + r) * D_SZ + kk + c * 8);
            cp16(sb + dsto, Bt + (size_t)(col0 + r) * D_SZ + kk + c * 8);
        }
    }

    __device__ __forceinline__ void mma_tile(int buf) {
        uint32_t ah_b = sa_h + (uint32_t)(buf * BUFB) + a_lm;
        uint32_t al_b = sa_l + (uint32_t)(buf * BUFB) + a_lm;
        uint32_t bb = sb + (uint32_t)(buf * BUFB) + b_lm;
#pragma unroll
        for (int s = 0; s < 2; s++) {
            uint32_t ahf[4][4], alf[4][4], bfr[2][4];
#pragma unroll
            for (int mf = 0; mf < 4; mf++) {
                ldsm_x4(ahf[mf], ah_b + (uint32_t)(mf * 16 * PITCH + s * 32));
                ldsm_x4(alf[mf], al_b + (uint32_t)(mf * 16 * PITCH + s * 32));
            }
#pragma unroll
            for (int nf2 = 0; nf2 < 2; nf2++)
                ldsm_x4(bfr[nf2], bb + (uint32_t)(nf2 * 16 * PITCH + s * 32));
#pragma unroll
            for (int mf = 0; mf < 4; mf++) {
#pragma unroll
                for (int nf = 0; nf < 4; nf++) {
                    uint32_t b2[2];
                    b2[0] = bfr[nf >> 1][nf & 1];
                    b2[1] = bfr[nf >> 1][(nf & 1) + 2];
                    mma16816(acc[mf][nf], ahf[mf], b2);
                    mma16816(acc[mf][nf], alf[mf], b2);
                }
            }
        }
    }

    __device__ __forceinline__ void run(const __half* Ah, const __half* Al,
                                        const __half* Bt) {
        load_tile(Ah, Al, Bt, 0, 0);
        cp_commit();
        const int NITER = D_SZ / BKQ;   // 16
        for (int kt = 0; kt < NITER; kt++) {
            int buf = kt & 1;
            if (kt + 1 < NITER) {
                load_tile(Ah, Al, Bt, (kt + 1) * BKQ, buf ^ 1);
                cp_commit();
                cp_wait1();
            } else {
                cp_wait0();
            }
            __syncthreads();
            mma_tile(buf);
            __syncthreads();
        }
    }
};

// ---------------- 4) qkv GEMM: [8192,512] x [512,1536] ---------------------
__global__ void __launch_bounds__(256, 2) qkv_gemm_kernel() {
    extern __shared__ __align__(16) char dsm[];
    GemmCore g;
    g.init(dsm);
    g.row0 = blockIdx.y * BM;
    g.col0 = blockIdx.x * BN;
    g.run(g_x_hi, g_x_lo, g_wt);

    // epilogue: scatter into g_q/g_k/g_v [B,H,S,HS]
    int n_gb = g.col0 + g.n_base;                 // warp's column base
    int which = n_gb >> 9;
    int hh = (n_gb >> 6) & 7;
    float* outp = (which == 0 ? g_q : which == 1 ? g_k : g_v);
    int e_base = (n_gb & 63) + (g.lane & 3) * 2;
    int rbase = g.row0 + g.m_base + (g.lane >> 2);
#pragma unroll
    for (int mf = 0; mf < 4; mf++) {
#pragma unroll
        for (int nf = 0; nf < 4; nf++) {
            int e = e_base + nf * 8;
            int m0 = rbase + mf * 16;
            int b0 = m0 >> 11, s0 = m0 & 2047;
            size_t o0 = ((size_t)(b0 * H_SZ + hh) * S_SZ + s0) * HS_SZ + e;
            int m1 = m0 + 8;
            int b1 = m1 >> 11, s1 = m1 & 2047;
            size_t o1 = ((size_t)(b1 * H_SZ + hh) * S_SZ + s1) * HS_SZ + e;
            *(float2*)(outp + o0) = make_float2(g.acc[mf][nf][0], g.acc[mf][nf][1]);
            *(float2*)(outp + o1) = make_float2(g.acc[mf][nf][2], g.acc[mf][nf][3]);
        }
    }
}

// ---------------- 5) logits GEMM: [8192,512] x [512,32000] -> d_out --------
__global__ void __launch_bounds__(256, 2) logits_gemm_kernel(float* __restrict__ C) {
    extern __shared__ __align__(16) char dsm[];
    GemmCore g;
    g.init(dsm);
    g.row0 = blockIdx.y * BM;
    g.col0 = blockIdx.x * BN;
    g.run(g_a_hi, g_a_lo, g_bt);

    int rbase = g.row0 + g.m_base + (g.lane >> 2);
    int cbase = g.col0 + g.n_base + (g.lane & 3) * 2;
#pragma unroll
    for (int mf = 0; mf < 4; mf++) {
#pragma unroll
        for (int nf = 0; nf < 4; nf++) {
            size_t o0 = (size_t)(rbase + mf * 16) * V_SZ + cbase + nf * 8;
            size_t o1 = o0 + (size_t)8 * V_SZ;
            *(float2*)(C + o0) = make_float2(g.acc[mf][nf][0], g.acc[mf][nf][1]);
            *(float2*)(C + o1) = make_float2(g.acc[mf][nf][2], g.acc[mf][nf][3]);
        }
    }
}

// ---------------- 6) causal attention (flash-style, dim-split) -------------
// Block 128 threads = 64 queries x 2 halves. Thread t: query=t>>1, half=t&1.
// Each thread owns 32 q-dims (for scores, combined via shfl_xor 1) and 32
// output dims. Writes fp16 hi/lo split directly (A operand of logits GEMM).
__global__ void attn_kernel() {
    __shared__ float Ksh[32][68];
    __shared__ float Vsh[32][68];

    int qt = blockIdx.x, h = blockIdx.y, b = blockIdx.z;
    int t = threadIdx.x;
    int q = t >> 1;
    int half = t & 1;
    size_t base = (size_t)(b * H_SZ + h) * S_SZ * HS_SZ;
    int qrow = qt * 64 + q;

    float qreg[32];
#pragma unroll
    for (int e = 0; e < 32; e += 4) {
        float4 qv = *(const float4*)&g_q[base + (size_t)qrow * HS_SZ + half * 32 + e];
        qreg[e] = qv.x; qreg[e + 1] = qv.y; qreg[e + 2] = qv.z; qreg[e + 3] = qv.w;
    }
    float o[32];
#pragma unroll
    for (int e = 0; e < 32; e++) o[e] = 0.f;
    float mval = -1e30f, l = 0.f;

    int ntiles = qt * 2 + 2;
    for (int kt = 0; kt < ntiles; kt++) {
        int krow0 = kt * 32;
        // cooperative load: 32 rows x 64 = 512 float4, 128 threads x 4
#pragma unroll
        for (int it = 0; it < 4; it++) {
            int f = it * 128 + t;
            int r = f >> 4;
            int e4 = (f & 15) * 4;
            *(float4*)&Ksh[r][e4] = *(const float4*)&g_k[base + (size_t)(krow0 + r) * HS_SZ + e4];
            *(float4*)&Vsh[r][e4] = *(const float4*)&g_v[base + (size_t)(krow0 + r) * HS_SZ + e4];
        }
        __syncthreads();

        float sreg[32];
        float tmax = -1e30f;
#pragma unroll
        for (int j = 0; j < 32; j++) {
            float s0 = 0.f, s1 = 0.f, s2 = 0.f, s3 = 0.f;
            const float* kr = &Ksh[j][half * 32];
#pragma unroll
            for (int d = 0; d < 32; d += 4) {
                s0 += qreg[d + 0] * kr[d + 0];
                s1 += qreg[d + 1] * kr[d + 1];
                s2 += qreg[d + 2] * kr[d + 2];
                s3 += qreg[d + 3] * kr[d + 3];
            }
            float part = (s0 + s1) + (s2 + s3);
            float s = (part + __shfl_xor_sync(0xffffffffu, part, 1)) * 0.125f;
            if (krow0 + j > qrow) s = -1e30f;
            sreg[j] = s;
            tmax = fmaxf(tmax, s);
        }
        float newm = fmaxf(mval, tmax);
        float factor = __expf(mval - newm);
        l *= factor;
#pragma unroll
        for (int e = 0; e < 32; e++) o[e] *= factor;
        const float* vcol = &Vsh[0][half * 32];
#pragma unroll
        for (int j = 0; j < 32; j++) {
            float p = __expf(sreg[j] - newm);
            l += p;
            const float* vr = vcol + j * 68;
#pragma unroll
            for (int e = 0; e < 32; e++) o[e] += p * vr[e];
        }
        mval = newm;
        __syncthreads();
    }

    float inv = 1.f / l;
    size_t dst = (size_t)(b * S_SZ + qrow) * D_SZ + h * HS_SZ + half * 32;
#pragma unroll
    for (int e = 0; e < 32; e += 2) {
        float x0 = o[e] * inv, x1 = o[e + 1] * inv;
        __half h0 = __float2half(x0), h1 = __float2half(x1);
        __half l0 = __float2half(x0 - __half2float(h0));
        __half l1 = __float2half(x1 - __half2float(h1));
        *(__half2*)(g_a_hi + dst + e) = __halves2half2(h0, h1);
        *(__half2*)(g_a_lo + dst + e) = __halves2half2(l0, l1);
    }
}

// ---------------- 7) per-row logsumexp + target pick ----------------------
__global__ void lse_kernel(const float* __restrict__ logits,
                           const int* __restrict__ target) {
    __shared__ float red[256];
    int m = blockIdx.x;
    const float* row = logits + (size_t)m * V_SZ;
    int tid = threadIdx.x;

    float mx = -1e30f;
    for (int i = tid; i < V_SZ; i += 256) mx = fmaxf(mx, row[i]);
    red[tid] = mx;
    __syncthreads();
    for (int s = 128; s > 0; s >>= 1) {
        if (tid < s) red[tid] = fmaxf(red[tid], red[tid + s]);
        __syncthreads();
    }
    float rowmax = red[0];
    __syncthreads();

    float sum = 0.f;
    for (int i = tid; i < V_SZ; i += 256) sum += __expf(row[i] - rowmax);
    red[tid] = sum;
    __syncthreads();
    for (int s = 128; s > 0; s >>= 1) {
        if (tid < s) red[tid] += red[tid + s];
        __syncthreads();
    }
    if (tid == 0) {
        float lse = rowmax + logf(red[0]);
        g_rowloss[m] = lse - row[target[m]];
    }
}

// ---------------- 8) deterministic mean reduction --------------------------
__global__ void loss_reduce_kernel(float* __restrict__ out, int loss_idx) {
    __shared__ float red[256];
    int tid = threadIdx.x;
    float s = 0.f;
    for (int i = tid; i < M_SZ; i += 256) s += g_rowloss[i];
    red[tid] = s;
    __syncthreads();
    for (int k = 128; k > 0; k >>= 1) {
        if (tid < k) red[tid] += red[tid + k];
        __syncthreads();
    }
    if (tid == 0) out[loss_idx] = red[0] / (float)M_SZ;
}

// ---------------- launch ----------------------------------------------------
extern "C" void kernel_launch(void* const* d_in, const int* in_sizes, int n_in,
                              void* d_out, int out_size) {
    const int* index = (const int*)d_in[0];
    const int* target = (const int*)d_in[1];
    const float* tok_emb = (const float*)d_in[2];
    const float* pos_emb = (const float*)d_in[3];
    const float* Wq = (const float*)d_in[4];
    const float* Wk = (const float*)d_in[5];
    const float* Wv = (const float*)d_in[6];
    const float* Wout = (const float*)d_in[7];
    float* out = (float*)d_out;

    static int smem_set = 0;
    if (!smem_set) {
        cudaFuncSetAttribute(qkv_gemm_kernel,
                             cudaFuncAttributeMaxDynamicSharedMemorySize, GEMM_DSMEM);
        cudaFuncSetAttribute(logits_gemm_kernel,
                             cudaFuncAttributeMaxDynamicSharedMemorySize, GEMM_DSMEM);
        smem_set = 1;
    }

    embed_kernel<<<M_SZ, 128>>>(index, tok_emb, pos_emb);
    wt_kernel<<<NQKV, 128>>>(Wq, Wk, Wv);
    convB_kernel<<<dim3(V_SZ / 32, D_SZ / 32), 256>>>(Wout);
    qkv_gemm_kernel<<<dim3(NQKV / BN, M_SZ / BM), 256, GEMM_DSMEM>>>();
    attn_kernel<<<dim3(S_SZ / 64, H_SZ, B_SZ), 128>>>();
    logits_gemm_kernel<<<dim3(V_SZ / BN, M_SZ / BM), 256, GEMM_DSMEM>>>(out);
    lse_kernel<<<M_SZ, 256>>>(out, target);
    loss_reduce_kernel<<<1, 256>>>(out, out_size - 1);
}

// round 5
// speedup vs baseline: 3.4413x; 1.5857x over previous
#include <cuda_runtime.h>
#include <cuda_fp16.h>
#include <math.h>
#include <cstdint>

#define V_SZ 32000
#define D_SZ 512
#define S_SZ 2048
#define H_SZ 8
#define HS_SZ 64
#define B_SZ 4
#define M_SZ (B_SZ * S_SZ)   // 8192 rows
#define NQKV (3 * D_SZ)      // 1536 stacked qkv cols

// scales (exact powers of two; cancel exactly)
#define X_SCALE 16.f
#define X_INV   0.0625f
#define V_SCALE 4.f          // applied to qkv acc (= x*16 * w): v64 = acc*4 -> 64*v

// ---------------- scratch (device globals; no runtime allocation) ----------
__device__ __half g_x_hi[M_SZ * D_SZ];                   // 16*x hi
__device__ __half g_x_lo[M_SZ * D_SZ];                   // 16*x lo
__device__ __half g_wt[NQKV * D_SZ];                     // qkv weights^T [1536, 512]
__device__ __half g_qh[B_SZ * H_SZ * S_SZ * HS_SZ];      // q fp16 [B,H,S,HS]
__device__ __half g_kh[B_SZ * H_SZ * S_SZ * HS_SZ];      // k fp16
__device__ __half g_vh[B_SZ * H_SZ * S_SZ * HS_SZ];      // 64*v hi
__device__ __half g_vl[B_SZ * H_SZ * S_SZ * HS_SZ];      // 64*v lo
__device__ __half g_a_hi[M_SZ * D_SZ];                   // 64*attn hi [B*S, D]
__device__ __half g_a_lo[M_SZ * D_SZ];                   // 64*attn lo
__device__ __half g_bt[(size_t)V_SZ * D_SZ];             // W_out^T fp16 [32000, 512]
__device__ float g_rowloss[M_SZ];

// =================== PTX helpers (portable, compute_103-legal) =============
__device__ __forceinline__ uint32_t smem_u32(const void* p) {
    uint32_t a;
    asm("{ .reg .u64 t; cvta.to.shared.u64 t, %1; cvt.u32.u64 %0, t; }" : "=r"(a) : "l"(p));
    return a;
}
__device__ __forceinline__ void cp16(uint32_t dst, const void* src) {
    asm volatile("cp.async.cg.shared.global [%0], [%1], 16;" :: "r"(dst), "l"(src));
}
__device__ __forceinline__ void cp_commit() {
    asm volatile("cp.async.commit_group;" ::: "memory");
}
__device__ __forceinline__ void cp_wait1() {
    asm volatile("cp.async.wait_group 1;" ::: "memory");
}
__device__ __forceinline__ void cp_wait0() {
    asm volatile("cp.async.wait_group 0;" ::: "memory");
}
__device__ __forceinline__ void ldsm_x4(uint32_t* r, uint32_t addr) {
    asm volatile("ldmatrix.sync.aligned.m8n8.x4.shared.b16 {%0,%1,%2,%3}, [%4];"
                 : "=r"(r[0]), "=r"(r[1]), "=r"(r[2]), "=r"(r[3]) : "r"(addr));
}
__device__ __forceinline__ void ldsm_x4_t(uint32_t* r, uint32_t addr) {
    asm volatile("ldmatrix.sync.aligned.m8n8.x4.trans.shared.b16 {%0,%1,%2,%3}, [%4];"
                 : "=r"(r[0]), "=r"(r[1]), "=r"(r[2]), "=r"(r[3]) : "r"(addr));
}
__device__ __forceinline__ void mma16816(float* c, const uint32_t* a, const uint32_t* b) {
    asm volatile("mma.sync.aligned.m16n8k16.row.col.f32.f16.f16.f32 "
                 "{%0,%1,%2,%3}, {%4,%5,%6,%7}, {%8,%9}, {%0,%1,%2,%3};"
                 : "+f"(c[0]), "+f"(c[1]), "+f"(c[2]), "+f"(c[3])
                 : "r"(a[0]), "r"(a[1]), "r"(a[2]), "r"(a[3]),
                   "r"(b[0]), "r"(b[1]));
}
__device__ __forceinline__ uint32_t pack_h2(float a, float b) {
    __half2 h = __halves2half2(__float2half(a), __float2half(b));
    return *(uint32_t*)&h;
}

// ---------------- 1) embeddings -> fp16 hi/lo (scaled x16) -----------------
__global__ void embed_kernel(const int* __restrict__ index,
                             const float* __restrict__ tok_emb,
                             const float* __restrict__ pos_emb) {
    int m = blockIdx.x;
    int s = m % S_SZ;
    int tok = index[m];
    const float4* te = (const float4*)(tok_emb + (size_t)tok * D_SZ);
    const float4* pe = (const float4*)(pos_emb + (size_t)s * D_SZ);
    int i = threadIdx.x;            // 128 threads, 4 floats each
    float4 a = te[i], b = pe[i];
    float x[4] = {(a.x + b.x) * X_SCALE, (a.y + b.y) * X_SCALE,
                  (a.z + b.z) * X_SCALE, (a.w + b.w) * X_SCALE};
    __half h[4], l[4];
#pragma unroll
    for (int j = 0; j < 4; j++) {
        h[j] = __float2half(x[j]);
        l[j] = __float2half(x[j] - __half2float(h[j]));
    }
    size_t o = (size_t)m * D_SZ + i * 4;
    *(uint2*)(g_x_hi + o) = *(uint2*)h;
    *(uint2*)(g_x_lo + o) = *(uint2*)l;
}

// ---------------- 2) qkv weight transpose: [H,D,HS]x3 -> [1536,512] fp16 ---
__global__ void wt_kernel(const float* __restrict__ Wq,
                          const float* __restrict__ Wk,
                          const float* __restrict__ Wv) {
    int n = blockIdx.x;                       // 0..1535
    int which = n >> 9;
    int h = (n >> 6) & 7;
    int e = n & 63;
    const float* W = (which == 0 ? Wq : which == 1 ? Wk : Wv) + (size_t)h * D_SZ * HS_SZ + e;
    __half* dst = g_wt + (size_t)n * D_SZ;
    int t = threadIdx.x;                      // 128 threads, 4 k's each
#pragma unroll
    for (int j = 0; j < 4; j++) {
        int k = t * 4 + j;
        dst[k] = __float2half(W[(size_t)k * HS_SZ]);
    }
}

// ---------------- 3) W_out transpose+convert: [512,V] -> [V,512] fp16 ------
__global__ void convB_kernel(const float* __restrict__ W) {
    __shared__ float tbuf[32][33];
    int v0 = blockIdx.x * 32, k0 = blockIdx.y * 32;
    int tx = threadIdx.x & 31;
    int ty4 = (threadIdx.x >> 5) * 4;
#pragma unroll
    for (int j = 0; j < 4; j++)
        tbuf[ty4 + j][tx] = W[(size_t)(k0 + ty4 + j) * V_SZ + v0 + tx];
    __syncthreads();
#pragma unroll
    for (int j = 0; j < 4; j++)
        g_bt[(size_t)(v0 + ty4 + j) * D_SZ + k0 + tx] = __float2half(tbuf[tx][ty4 + j]);
}

// ---------------- shared GEMM machinery (fp16 2-pass: C = Ah*B + Al*B) ------
// Tile 128x128, BK=32, 256 threads (8 warps 2x4), warp 64x32, 3-stage cp.async.
#define BM 128
#define BN 128
#define BKQ 32
#define PITCH 80
#define OPB (BM * PITCH)        // 10240 per operand
#define BUFB (3 * OPB)          // 30720 per stage
#define NSTAGE 3
#define GEMM_DSMEM (NSTAGE * BUFB)   // 92160

struct GemmCore {
    uint32_t sa_h, sa_l, sb;
    uint32_t a_lm, b_lm;
    int row0, col0, m_base, n_base, lane, wid;
    float acc[4][4][4];

    __device__ __forceinline__ void init(char* dsm) {
        int tid = threadIdx.x;
        lane = tid & 31;
        wid = tid >> 5;
        m_base = (wid & 1) * 64;
        n_base = (wid >> 1) * 32;
        uint32_t base = smem_u32(dsm);
        sa_h = base;
        sa_l = base + OPB;
        sb = base + 2 * OPB;
        a_lm = (uint32_t)((m_base + (lane & 15)) * PITCH + (lane >> 4) * 16);
        b_lm = (uint32_t)((n_base + (lane & 15)) * PITCH + (lane >> 4) * 16);
#pragma unroll
        for (int i = 0; i < 4; i++)
#pragma unroll
            for (int j = 0; j < 4; j++)
#pragma unroll
                for (int k = 0; k < 4; k++) acc[i][j][k] = 0.f;
    }

    __device__ __forceinline__ void load_tile(const __half* Ah, const __half* Al,
                                              const __half* Bt, int kk, int buf) {
        int tid = threadIdx.x;
#pragma unroll
        for (int it = 0; it < 2; it++) {
            int idx = it * 256 + tid;
            int r = idx >> 2;
            int c = idx & 3;
            uint32_t dsto = (uint32_t)(buf * BUFB + r * PITCH + c * 16);
            cp16(sa_h + dsto, Ah + (size_t)(row0 + r) * D_SZ + kk + c * 8);
            cp16(sa_l + dsto, Al + (size_t)(row0 + r) * D_SZ + kk + c * 8);
            cp16(sb + dsto, Bt + (size_t)(col0 + r) * D_SZ + kk + c * 8);
        }
    }

    __device__ __forceinline__ void mma_tile(int buf) {
        uint32_t ah_b = sa_h + (uint32_t)(buf * BUFB) + a_lm;
        uint32_t al_b = sa_l + (uint32_t)(buf * BUFB) + a_lm;
        uint32_t bb = sb + (uint32_t)(buf * BUFB) + b_lm;
#pragma unroll
        for (int s = 0; s < 2; s++) {
            uint32_t ahf[4][4], alf[4][4], bfr[2][4];
#pragma unroll
            for (int mf = 0; mf < 4; mf++) {
                ldsm_x4(ahf[mf], ah_b + (uint32_t)(mf * 16 * PITCH + s * 32));
                ldsm_x4(alf[mf], al_b + (uint32_t)(mf * 16 * PITCH + s * 32));
            }
#pragma unroll
            for (int nf2 = 0; nf2 < 2; nf2++)
                ldsm_x4(bfr[nf2], bb + (uint32_t)(nf2 * 16 * PITCH + s * 32));
#pragma unroll
            for (int mf = 0; mf < 4; mf++) {
#pragma unroll
                for (int nf = 0; nf < 4; nf++) {
                    uint32_t b2[2];
                    b2[0] = bfr[nf >> 1][nf & 1];
                    b2[1] = bfr[nf >> 1][(nf & 1) + 2];
                    mma16816(acc[mf][nf], ahf[mf], b2);
                    mma16816(acc[mf][nf], alf[mf], b2);
                }
            }
        }
    }

    __device__ __forceinline__ void run(const __half* Ah, const __half* Al,
                                        const __half* Bt) {
        load_tile(Ah, Al, Bt, 0, 0);
        cp_commit();
        load_tile(Ah, Al, Bt, BKQ, 1);
        cp_commit();
        const int NITER = D_SZ / BKQ;   // 16
        for (int kt = 0; kt < NITER; kt++) {
            int buf = kt % NSTAGE;
            cp_wait1();
            __syncthreads();
            if (kt + 2 < NITER)
                load_tile(Ah, Al, Bt, (kt + 2) * BKQ, (kt + 2) % NSTAGE);
            cp_commit();
            mma_tile(buf);
        }
    }
};

// ---------------- 4) qkv GEMM: [8192,512] x [512,1536] ---------------------
__global__ void __launch_bounds__(256, 2) qkv_gemm_kernel() {
    extern __shared__ __align__(16) char dsm[];
    GemmCore g;
    g.init(dsm);
    g.row0 = blockIdx.y * BM;
    g.col0 = blockIdx.x * BN;
    g.run(g_x_hi, g_x_lo, g_wt);

    // epilogue: write q/k fp16, v hi/lo (scaled)
    int n_gb = g.col0 + g.n_base;
    int which = n_gb >> 9;
    int hh = (n_gb >> 6) & 7;
    int e_base = (n_gb & 63) + (g.lane & 3) * 2;
    int rbase = g.row0 + g.m_base + (g.lane >> 2);
#pragma unroll
    for (int mf = 0; mf < 4; mf++) {
#pragma unroll
        for (int nf = 0; nf < 4; nf++) {
            int e = e_base + ((nf * 8) & 31);
            int m0 = rbase + mf * 16;
            int m1 = m0 + 8;
            size_t o0 = ((size_t)((m0 >> 11) * H_SZ + hh) * S_SZ + (m0 & 2047)) * HS_SZ + e;
            size_t o1 = ((size_t)((m1 >> 11) * H_SZ + hh) * S_SZ + (m1 & 2047)) * HS_SZ + e;
            float a0 = g.acc[mf][nf][0], a1 = g.acc[mf][nf][1];
            float a2 = g.acc[mf][nf][2], a3 = g.acc[mf][nf][3];
            if (which < 2) {
                __half* dst = which == 0 ? g_qh : g_kh;
                *(uint32_t*)(dst + o0) = pack_h2(a0 * X_INV, a1 * X_INV);
                *(uint32_t*)(dst + o1) = pack_h2(a2 * X_INV, a3 * X_INV);
            } else {
                float v0 = a0 * V_SCALE, v1 = a1 * V_SCALE;
                float v2 = a2 * V_SCALE, v3 = a3 * V_SCALE;
                __half h0 = __float2half(v0), h1 = __float2half(v1);
                __half h2v = __float2half(v2), h3 = __float2half(v3);
                *(uint32_t*)(g_vh + o0) = pack_h2(v0, v1);
                *(uint32_t*)(g_vh + o1) = pack_h2(v2, v3);
                *(uint32_t*)(g_vl + o0) = pack_h2(v0 - __half2float(h0), v1 - __half2float(h1));
                *(uint32_t*)(g_vl + o1) = pack_h2(v2 - __half2float(h2v), v3 - __half2float(h3));
            }
        }
    }
}

// ---------------- 5) logits GEMM: [8192,512] x [512,32000] -> d_out --------
__global__ void __launch_bounds__(256, 2) logits_gemm_kernel(float* __restrict__ C) {
    extern __shared__ __align__(16) char dsm[];
    GemmCore g;
    g.init(dsm);
    g.row0 = blockIdx.y * BM;
    g.col0 = blockIdx.x * BN;
    g.run(g_a_hi, g_a_lo, g_bt);

    const float ds = 1.f / 64.f;   // A scale removal
    int rbase = g.row0 + g.m_base + (g.lane >> 2);
    int cbase = g.col0 + g.n_base + (g.lane & 3) * 2;
#pragma unroll
    for (int mf = 0; mf < 4; mf++) {
#pragma unroll
        for (int nf = 0; nf < 4; nf++) {
            size_t o0 = (size_t)(rbase + mf * 16) * V_SZ + cbase + nf * 8;
            size_t o1 = o0 + (size_t)8 * V_SZ;
            *(float2*)(C + o0) = make_float2(g.acc[mf][nf][0] * ds, g.acc[mf][nf][1] * ds);
            *(float2*)(C + o1) = make_float2(g.acc[mf][nf][2] * ds, g.acc[mf][nf][3] * ds);
        }
    }
}

// ---------------- 6) tensor-core flash attention ----------------------------
// Block 128 thr (4 warps), 64 queries per block (warp w: 16 rows). K-tile 64.
// S = Q*K^T fp16 single; PV 3-pass split. Output = 64*attn as fp16 hi/lo.
#define AP 144                   // smem pitch for 64-dim fp16 rows
#define QTILE (64 * AP)          // 9216
#define KVSTAGE (3 * QTILE)      // K,Vh,Vl per stage
#define ATTN_SMEM (QTILE + 2 * KVSTAGE)  // 64512

__global__ void attn_kernel() {
    extern __shared__ __align__(16) char smema[];
    uint32_t sbse = smem_u32(smema);

    int qt = blockIdx.x, h = blockIdx.y, b = blockIdx.z;
    int tid = threadIdx.x;
    int lane = tid & 31;
    int w = tid >> 5;
    size_t base = (size_t)(b * H_SZ + h) * S_SZ * HS_SZ;

    // prologue: Q tile + KV tile 0
    {
#pragma unroll
        for (int it = 0; it < 4; it++) {
            int idx = it * 128 + tid;
            int r = idx >> 3, c = idx & 7;
            cp16(sbse + (uint32_t)(r * AP + c * 16),
                 g_qh + base + (size_t)(qt * 64 + r) * HS_SZ + c * 8);
        }
    }
    auto ldkv = [&](int kt, int buf) {
        uint32_t db = sbse + QTILE + (uint32_t)(buf * KVSTAGE);
#pragma unroll
        for (int it = 0; it < 4; it++) {
            int idx = it * 128 + tid;
            int r = idx >> 3, c = idx & 7;
            uint32_t off = (uint32_t)(r * AP + c * 16);
            size_t src = base + (size_t)(kt * 64 + r) * HS_SZ + c * 8;
            cp16(db + off, g_kh + src);
            cp16(db + QTILE + off, g_vh + src);
            cp16(db + 2 * QTILE + off, g_vl + src);
        }
    };
    ldkv(0, 0);
    cp_commit();

    const uint32_t q_lm = sbse + (uint32_t)((w * 16 + (lane & 15)) * AP + (lane >> 4) * 16);
    const uint32_t o_lm = (uint32_t)((lane & 15) * AP + (lane >> 4) * 16);

    float oacc[8][4];
#pragma unroll
    for (int f = 0; f < 8; f++)
#pragma unroll
        for (int k = 0; k < 4; k++) oacc[f][k] = 0.f;
    float m0 = -1e30f, m1 = -1e30f, l0 = 0.f, l1 = 0.f;
    uint32_t qf[4][4];

    int ntiles = qt + 1;
    for (int kt = 0; kt < ntiles; kt++) {
        int buf = kt & 1;
        if (kt + 1 < ntiles) {
            ldkv(kt + 1, buf ^ 1);
            cp_commit();
            cp_wait1();
        } else {
            cp_wait0();
        }
        __syncthreads();
        if (kt == 0) {
#pragma unroll
            for (int kf = 0; kf < 4; kf++) ldsm_x4(qf[kf], q_lm + kf * 32);
        }

        // ---- S = Q K^T ----
        uint32_t kb = sbse + QTILE + (uint32_t)(buf * KVSTAGE) + o_lm;
        float sacc[8][4];
#pragma unroll
        for (int f = 0; f < 8; f++)
#pragma unroll
            for (int k = 0; k < 4; k++) sacc[f][k] = 0.f;
#pragma unroll
        for (int ng = 0; ng < 4; ng++) {
#pragma unroll
            for (int s = 0; s < 4; s++) {
                uint32_t bf[4];
                ldsm_x4(bf, kb + (uint32_t)(ng * 16 * AP + s * 32));
                uint32_t b2a[2] = {bf[0], bf[2]};
                uint32_t b2b[2] = {bf[1], bf[3]};
                mma16816(sacc[2 * ng], qf[s], b2a);
                mma16816(sacc[2 * ng + 1], qf[s], b2b);
            }
        }
        // scale + causal mask (only diagonal tile)
        int rloc = w * 16 + (lane >> 2);
#pragma unroll
        for (int f = 0; f < 8; f++) {
#pragma unroll
            for (int k = 0; k < 4; k++) sacc[f][k] *= 0.125f;
            if (kt == qt) {
                int colb = f * 8 + 2 * (lane & 3);
                if (colb > rloc) sacc[f][0] = -1e30f;
                if (colb + 1 > rloc) sacc[f][1] = -1e30f;
                if (colb > rloc + 8) sacc[f][2] = -1e30f;
                if (colb + 1 > rloc + 8) sacc[f][3] = -1e30f;
            }
        }
        // ---- online softmax ----
        float t0 = -1e30f, t1 = -1e30f;
#pragma unroll
        for (int f = 0; f < 8; f++) {
            t0 = fmaxf(t0, fmaxf(sacc[f][0], sacc[f][1]));
            t1 = fmaxf(t1, fmaxf(sacc[f][2], sacc[f][3]));
        }
        t0 = fmaxf(t0, __shfl_xor_sync(0xffffffffu, t0, 1));
        t0 = fmaxf(t0, __shfl_xor_sync(0xffffffffu, t0, 2));
        t1 = fmaxf(t1, __shfl_xor_sync(0xffffffffu, t1, 1));
        t1 = fmaxf(t1, __shfl_xor_sync(0xffffffffu, t1, 2));
        float nm0 = fmaxf(m0, t0), nm1 = fmaxf(m1, t1);
        float f0 = __expf(m0 - nm0), f1 = __expf(m1 - nm1);
        m0 = nm0; m1 = nm1;
        l0 *= f0; l1 *= f1;
#pragma unroll
        for (int f = 0; f < 8; f++) {
            oacc[f][0] *= f0; oacc[f][1] *= f0;
            oacc[f][2] *= f1; oacc[f][3] *= f1;
        }
        float al0 = 0.f, al1 = 0.f;
#pragma unroll
        for (int f = 0; f < 8; f++) {
            sacc[f][0] = __expf(sacc[f][0] - nm0);
            sacc[f][1] = __expf(sacc[f][1] - nm0);
            sacc[f][2] = __expf(sacc[f][2] - nm1);
            sacc[f][3] = __expf(sacc[f][3] - nm1);
            al0 += sacc[f][0] + sacc[f][1];
            al1 += sacc[f][2] + sacc[f][3];
        }
        al0 += __shfl_xor_sync(0xffffffffu, al0, 1);
        al0 += __shfl_xor_sync(0xffffffffu, al0, 2);
        al1 += __shfl_xor_sync(0xffffffffu, al1, 1);
        al1 += __shfl_xor_sync(0xffffffffu, al1, 2);
        l0 += al0; l1 += al1;

        // ---- O += P V (3-pass split) ----
        uint32_t vb = sbse + QTILE + (uint32_t)(buf * KVSTAGE) + QTILE + o_lm;
#pragma unroll
        for (int s = 0; s < 4; s++) {
            uint32_t pah[4], pal[4];
            {
                float p00 = sacc[2 * s][0], p01 = sacc[2 * s][1];
                float p10 = sacc[2 * s][2], p11 = sacc[2 * s][3];
                float p20 = sacc[2 * s + 1][0], p21 = sacc[2 * s + 1][1];
                float p30 = sacc[2 * s + 1][2], p31 = sacc[2 * s + 1][3];
                __half h00 = __float2half(p00), h01 = __float2half(p01);
                __half h10 = __float2half(p10), h11 = __float2half(p11);
                __half h20 = __float2half(p20), h21 = __float2half(p21);
                __half h30 = __float2half(p30), h31 = __float2half(p31);
                pah[0] = pack_h2(p00, p01); pah[1] = pack_h2(p10, p11);
                pah[2] = pack_h2(p20, p21); pah[3] = pack_h2(p30, p31);
                pal[0] = pack_h2(p00 - __half2float(h00), p01 - __half2float(h01));
                pal[1] = pack_h2(p10 - __half2float(h10), p11 - __half2float(h11));
                pal[2] = pack_h2(p20 - __half2float(h20), p21 - __half2float(h21));
                pal[3] = pack_h2(p30 - __half2float(h30), p31 - __half2float(h31));
            }
#pragma unroll
            for (int ng = 0; ng < 4; ng++) {
                uint32_t vh4[4], vl4[4];
                ldsm_x4_t(vh4, vb + (uint32_t)(s * 16 * AP + ng * 32));
                ldsm_x4_t(vl4, vb + QTILE + (uint32_t)(s * 16 * AP + ng * 32));
                uint32_t bh0[2] = {vh4[0], vh4[1]};
                uint32_t bh1[2] = {vh4[2], vh4[3]};
                uint32_t bl0[2] = {vl4[0], vl4[1]};
                uint32_t bl1[2] = {vl4[2], vl4[3]};
                mma16816(oacc[2 * ng], pah, bh0);
                mma16816(oacc[2 * ng + 1], pah, bh1);
                mma16816(oacc[2 * ng], pah, bl0);
                mma16816(oacc[2 * ng + 1], pah, bl1);
                mma16816(oacc[2 * ng], pal, bh0);
                mma16816(oacc[2 * ng + 1], pal, bh1);
            }
        }
        __syncthreads();
    }

    // epilogue: write 64*attn as fp16 hi/lo
    float inv0 = 1.f / l0, inv1 = 1.f / l1;
    int s0 = qt * 64 + w * 16 + (lane >> 2);
    int s1 = s0 + 8;
    size_t d0 = (size_t)(b * S_SZ + s0) * D_SZ + h * HS_SZ + 2 * (lane & 3);
    size_t d1 = (size_t)(b * S_SZ + s1) * D_SZ + h * HS_SZ + 2 * (lane & 3);
#pragma unroll
    for (int f = 0; f < 8; f++) {
        float x0 = oacc[f][0] * inv0, x1 = oacc[f][1] * inv0;
        float x2 = oacc[f][2] * inv1, x3 = oacc[f][3] * inv1;
        __half h0 = __float2half(x0), h1 = __float2half(x1);
        __half h2v = __float2half(x2), h3 = __float2half(x3);
        *(uint32_t*)(g_a_hi + d0 + f * 8) = pack_h2(x0, x1);
        *(uint32_t*)(g_a_hi + d1 + f * 8) = pack_h2(x2, x3);
        *(uint32_t*)(g_a_lo + d0 + f * 8) = pack_h2(x0 - __half2float(h0), x1 - __half2float(h1));
        *(uint32_t*)(g_a_lo + d1 + f * 8) = pack_h2(x2 - __half2float(h2v), x3 - __half2float(h3));
    }
}

// ---------------- 7) single-pass online logsumexp + target pick -------------
__global__ void lse_kernel(const float* __restrict__ logits,
                           const int* __restrict__ target) {
    __shared__ float rm[256], rl[256];
    int m = blockIdx.x;
    const float* row = logits + (size_t)m * V_SZ;
    int tid = threadIdx.x;

    float mx = -1e30f, l = 0.f;
    for (int i = tid; i < V_SZ; i += 256) {
        float x = row[i];
        if (x > mx) {
            l *= __expf(mx - x);
            mx = x;
        }
        l += __expf(x - mx);
    }
    rm[tid] = mx; rl[tid] = l;
    __syncthreads();
    for (int s = 128; s > 0; s >>= 1) {
        if (tid < s) {
            float m2 = rm[tid + s], l2 = rl[tid + s];
            float M = fmaxf(rm[tid], m2);
            rl[tid] = rl[tid] * __expf(rm[tid] - M) + l2 * __expf(m2 - M);
            rm[tid] = M;
        }
        __syncthreads();
    }
    if (tid == 0)
        g_rowloss[m] = rm[0] + logf(rl[0]) - row[target[m]];
}

// ---------------- 8) deterministic mean reduction --------------------------
__global__ void loss_reduce_kernel(float* __restrict__ out, int loss_idx) {
    __shared__ float red[256];
    int tid = threadIdx.x;
    float s = 0.f;
    for (int i = tid; i < M_SZ; i += 256) s += g_rowloss[i];
    red[tid] = s;
    __syncthreads();
    for (int k = 128; k > 0; k >>= 1) {
        if (tid < k) red[tid] += red[tid + k];
        __syncthreads();
    }
    if (tid == 0) out[loss_idx] = red[0] / (float)M_SZ;
}

// ---------------- launch ----------------------------------------------------
extern "C" void kernel_launch(void* const* d_in, const int* in_sizes, int n_in,
                              void* d_out, int out_size) {
    const int* index = (const int*)d_in[0];
    const int* target = (const int*)d_in[1];
    const float* tok_emb = (const float*)d_in[2];
    const float* pos_emb = (const float*)d_in[3];
    const float* Wq = (const float*)d_in[4];
    const float* Wk = (const float*)d_in[5];
    const float* Wv = (const float*)d_in[6];
    const float* Wout = (const float*)d_in[7];
    float* out = (float*)d_out;

    cudaFuncSetAttribute(qkv_gemm_kernel,
                         cudaFuncAttributeMaxDynamicSharedMemorySize, GEMM_DSMEM);
    cudaFuncSetAttribute(logits_gemm_kernel,
                         cudaFuncAttributeMaxDynamicSharedMemorySize, GEMM_DSMEM);
    cudaFuncSetAttribute(attn_kernel,
                         cudaFuncAttributeMaxDynamicSharedMemorySize, ATTN_SMEM);

    embed_kernel<<<M_SZ, 128>>>(index, tok_emb, pos_emb);
    wt_kernel<<<NQKV, 128>>>(Wq, Wk, Wv);
    convB_kernel<<<dim3(V_SZ / 32, D_SZ / 32), 256>>>(Wout);
    qkv_gemm_kernel<<<dim3(NQKV / BN, M_SZ / BM), 256, GEMM_DSMEM>>>();
    attn_kernel<<<dim3(S_SZ / 64, H_SZ, B_SZ), 128, ATTN_SMEM>>>();
    logits_gemm_kernel<<<dim3(V_SZ / BN, M_SZ / BM), 256, GEMM_DSMEM>>>(out);
    lse_kernel<<<M_SZ, 256>>>(out, target);
    loss_reduce_kernel<<<1, 256>>>(out, out_size - 1);
}

// round 6
// speedup vs baseline: 3.8268x; 1.1120x over previous
#include <cuda_runtime.h>
#include <cuda_fp16.h>
#include <math.h>
#include <cstdint>

#define V_SZ 32000
#define D_SZ 512
#define S_SZ 2048
#define H_SZ 8
#define HS_SZ 64
#define B_SZ 4
#define M_SZ (B_SZ * S_SZ)   // 8192 rows
#define NQKV (3 * D_SZ)      // 1536 stacked qkv cols
#define NCOLB (V_SZ / 256)   // 125 col blocks for partial lse

// scales (exact powers of two; cancel exactly)
#define X_SCALE 16.f
#define X_INV   0.0625f
#define V_SCALE 4.f          // v64 = (16x*w)*4 = 64*v

// ---------------- scratch (device globals; no runtime allocation) ----------
__device__ __half g_x_hi[M_SZ * D_SZ];                   // 16*x hi
__device__ __half g_x_lo[M_SZ * D_SZ];                   // 16*x lo
__device__ __half g_wt[NQKV * D_SZ];                     // qkv weights^T [1536, 512]
__device__ __half g_qh[B_SZ * H_SZ * S_SZ * HS_SZ];      // q fp16 [B,H,S,HS]
__device__ __half g_kh[B_SZ * H_SZ * S_SZ * HS_SZ];      // k fp16
__device__ __half g_vh[B_SZ * H_SZ * S_SZ * HS_SZ];      // 64*v hi
__device__ __half g_vl[B_SZ * H_SZ * S_SZ * HS_SZ];      // 64*v lo
__device__ __half g_a_hi[M_SZ * D_SZ];                   // 64*attn hi [B*S, D]
__device__ __half g_a_lo[M_SZ * D_SZ];                   // 64*attn lo
__device__ __half g_bt[(size_t)V_SZ * D_SZ];             // W_out^T fp16 [32000, 512]
__device__ float2 g_part[(size_t)M_SZ * NCOLB];          // per (row, colblock) (max, sumexp)
__device__ float g_rowloss[M_SZ];

// =================== PTX helpers (portable, compute_103-legal) =============
__device__ __forceinline__ uint32_t smem_u32(const void* p) {
    uint32_t a;
    asm("{ .reg .u64 t; cvta.to.shared.u64 t, %1; cvt.u32.u64 %0, t; }" : "=r"(a) : "l"(p));
    return a;
}
__device__ __forceinline__ void cp16(uint32_t dst, const void* src) {
    asm volatile("cp.async.cg.shared.global [%0], [%1], 16;" :: "r"(dst), "l"(src));
}
__device__ __forceinline__ void cp_commit() {
    asm volatile("cp.async.commit_group;" ::: "memory");
}
__device__ __forceinline__ void cp_wait1() {
    asm volatile("cp.async.wait_group 1;" ::: "memory");
}
__device__ __forceinline__ void cp_wait0() {
    asm volatile("cp.async.wait_group 0;" ::: "memory");
}
__device__ __forceinline__ void ldsm_x4(uint32_t* r, uint32_t addr) {
    asm volatile("ldmatrix.sync.aligned.m8n8.x4.shared.b16 {%0,%1,%2,%3}, [%4];"
                 : "=r"(r[0]), "=r"(r[1]), "=r"(r[2]), "=r"(r[3]) : "r"(addr));
}
__device__ __forceinline__ void ldsm_x4_t(uint32_t* r, uint32_t addr) {
    asm volatile("ldmatrix.sync.aligned.m8n8.x4.trans.shared.b16 {%0,%1,%2,%3}, [%4];"
                 : "=r"(r[0]), "=r"(r[1]), "=r"(r[2]), "=r"(r[3]) : "r"(addr));
}
__device__ __forceinline__ void mma16816(float* c, const uint32_t* a, const uint32_t* b) {
    asm volatile("mma.sync.aligned.m16n8k16.row.col.f32.f16.f16.f32 "
                 "{%0,%1,%2,%3}, {%4,%5,%6,%7}, {%8,%9}, {%0,%1,%2,%3};"
                 : "+f"(c[0]), "+f"(c[1]), "+f"(c[2]), "+f"(c[3])
                 : "r"(a[0]), "r"(a[1]), "r"(a[2]), "r"(a[3]),
                   "r"(b[0]), "r"(b[1]));
}
__device__ __forceinline__ uint32_t pack_h2(float a, float b) {
    __half2 h = __halves2half2(__float2half(a), __float2half(b));
    return *(uint32_t*)&h;
}

// ---------------- 1) embeddings -> fp16 hi/lo (scaled x16) -----------------
__global__ void embed_kernel(const int* __restrict__ index,
                             const float* __restrict__ tok_emb,
                             const float* __restrict__ pos_emb) {
    int m = blockIdx.x;
    int s = m % S_SZ;
    int tok = index[m];
    const float4* te = (const float4*)(tok_emb + (size_t)tok * D_SZ);
    const float4* pe = (const float4*)(pos_emb + (size_t)s * D_SZ);
    int i = threadIdx.x;            // 128 threads, 4 floats each
    float4 a = te[i], b = pe[i];
    float x[4] = {(a.x + b.x) * X_SCALE, (a.y + b.y) * X_SCALE,
                  (a.z + b.z) * X_SCALE, (a.w + b.w) * X_SCALE};
    __half h[4], l[4];
#pragma unroll
    for (int j = 0; j < 4; j++) {
        h[j] = __float2half(x[j]);
        l[j] = __float2half(x[j] - __half2float(h[j]));
    }
    size_t o = (size_t)m * D_SZ + i * 4;
    *(uint2*)(g_x_hi + o) = *(uint2*)h;
    *(uint2*)(g_x_lo + o) = *(uint2*)l;
}

// ---------------- 2) qkv weight transpose: [H,D,HS]x3 -> [1536,512] fp16 ---
__global__ void wt_kernel(const float* __restrict__ Wq,
                          const float* __restrict__ Wk,
                          const float* __restrict__ Wv) {
    int n = blockIdx.x;                       // 0..1535
    int which = n >> 9;
    int h = (n >> 6) & 7;
    int e = n & 63;
    const float* W = (which == 0 ? Wq : which == 1 ? Wk : Wv) + (size_t)h * D_SZ * HS_SZ + e;
    __half* dst = g_wt + (size_t)n * D_SZ;
    int t = threadIdx.x;                      // 128 threads, 4 k's each
#pragma unroll
    for (int j = 0; j < 4; j++) {
        int k = t * 4 + j;
        dst[k] = __float2half(W[(size_t)k * HS_SZ]);
    }
}

// ---------------- 3) W_out transpose+convert: [512,V] -> [V,512] fp16 ------
__global__ void convB_kernel(const float* __restrict__ W) {
    __shared__ float tbuf[32][33];
    int v0 = blockIdx.x * 32, k0 = blockIdx.y * 32;
    int tx = threadIdx.x & 31;
    int ty4 = (threadIdx.x >> 5) * 4;
#pragma unroll
    for (int j = 0; j < 4; j++)
        tbuf[ty4 + j][tx] = W[(size_t)(k0 + ty4 + j) * V_SZ + v0 + tx];
    __syncthreads();
#pragma unroll
    for (int j = 0; j < 4; j++)
        g_bt[(size_t)(v0 + ty4 + j) * D_SZ + k0 + tx] = __float2half(tbuf[tx][ty4 + j]);
}

// ---------------- shared GEMM machinery (fp16 2-pass: C = Ah*B + Al*B) ------
// Tile 128x256, BK=32, 512 threads (16 warps 4m x 4n), warp tile 32x64.
// 3-stage cp.async. Stage layout: [Ah 128x80 | Al 128x80 | B 256x80].
#define BM 128
#define BN 256
#define BKQ 32
#define PITCH 80
#define OPA (BM * PITCH)          // 10240
#define OPBX (BN * PITCH)         // 20480
#define SSZ (2 * OPA + OPBX)      // 40960 per stage
#define NSTAGE 3
#define GEMM_DSMEM (NSTAGE * SSZ) // 122880

struct GemmCore {
    uint32_t sa;                 // smem base
    uint32_t a_lm, b_lm;         // lane-dependent ldmatrix offsets
    int row0, col0, m_base, n_base, lane, wid;
    float acc[2][8][4];

    __device__ __forceinline__ void init(char* dsm) {
        int tid = threadIdx.x;
        lane = tid & 31;
        wid = tid >> 5;
        m_base = (wid & 3) * 32;
        n_base = (wid >> 2) * 64;
        sa = smem_u32(dsm);
        a_lm = (uint32_t)((m_base + (lane & 15)) * PITCH + (lane >> 4) * 16);
        b_lm = (uint32_t)((n_base + (lane & 15)) * PITCH + (lane >> 4) * 16);
#pragma unroll
        for (int i = 0; i < 2; i++)
#pragma unroll
            for (int j = 0; j < 8; j++)
#pragma unroll
                for (int k = 0; k < 4; k++) acc[i][j][k] = 0.f;
    }

    __device__ __forceinline__ void load_tile(const __half* Ah, const __half* Al,
                                              const __half* Bt, int kk, int stage) {
        int tid = threadIdx.x;
        {
            int r = tid >> 2, c = tid & 3;          // 512 chunks: A
            uint32_t d = (uint32_t)(stage * SSZ + r * PITCH + c * 16);
            cp16(sa + d, Ah + (size_t)(row0 + r) * D_SZ + kk + c * 8);
            cp16(sa + OPA + d, Al + (size_t)(row0 + r) * D_SZ + kk + c * 8);
        }
#pragma unroll
        for (int it = 0; it < 2; it++) {            // 1024 chunks: B
            int idx = it * 512 + tid;
            int r = idx >> 2, c = idx & 3;
            uint32_t d = (uint32_t)(stage * SSZ + 2 * OPA + r * PITCH + c * 16);
            cp16(sa + d, Bt + (size_t)(col0 + r) * D_SZ + kk + c * 8);
        }
    }

    __device__ __forceinline__ void mma_tile(int stage) {
        uint32_t ah = sa + (uint32_t)(stage * SSZ) + a_lm;
        uint32_t al = ah + OPA;
        uint32_t bb = sa + (uint32_t)(stage * SSZ + 2 * OPA) + b_lm;
#pragma unroll
        for (int s = 0; s < 2; s++) {
            uint32_t ahf[2][4], alf[2][4], bfr[4][4];
#pragma unroll
            for (int mf = 0; mf < 2; mf++) {
                ldsm_x4(ahf[mf], ah + (uint32_t)(mf * 16 * PITCH + s * 32));
                ldsm_x4(alf[mf], al + (uint32_t)(mf * 16 * PITCH + s * 32));
            }
#pragma unroll
            for (int nf2 = 0; nf2 < 4; nf2++)
                ldsm_x4(bfr[nf2], bb + (uint32_t)(nf2 * 16 * PITCH + s * 32));
            // hi pass (16 independent MMAs), then lo pass -> no RAW pairs
#pragma unroll
            for (int mf = 0; mf < 2; mf++)
#pragma unroll
                for (int nf = 0; nf < 8; nf++) {
                    uint32_t b2[2] = {bfr[nf >> 1][nf & 1], bfr[nf >> 1][(nf & 1) + 2]};
                    mma16816(acc[mf][nf], ahf[mf], b2);
                }
#pragma unroll
            for (int mf = 0; mf < 2; mf++)
#pragma unroll
                for (int nf = 0; nf < 8; nf++) {
                    uint32_t b2[2] = {bfr[nf >> 1][nf & 1], bfr[nf >> 1][(nf & 1) + 2]};
                    mma16816(acc[mf][nf], alf[mf], b2);
                }
        }
    }

    __device__ __forceinline__ void run(const __half* Ah, const __half* Al,
                                        const __half* Bt) {
        load_tile(Ah, Al, Bt, 0, 0);
        cp_commit();
        load_tile(Ah, Al, Bt, BKQ, 1);
        cp_commit();
        const int NITER = D_SZ / BKQ;   // 16
        for (int kt = 0; kt < NITER; kt++) {
            int stage = kt % NSTAGE;
            cp_wait1();
            __syncthreads();
            if (kt + 2 < NITER)
                load_tile(Ah, Al, Bt, (kt + 2) * BKQ, (kt + 2) % NSTAGE);
            cp_commit();
            mma_tile(stage);
        }
        __syncthreads();   // all warps done reading smem before epilogue reuse
    }
};

// ---------------- 4) qkv GEMM: [8192,512] x [512,1536] ---------------------
__global__ void __launch_bounds__(512, 1) qkv_gemm_kernel() {
    extern __shared__ __align__(16) char dsm[];
    GemmCore g;
    g.init(dsm);
    g.row0 = blockIdx.y * BM;
    g.col0 = blockIdx.x * BN;
    g.run(g_x_hi, g_x_lo, g_wt);

    // epilogue: write q/k fp16, v hi/lo (scaled). 64-col warp span never
    // crosses a 512 (q/k/v) or 64 (head) boundary.
    int n_gb = g.col0 + g.n_base;
    int which = n_gb >> 9;
    int hh = (n_gb >> 6) & 7;
    int rb = g.row0 + g.m_base + (g.lane >> 2);
#pragma unroll
    for (int mf = 0; mf < 2; mf++) {
#pragma unroll
        for (int nf = 0; nf < 8; nf++) {
            int e = (g.lane & 3) * 2 + nf * 8;
            int m0 = rb + mf * 16;
            int m1 = m0 + 8;
            size_t o0 = ((size_t)((m0 >> 11) * H_SZ + hh) * S_SZ + (m0 & 2047)) * HS_SZ + e;
            size_t o1 = ((size_t)((m1 >> 11) * H_SZ + hh) * S_SZ + (m1 & 2047)) * HS_SZ + e;
            float a0 = g.acc[mf][nf][0], a1 = g.acc[mf][nf][1];
            float a2 = g.acc[mf][nf][2], a3 = g.acc[mf][nf][3];
            if (which < 2) {
                __half* dst = which == 0 ? g_qh : g_kh;
                *(uint32_t*)(dst + o0) = pack_h2(a0 * X_INV, a1 * X_INV);
                *(uint32_t*)(dst + o1) = pack_h2(a2 * X_INV, a3 * X_INV);
            } else {
                float v0 = a0 * V_SCALE, v1 = a1 * V_SCALE;
                float v2 = a2 * V_SCALE, v3 = a3 * V_SCALE;
                __half h0 = __float2half(v0), h1 = __float2half(v1);
                __half h2v = __float2half(v2), h3 = __float2half(v3);
                *(uint32_t*)(g_vh + o0) = pack_h2(v0, v1);
                *(uint32_t*)(g_vh + o1) = pack_h2(v2, v3);
                *(uint32_t*)(g_vl + o0) = pack_h2(v0 - __half2float(h0), v1 - __half2float(h1));
                *(uint32_t*)(g_vl + o1) = pack_h2(v2 - __half2float(h2v), v3 - __half2float(h3));
            }
        }
    }
}

// ---------------- 5) logits GEMM + fused partial logsumexp -----------------
__global__ void __launch_bounds__(512, 1) logits_gemm_kernel(float* __restrict__ C) {
    extern __shared__ __align__(16) char dsm[];
    GemmCore g;
    g.init(dsm);
    g.row0 = blockIdx.y * BM;
    g.col0 = blockIdx.x * BN;
    g.run(g_a_hi, g_a_lo, g_bt);

    const float ds = 1.f / 64.f;   // remove 64x A scale
    int rb = g.row0 + g.m_base + (g.lane >> 2);
    int cb = g.col0 + g.n_base + (g.lane & 3) * 2;
#pragma unroll
    for (int mf = 0; mf < 2; mf++)
#pragma unroll
        for (int nf = 0; nf < 8; nf++)
#pragma unroll
            for (int k = 0; k < 4; k++) g.acc[mf][nf][k] *= ds;

    // store logits
#pragma unroll
    for (int mf = 0; mf < 2; mf++) {
#pragma unroll
        for (int nf = 0; nf < 8; nf++) {
            size_t o0 = (size_t)(rb + mf * 16) * V_SZ + cb + nf * 8;
            size_t o1 = o0 + (size_t)8 * V_SZ;
            *(float2*)(C + o0) = make_float2(g.acc[mf][nf][0], g.acc[mf][nf][1]);
            *(float2*)(C + o1) = make_float2(g.acc[mf][nf][2], g.acc[mf][nf][3]);
        }
    }

    // partial (max, sumexp) over this CTA's 256 cols, per row
    float pm[2][2], ps[2][2];
#pragma unroll
    for (int mf = 0; mf < 2; mf++) {
#pragma unroll
        for (int h = 0; h < 2; h++) {
            float mx = -1e30f;
#pragma unroll
            for (int nf = 0; nf < 8; nf++)
                mx = fmaxf(mx, fmaxf(g.acc[mf][nf][h * 2], g.acc[mf][nf][h * 2 + 1]));
            mx = fmaxf(mx, __shfl_xor_sync(0xffffffffu, mx, 1));
            mx = fmaxf(mx, __shfl_xor_sync(0xffffffffu, mx, 2));
            float sm = 0.f;
#pragma unroll
            for (int nf = 0; nf < 8; nf++)
                sm += __expf(g.acc[mf][nf][h * 2] - mx) + __expf(g.acc[mf][nf][h * 2 + 1] - mx);
            sm += __shfl_xor_sync(0xffffffffu, sm, 1);
            sm += __shfl_xor_sync(0xffffffffu, sm, 2);
            pm[mf][h] = mx;
            ps[mf][h] = sm;
        }
    }
    float2* part = (float2*)dsm;   // [128][4]
    if ((g.lane & 3) == 0) {
#pragma unroll
        for (int mf = 0; mf < 2; mf++)
#pragma unroll
            for (int h = 0; h < 2; h++) {
                int rt = g.m_base + mf * 16 + h * 8 + (g.lane >> 2);
                part[rt * 4 + (g.wid >> 2)] = make_float2(pm[mf][h], ps[mf][h]);
            }
    }
    __syncthreads();
    int tid = threadIdx.x;
    if (tid < 128) {
        float M = -1e30f, S = 0.f;
#pragma unroll
        for (int qd = 0; qd < 4; qd++) {
            float2 p = part[tid * 4 + qd];
            float nm = fmaxf(M, p.x);
            S = S * __expf(M - nm) + p.y * __expf(p.x - nm);
            M = nm;
        }
        g_part[(size_t)(g.row0 + tid) * NCOLB + blockIdx.x] = make_float2(M, S);
    }
}

// ---------------- 6) tensor-core flash attention ----------------------------
// Block 128 thr (4 warps), 64 queries per block. qt order reversed so the
// longest (most causal tiles) blocks launch first.
#define AP 144
#define QTILE (64 * AP)
#define KVSTAGE (3 * QTILE)
#define ATTN_SMEM (QTILE + 2 * KVSTAGE)

__global__ void attn_kernel() {
    extern __shared__ __align__(16) char smema[];
    uint32_t sbse = smem_u32(smema);

    int qt = (int)gridDim.x - 1 - (int)blockIdx.x;   // longest first
    int h = blockIdx.y, b = blockIdx.z;
    int tid = threadIdx.x;
    int lane = tid & 31;
    int w = tid >> 5;
    size_t base = (size_t)(b * H_SZ + h) * S_SZ * HS_SZ;

    {
#pragma unroll
        for (int it = 0; it < 4; it++) {
            int idx = it * 128 + tid;
            int r = idx >> 3, c = idx & 7;
            cp16(sbse + (uint32_t)(r * AP + c * 16),
                 g_qh + base + (size_t)(qt * 64 + r) * HS_SZ + c * 8);
        }
    }
    auto ldkv = [&](int kt, int buf) {
        uint32_t db = sbse + QTILE + (uint32_t)(buf * KVSTAGE);
#pragma unroll
        for (int it = 0; it < 4; it++) {
            int idx = it * 128 + tid;
            int r = idx >> 3, c = idx & 7;
            uint32_t off = (uint32_t)(r * AP + c * 16);
            size_t src = base + (size_t)(kt * 64 + r) * HS_SZ + c * 8;
            cp16(db + off, g_kh + src);
            cp16(db + QTILE + off, g_vh + src);
            cp16(db + 2 * QTILE + off, g_vl + src);
        }
    };
    ldkv(0, 0);
    cp_commit();

    const uint32_t q_lm = sbse + (uint32_t)((w * 16 + (lane & 15)) * AP + (lane >> 4) * 16);
    const uint32_t o_lm = (uint32_t)((lane & 15) * AP + (lane >> 4) * 16);

    float oacc[8][4];
#pragma unroll
    for (int f = 0; f < 8; f++)
#pragma unroll
        for (int k = 0; k < 4; k++) oacc[f][k] = 0.f;
    float m0 = -1e30f, m1 = -1e30f, l0 = 0.f, l1 = 0.f;
    uint32_t qf[4][4];

    int ntiles = qt + 1;
    for (int kt = 0; kt < ntiles; kt++) {
        int buf = kt & 1;
        if (kt + 1 < ntiles) {
            ldkv(kt + 1, buf ^ 1);
            cp_commit();
            cp_wait1();
        } else {
            cp_wait0();
        }
        __syncthreads();
        if (kt == 0) {
#pragma unroll
            for (int kf = 0; kf < 4; kf++) ldsm_x4(qf[kf], q_lm + kf * 32);
        }

        uint32_t kb = sbse + QTILE + (uint32_t)(buf * KVSTAGE) + o_lm;
        float sacc[8][4];
#pragma unroll
        for (int f = 0; f < 8; f++)
#pragma unroll
            for (int k = 0; k < 4; k++) sacc[f][k] = 0.f;
#pragma unroll
        for (int ng = 0; ng < 4; ng++) {
#pragma unroll
            for (int s = 0; s < 4; s++) {
                uint32_t bf[4];
                ldsm_x4(bf, kb + (uint32_t)(ng * 16 * AP + s * 32));
                uint32_t b2a[2] = {bf[0], bf[2]};
                uint32_t b2b[2] = {bf[1], bf[3]};
                mma16816(sacc[2 * ng], qf[s], b2a);
                mma16816(sacc[2 * ng + 1], qf[s], b2b);
            }
        }
        int rloc = w * 16 + (lane >> 2);
#pragma unroll
        for (int f = 0; f < 8; f++) {
#pragma unroll
            for (int k = 0; k < 4; k++) sacc[f][k] *= 0.125f;
            if (kt == qt) {
                int colb = f * 8 + 2 * (lane & 3);
                if (colb > rloc) sacc[f][0] = -1e30f;
                if (colb + 1 > rloc) sacc[f][1] = -1e30f;
                if (colb > rloc + 8) sacc[f][2] = -1e30f;
                if (colb + 1 > rloc + 8) sacc[f][3] = -1e30f;
            }
        }
        float t0 = -1e30f, t1 = -1e30f;
#pragma unroll
        for (int f = 0; f < 8; f++) {
            t0 = fmaxf(t0, fmaxf(sacc[f][0], sacc[f][1]));
            t1 = fmaxf(t1, fmaxf(sacc[f][2], sacc[f][3]));
        }
        t0 = fmaxf(t0, __shfl_xor_sync(0xffffffffu, t0, 1));
        t0 = fmaxf(t0, __shfl_xor_sync(0xffffffffu, t0, 2));
        t1 = fmaxf(t1, __shfl_xor_sync(0xffffffffu, t1, 1));
        t1 = fmaxf(t1, __shfl_xor_sync(0xffffffffu, t1, 2));
        float nm0 = fmaxf(m0, t0), nm1 = fmaxf(m1, t1);
        float f0 = __expf(m0 - nm0), f1 = __expf(m1 - nm1);
        m0 = nm0; m1 = nm1;
        l0 *= f0; l1 *= f1;
#pragma unroll
        for (int f = 0; f < 8; f++) {
            oacc[f][0] *= f0; oacc[f][1] *= f0;
            oacc[f][2] *= f1; oacc[f][3] *= f1;
        }
        float al0 = 0.f, al1 = 0.f;
#pragma unroll
        for (int f = 0; f < 8; f++) {
            sacc[f][0] = __expf(sacc[f][0] - nm0);
            sacc[f][1] = __expf(sacc[f][1] - nm0);
            sacc[f][2] = __expf(sacc[f][2] - nm1);
            sacc[f][3] = __expf(sacc[f][3] - nm1);
            al0 += sacc[f][0] + sacc[f][1];
            al1 += sacc[f][2] + sacc[f][3];
        }
        al0 += __shfl_xor_sync(0xffffffffu, al0, 1);
        al0 += __shfl_xor_sync(0xffffffffu, al0, 2);
        al1 += __shfl_xor_sync(0xffffffffu, al1, 1);
        al1 += __shfl_xor_sync(0xffffffffu, al1, 2);
        l0 += al0; l1 += al1;

        uint32_t vb = sbse + QTILE + (uint32_t)(buf * KVSTAGE) + QTILE + o_lm;
#pragma unroll
        for (int s = 0; s < 4; s++) {
            uint32_t pah[4], pal[4];
            {
                float p00 = sacc[2 * s][0], p01 = sacc[2 * s][1];
                float p10 = sacc[2 * s][2], p11 = sacc[2 * s][3];
                float p20 = sacc[2 * s + 1][0], p21 = sacc[2 * s + 1][1];
                float p30 = sacc[2 * s + 1][2], p31 = sacc[2 * s + 1][3];
                __half h00 = __float2half(p00), h01 = __float2half(p01);
                __half h10 = __float2half(p10), h11 = __float2half(p11);
                __half h20 = __float2half(p20), h21 = __float2half(p21);
                __half h30 = __float2half(p30), h31 = __float2half(p31);
                pah[0] = pack_h2(p00, p01); pah[1] = pack_h2(p10, p11);
                pah[2] = pack_h2(p20, p21); pah[3] = pack_h2(p30, p31);
                pal[0] = pack_h2(p00 - __half2float(h00), p01 - __half2float(h01));
                pal[1] = pack_h2(p10 - __half2float(h10), p11 - __half2float(h11));
                pal[2] = pack_h2(p20 - __half2float(h20), p21 - __half2float(h21));
                pal[3] = pack_h2(p30 - __half2float(h30), p31 - __half2float(h31));
            }
#pragma unroll
            for (int ng = 0; ng < 4; ng++) {
                uint32_t vh4[4], vl4[4];
                ldsm_x4_t(vh4, vb + (uint32_t)(s * 16 * AP + ng * 32));
                ldsm_x4_t(vl4, vb + QTILE + (uint32_t)(s * 16 * AP + ng * 32));
                uint32_t bh0[2] = {vh4[0], vh4[1]};
                uint32_t bh1[2] = {vh4[2], vh4[3]};
                uint32_t bl0[2] = {vl4[0], vl4[1]};
                uint32_t bl1[2] = {vl4[2], vl4[3]};
                mma16816(oacc[2 * ng], pah, bh0);
                mma16816(oacc[2 * ng + 1], pah, bh1);
                mma16816(oacc[2 * ng], pah, bl0);
                mma16816(oacc[2 * ng + 1], pah, bl1);
                mma16816(oacc[2 * ng], pal, bh0);
                mma16816(oacc[2 * ng + 1], pal, bh1);
            }
        }
        __syncthreads();
    }

    float inv0 = 1.f / l0, inv1 = 1.f / l1;
    int s0 = qt * 64 + w * 16 + (lane >> 2);
    int s1 = s0 + 8;
    size_t d0 = (size_t)(b * S_SZ + s0) * D_SZ + h * HS_SZ + 2 * (lane & 3);
    size_t d1 = (size_t)(b * S_SZ + s1) * D_SZ + h * HS_SZ + 2 * (lane & 3);
#pragma unroll
    for (int f = 0; f < 8; f++) {
        float x0 = oacc[f][0] * inv0, x1 = oacc[f][1] * inv0;
        float x2 = oacc[f][2] * inv1, x3 = oacc[f][3] * inv1;
        __half h0 = __float2half(x0), h1 = __float2half(x1);
        __half h2v = __float2half(x2), h3 = __float2half(x3);
        *(uint32_t*)(g_a_hi + d0 + f * 8) = pack_h2(x0, x1);
        *(uint32_t*)(g_a_hi + d1 + f * 8) = pack_h2(x2, x3);
        *(uint32_t*)(g_a_lo + d0 + f * 8) = pack_h2(x0 - __half2float(h0), x1 - __half2float(h1));
        *(uint32_t*)(g_a_lo + d1 + f * 8) = pack_h2(x2 - __half2float(h2v), x3 - __half2float(h3));
    }
}

// ---------------- 7) combine partial lse + target pick ---------------------
__global__ void lse_combine_kernel(const float* __restrict__ C,
                                   const int* __restrict__ target) {
    int m = blockIdx.x * 8 + (threadIdx.x >> 5);
    int lane = threadIdx.x & 31;
    const float2* p = g_part + (size_t)m * NCOLB;
    float M = -1e30f, S = 0.f;
    for (int i = lane; i < NCOLB; i += 32) {
        float2 q = p[i];
        float nm = fmaxf(M, q.x);
        S = S * __expf(M - nm) + q.y * __expf(q.x - nm);
        M = nm;
    }
#pragma unroll
    for (int off = 16; off > 0; off >>= 1) {
        float m2 = __shfl_xor_sync(0xffffffffu, M, off);
        float s2 = __shfl_xor_sync(0xffffffffu, S, off);
        float nm = fmaxf(M, m2);
        S = S * __expf(M - nm) + s2 * __expf(m2 - nm);
        M = nm;
    }
    if (lane == 0)
        g_rowloss[m] = M + logf(S) - C[(size_t)m * V_SZ + target[m]];
}

// ---------------- 8) deterministic mean reduction --------------------------
__global__ void loss_reduce_kernel(float* __restrict__ out, int loss_idx) {
    __shared__ float red[256];
    int tid = threadIdx.x;
    float s = 0.f;
    for (int i = tid; i < M_SZ; i += 256) s += g_rowloss[i];
    red[tid] = s;
    __syncthreads();
    for (int k = 128; k > 0; k >>= 1) {
        if (tid < k) red[tid] += red[tid + k];
        __syncthreads();
    }
    if (tid == 0) out[loss_idx] = red[0] / (float)M_SZ;
}

// ---------------- launch ----------------------------------------------------
extern "C" void kernel_launch(void* const* d_in, const int* in_sizes, int n_in,
                              void* d_out, int out_size) {
    const int* index = (const int*)d_in[0];
    const int* target = (const int*)d_in[1];
    const float* tok_emb = (const float*)d_in[2];
    const float* pos_emb = (const float*)d_in[3];
    const float* Wq = (const float*)d_in[4];
    const float* Wk = (const float*)d_in[5];
    const float* Wv = (const float*)d_in[6];
    const float* Wout = (const float*)d_in[7];
    float* out = (float*)d_out;

    cudaFuncSetAttribute(qkv_gemm_kernel,
                         cudaFuncAttributeMaxDynamicSharedMemorySize, GEMM_DSMEM);
    cudaFuncSetAttribute(logits_gemm_kernel,
                         cudaFuncAttributeMaxDynamicSharedMemorySize, GEMM_DSMEM);
    cudaFuncSetAttribute(attn_kernel,
                         cudaFuncAttributeMaxDynamicSharedMemorySize, ATTN_SMEM);

    embed_kernel<<<M_SZ, 128>>>(index, tok_emb, pos_emb);
    wt_kernel<<<NQKV, 128>>>(Wq, Wk, Wv);
    convB_kernel<<<dim3(V_SZ / 32, D_SZ / 32), 256>>>(Wout);
    qkv_gemm_kernel<<<dim3(NQKV / BN, M_SZ / BM), 512, GEMM_DSMEM>>>();
    attn_kernel<<<dim3(S_SZ / 64, H_SZ, B_SZ), 128, ATTN_SMEM>>>();
    logits_gemm_kernel<<<dim3(V_SZ / BN, M_SZ / BM), 512, GEMM_DSMEM>>>(out);
    lse_combine_kernel<<<M_SZ / 8, 256>>>(out, target);
    loss_reduce_kernel<<<1, 256>>>(out, out_size - 1);
}

// round 7
// speedup vs baseline: 5.6770x; 1.4835x over previous
#include <cuda_runtime.h>
#include <cuda_fp16.h>
#include <math.h>
#include <cstdint>

#define V_SZ 32000
#define D_SZ 512
#define S_SZ 2048
#define H_SZ 8
#define HS_SZ 64
#define B_SZ 4
#define M_SZ (B_SZ * S_SZ)   // 8192 rows
#define NQKV (3 * D_SZ)      // 1536 stacked qkv cols
#define NCOLB (V_SZ / 256)   // 125 col blocks for partial lse

// scales (exact powers of two; cancel exactly)
#define X_SCALE 16.f
#define X_INV   0.0625f
#define V_SCALE 4.f          // v64 = (16x*w)*4 = 64*v

// ---------------- scratch (device globals; no runtime allocation) ----------
__device__ __half g_x_hi[M_SZ * D_SZ];                   // 16*x hi
__device__ __half g_x_lo[M_SZ * D_SZ];                   // 16*x lo
__device__ __half g_wt[NQKV * D_SZ];                     // qkv weights^T [1536, 512]
__device__ __half g_qh[B_SZ * H_SZ * S_SZ * HS_SZ];      // q fp16 [B,H,S,HS]
__device__ __half g_kh[B_SZ * H_SZ * S_SZ * HS_SZ];      // k fp16
__device__ __half g_vh[B_SZ * H_SZ * S_SZ * HS_SZ];      // 64*v hi
__device__ __half g_vl[B_SZ * H_SZ * S_SZ * HS_SZ];      // 64*v lo
__device__ __half g_a_hi[M_SZ * D_SZ];                   // 64*attn fp16 [B*S, D]
__device__ __half g_bt[(size_t)V_SZ * D_SZ];             // W_out^T fp16 [32000, 512]
__device__ float2 g_part[(size_t)M_SZ * NCOLB];          // per (row, colblock) (max, sumexp)
__device__ float g_rowloss[M_SZ];

// =================== PTX helpers (portable, compute_103-legal) =============
__device__ __forceinline__ uint32_t smem_u32(const void* p) {
    uint32_t a;
    asm("{ .reg .u64 t; cvta.to.shared.u64 t, %1; cvt.u32.u64 %0, t; }" : "=r"(a) : "l"(p));
    return a;
}
__device__ __forceinline__ void cp16(uint32_t dst, const void* src) {
    asm volatile("cp.async.cg.shared.global [%0], [%1], 16;" :: "r"(dst), "l"(src));
}
__device__ __forceinline__ void cp_commit() {
    asm volatile("cp.async.commit_group;" ::: "memory");
}
__device__ __forceinline__ void cp_wait1() {
    asm volatile("cp.async.wait_group 1;" ::: "memory");
}
__device__ __forceinline__ void cp_wait2() {
    asm volatile("cp.async.wait_group 2;" ::: "memory");
}
__device__ __forceinline__ void cp_wait0() {
    asm volatile("cp.async.wait_group 0;" ::: "memory");
}
__device__ __forceinline__ void ldsm_x4(uint32_t* r, uint32_t addr) {
    asm volatile("ldmatrix.sync.aligned.m8n8.x4.shared.b16 {%0,%1,%2,%3}, [%4];"
                 : "=r"(r[0]), "=r"(r[1]), "=r"(r[2]), "=r"(r[3]) : "r"(addr));
}
__device__ __forceinline__ void ldsm_x4_t(uint32_t* r, uint32_t addr) {
    asm volatile("ldmatrix.sync.aligned.m8n8.x4.trans.shared.b16 {%0,%1,%2,%3}, [%4];"
                 : "=r"(r[0]), "=r"(r[1]), "=r"(r[2]), "=r"(r[3]) : "r"(addr));
}
__device__ __forceinline__ void mma16816(float* c, const uint32_t* a, const uint32_t* b) {
    asm volatile("mma.sync.aligned.m16n8k16.row.col.f32.f16.f16.f32 "
                 "{%0,%1,%2,%3}, {%4,%5,%6,%7}, {%8,%9}, {%0,%1,%2,%3};"
                 : "+f"(c[0]), "+f"(c[1]), "+f"(c[2]), "+f"(c[3])
                 : "r"(a[0]), "r"(a[1]), "r"(a[2]), "r"(a[3]),
                   "r"(b[0]), "r"(b[1]));
}
__device__ __forceinline__ uint32_t pack_h2(float a, float b) {
    __half2 h = __halves2half2(__float2half(a), __float2half(b));
    return *(uint32_t*)&h;
}

// ---------------- 1) embeddings -> fp16 hi/lo (scaled x16) -----------------
__global__ void embed_kernel(const int* __restrict__ index,
                             const float* __restrict__ tok_emb,
                             const float* __restrict__ pos_emb) {
    int m = blockIdx.x;
    int s = m % S_SZ;
    int tok = index[m];
    const float4* te = (const float4*)(tok_emb + (size_t)tok * D_SZ);
    const float4* pe = (const float4*)(pos_emb + (size_t)s * D_SZ);
    int i = threadIdx.x;            // 128 threads, 4 floats each
    float4 a = te[i], b = pe[i];
    float x[4] = {(a.x + b.x) * X_SCALE, (a.y + b.y) * X_SCALE,
                  (a.z + b.z) * X_SCALE, (a.w + b.w) * X_SCALE};
    __half h[4], l[4];
#pragma unroll
    for (int j = 0; j < 4; j++) {
        h[j] = __float2half(x[j]);
        l[j] = __float2half(x[j] - __half2float(h[j]));
    }
    size_t o = (size_t)m * D_SZ + i * 4;
    *(uint2*)(g_x_hi + o) = *(uint2*)h;
    *(uint2*)(g_x_lo + o) = *(uint2*)l;
}

// ---------------- 2) qkv weight transpose: [H,D,HS]x3 -> [1536,512] fp16 ---
__global__ void wt_kernel(const float* __restrict__ Wq,
                          const float* __restrict__ Wk,
                          const float* __restrict__ Wv) {
    int n = blockIdx.x;                       // 0..1535
    int which = n >> 9;
    int h = (n >> 6) & 7;
    int e = n & 63;
    const float* W = (which == 0 ? Wq : which == 1 ? Wk : Wv) + (size_t)h * D_SZ * HS_SZ + e;
    __half* dst = g_wt + (size_t)n * D_SZ;
    int t = threadIdx.x;                      // 128 threads, 4 k's each
#pragma unroll
    for (int j = 0; j < 4; j++) {
        int k = t * 4 + j;
        dst[k] = __float2half(W[(size_t)k * HS_SZ]);
    }
}

// ---------------- 3) W_out transpose+convert: [512,V] -> [V,512] fp16 ------
__global__ void convB_kernel(const float* __restrict__ W) {
    __shared__ float tbuf[32][33];
    int v0 = blockIdx.x * 32, k0 = blockIdx.y * 32;
    int tx = threadIdx.x & 31;
    int ty4 = (threadIdx.x >> 5) * 4;
#pragma unroll
    for (int j = 0; j < 4; j++)
        tbuf[ty4 + j][tx] = W[(size_t)(k0 + ty4 + j) * V_SZ + v0 + tx];
    __syncthreads();
#pragma unroll
    for (int j = 0; j < 4; j++)
        g_bt[(size_t)(v0 + ty4 + j) * D_SZ + k0 + tx] = __float2half(tbuf[tx][ty4 + j]);
}

// ---------------- shared GEMM machinery -------------------------------------
// Tile 128x256, BK=32, 512 threads (16 warps 4m x 4n), warp tile 32x64.
// LO=true: 2-pass (Ah+Al) 3-stage; LO=false: single-pass 4-stage.
#define BM 128
#define BN 256
#define BKQ 32
#define PITCH 80
#define OPA (BM * PITCH)          // 10240
#define OPBX (BN * PITCH)         // 20480
#define GEMM_DSMEM 122880

template <bool LO>
struct GemmCore {
    static constexpr int SS = (LO ? 2 : 1) * OPA + OPBX;   // stage bytes
    static constexpr int NST = LO ? 3 : 4;
    uint32_t sa;
    uint32_t a_lm, b_lm;
    int row0, col0, m_base, n_base, lane, wid;
    float acc[2][8][4];

    __device__ __forceinline__ void init(char* dsm) {
        int tid = threadIdx.x;
        lane = tid & 31;
        wid = tid >> 5;
        m_base = (wid & 3) * 32;
        n_base = (wid >> 2) * 64;
        sa = smem_u32(dsm);
        a_lm = (uint32_t)((m_base + (lane & 15)) * PITCH + (lane >> 4) * 16);
        b_lm = (uint32_t)((n_base + (lane & 15)) * PITCH + (lane >> 4) * 16);
#pragma unroll
        for (int i = 0; i < 2; i++)
#pragma unroll
            for (int j = 0; j < 8; j++)
#pragma unroll
                for (int k = 0; k < 4; k++) acc[i][j][k] = 0.f;
    }

    __device__ __forceinline__ void load_tile(const __half* Ah, const __half* Al,
                                              const __half* Bt, int kk, int stage) {
        int tid = threadIdx.x;
        {
            int r = tid >> 2, c = tid & 3;
            uint32_t d = (uint32_t)(stage * SS + r * PITCH + c * 16);
            cp16(sa + d, Ah + (size_t)(row0 + r) * D_SZ + kk + c * 8);
            if (LO)
                cp16(sa + OPA + d, Al + (size_t)(row0 + r) * D_SZ + kk + c * 8);
        }
#pragma unroll
        for (int it = 0; it < 2; it++) {
            int idx = it * 512 + tid;
            int r = idx >> 2, c = idx & 3;
            uint32_t d = (uint32_t)(stage * SS + (LO ? 2 : 1) * OPA + r * PITCH + c * 16);
            cp16(sa + d, Bt + (size_t)(col0 + r) * D_SZ + kk + c * 8);
        }
    }

    __device__ __forceinline__ void mma_tile(int stage) {
        uint32_t ah = sa + (uint32_t)(stage * SS) + a_lm;
        uint32_t bb = sa + (uint32_t)(stage * SS + (LO ? 2 : 1) * OPA) + b_lm;
#pragma unroll
        for (int s = 0; s < 2; s++) {
            uint32_t ahf[2][4], alf[2][4], bfr[4][4];
#pragma unroll
            for (int mf = 0; mf < 2; mf++) {
                ldsm_x4(ahf[mf], ah + (uint32_t)(mf * 16 * PITCH + s * 32));
                if (LO)
                    ldsm_x4(alf[mf], ah + OPA + (uint32_t)(mf * 16 * PITCH + s * 32));
            }
#pragma unroll
            for (int nf2 = 0; nf2 < 4; nf2++)
                ldsm_x4(bfr[nf2], bb + (uint32_t)(nf2 * 16 * PITCH + s * 32));
#pragma unroll
            for (int mf = 0; mf < 2; mf++)
#pragma unroll
                for (int nf = 0; nf < 8; nf++) {
                    uint32_t b2[2] = {bfr[nf >> 1][nf & 1], bfr[nf >> 1][(nf & 1) + 2]};
                    mma16816(acc[mf][nf], ahf[mf], b2);
                }
            if (LO) {
#pragma unroll
                for (int mf = 0; mf < 2; mf++)
#pragma unroll
                    for (int nf = 0; nf < 8; nf++) {
                        uint32_t b2[2] = {bfr[nf >> 1][nf & 1], bfr[nf >> 1][(nf & 1) + 2]};
                        mma16816(acc[mf][nf], alf[mf], b2);
                    }
            }
        }
    }

    __device__ __forceinline__ void run(const __half* Ah, const __half* Al,
                                        const __half* Bt) {
        const int NITER = D_SZ / BKQ;   // 16
        if (LO) {
            load_tile(Ah, Al, Bt, 0, 0);
            cp_commit();
            load_tile(Ah, Al, Bt, BKQ, 1);
            cp_commit();
            for (int kt = 0; kt < NITER; kt++) {
                int stage = kt % NST;
                cp_wait1();
                __syncthreads();
                if (kt + 2 < NITER)
                    load_tile(Ah, Al, Bt, (kt + 2) * BKQ, (kt + 2) % NST);
                cp_commit();
                mma_tile(stage);
            }
        } else {
            load_tile(Ah, Al, Bt, 0, 0);
            cp_commit();
            load_tile(Ah, Al, Bt, BKQ, 1);
            cp_commit();
            load_tile(Ah, Al, Bt, 2 * BKQ, 2);
            cp_commit();
            for (int kt = 0; kt < NITER; kt++) {
                int stage = kt & 3;
                cp_wait2();
                __syncthreads();
                if (kt + 3 < NITER)
                    load_tile(Ah, Al, Bt, (kt + 3) * BKQ, (kt + 3) & 3);
                cp_commit();
                mma_tile(stage);
            }
        }
        __syncthreads();
    }
};

// ---------------- 4) qkv GEMM: [8192,512] x [512,1536] ---------------------
__global__ void __launch_bounds__(512, 1) qkv_gemm_kernel() {
    extern __shared__ __align__(16) char dsm[];
    GemmCore<true> g;
    g.init(dsm);
    g.row0 = blockIdx.y * BM;
    g.col0 = blockIdx.x * BN;
    g.run(g_x_hi, g_x_lo, g_wt);

    int n_gb = g.col0 + g.n_base;
    int which = n_gb >> 9;
    int hh = (n_gb >> 6) & 7;
    int rb = g.row0 + g.m_base + (g.lane >> 2);
#pragma unroll
    for (int mf = 0; mf < 2; mf++) {
#pragma unroll
        for (int nf = 0; nf < 8; nf++) {
            int e = (g.lane & 3) * 2 + nf * 8;
            int m0 = rb + mf * 16;
            int m1 = m0 + 8;
            size_t o0 = ((size_t)((m0 >> 11) * H_SZ + hh) * S_SZ + (m0 & 2047)) * HS_SZ + e;
            size_t o1 = ((size_t)((m1 >> 11) * H_SZ + hh) * S_SZ + (m1 & 2047)) * HS_SZ + e;
            float a0 = g.acc[mf][nf][0], a1 = g.acc[mf][nf][1];
            float a2 = g.acc[mf][nf][2], a3 = g.acc[mf][nf][3];
            if (which < 2) {
                __half* dst = which == 0 ? g_qh : g_kh;
                *(uint32_t*)(dst + o0) = pack_h2(a0 * X_INV, a1 * X_INV);
                *(uint32_t*)(dst + o1) = pack_h2(a2 * X_INV, a3 * X_INV);
            } else {
                float v0 = a0 * V_SCALE, v1 = a1 * V_SCALE;
                float v2 = a2 * V_SCALE, v3 = a3 * V_SCALE;
                __half h0 = __float2half(v0), h1 = __float2half(v1);
                __half h2v = __float2half(v2), h3 = __float2half(v3);
                *(uint32_t*)(g_vh + o0) = pack_h2(v0, v1);
                *(uint32_t*)(g_vh + o1) = pack_h2(v2, v3);
                *(uint32_t*)(g_vl + o0) = pack_h2(v0 - __half2float(h0), v1 - __half2float(h1));
                *(uint32_t*)(g_vl + o1) = pack_h2(v2 - __half2float(h2v), v3 - __half2float(h3));
            }
        }
    }
}

// ---------------- 5) logits GEMM (single-pass fp16) + fused partial lse ----
__global__ void __launch_bounds__(512, 1) logits_gemm_kernel(float* __restrict__ C) {
    extern __shared__ __align__(16) char dsm[];
    GemmCore<false> g;
    g.init(dsm);
    g.row0 = blockIdx.y * BM;
    g.col0 = blockIdx.x * BN;
    g.run(g_a_hi, nullptr, g_bt);

    const float ds = 1.f / 64.f;   // remove 64x A scale
    int rb = g.row0 + g.m_base + (g.lane >> 2);
    int cb = g.col0 + g.n_base + (g.lane & 3) * 2;
#pragma unroll
    for (int mf = 0; mf < 2; mf++)
#pragma unroll
        for (int nf = 0; nf < 8; nf++)
#pragma unroll
            for (int k = 0; k < 4; k++) g.acc[mf][nf][k] *= ds;

#pragma unroll
    for (int mf = 0; mf < 2; mf++) {
#pragma unroll
        for (int nf = 0; nf < 8; nf++) {
            size_t o0 = (size_t)(rb + mf * 16) * V_SZ + cb + nf * 8;
            size_t o1 = o0 + (size_t)8 * V_SZ;
            *(float2*)(C + o0) = make_float2(g.acc[mf][nf][0], g.acc[mf][nf][1]);
            *(float2*)(C + o1) = make_float2(g.acc[mf][nf][2], g.acc[mf][nf][3]);
        }
    }

    // partial (max, sumexp) over this CTA's 256 cols, per row
    float pm[2][2], ps[2][2];
#pragma unroll
    for (int mf = 0; mf < 2; mf++) {
#pragma unroll
        for (int h = 0; h < 2; h++) {
            float mx = -1e30f;
#pragma unroll
            for (int nf = 0; nf < 8; nf++)
                mx = fmaxf(mx, fmaxf(g.acc[mf][nf][h * 2], g.acc[mf][nf][h * 2 + 1]));
            mx = fmaxf(mx, __shfl_xor_sync(0xffffffffu, mx, 1));
            mx = fmaxf(mx, __shfl_xor_sync(0xffffffffu, mx, 2));
            float sm = 0.f;
#pragma unroll
            for (int nf = 0; nf < 8; nf++)
                sm += __expf(g.acc[mf][nf][h * 2] - mx) + __expf(g.acc[mf][nf][h * 2 + 1] - mx);
            sm += __shfl_xor_sync(0xffffffffu, sm, 1);
            sm += __shfl_xor_sync(0xffffffffu, sm, 2);
            pm[mf][h] = mx;
            ps[mf][h] = sm;
        }
    }
    float2* part = (float2*)dsm;   // [128][4]
    if ((g.lane & 3) == 0) {
#pragma unroll
        for (int mf = 0; mf < 2; mf++)
#pragma unroll
            for (int h = 0; h < 2; h++) {
                int rt = g.m_base + mf * 16 + h * 8 + (g.lane >> 2);
                part[rt * 4 + (g.wid >> 2)] = make_float2(pm[mf][h], ps[mf][h]);
            }
    }
    __syncthreads();
    int tid = threadIdx.x;
    if (tid < 128) {
        float M = -1e30f, S = 0.f;
#pragma unroll
        for (int qd = 0; qd < 4; qd++) {
            float2 p = part[tid * 4 + qd];
            float nm = fmaxf(M, p.x);
            S = S * __expf(M - nm) + p.y * __expf(p.x - nm);
            M = nm;
        }
        g_part[(size_t)(g.row0 + tid) * NCOLB + blockIdx.x] = make_float2(M, S);
    }
}

// ---------------- 6) tensor-core flash attention ----------------------------
#define AP 144
#define QTILE (64 * AP)
#define KVSTAGE (3 * QTILE)
#define ATTN_SMEM (QTILE + 2 * KVSTAGE)

__global__ void attn_kernel() {
    extern __shared__ __align__(16) char smema[];
    uint32_t sbse = smem_u32(smema);

    int qt = (int)gridDim.x - 1 - (int)blockIdx.x;   // longest first
    int h = blockIdx.y, b = blockIdx.z;
    int tid = threadIdx.x;
    int lane = tid & 31;
    int w = tid >> 5;
    size_t base = (size_t)(b * H_SZ + h) * S_SZ * HS_SZ;

    {
#pragma unroll
        for (int it = 0; it < 4; it++) {
            int idx = it * 128 + tid;
            int r = idx >> 3, c = idx & 7;
            cp16(sbse + (uint32_t)(r * AP + c * 16),
                 g_qh + base + (size_t)(qt * 64 + r) * HS_SZ + c * 8);
        }
    }
    auto ldkv = [&](int kt, int buf) {
        uint32_t db = sbse + QTILE + (uint32_t)(buf * KVSTAGE);
#pragma unroll
        for (int it = 0; it < 4; it++) {
            int idx = it * 128 + tid;
            int r = idx >> 3, c = idx & 7;
            uint32_t off = (uint32_t)(r * AP + c * 16);
            size_t src = base + (size_t)(kt * 64 + r) * HS_SZ + c * 8;
            cp16(db + off, g_kh + src);
            cp16(db + QTILE + off, g_vh + src);
            cp16(db + 2 * QTILE + off, g_vl + src);
        }
    };
    ldkv(0, 0);
    cp_commit();

    const uint32_t q_lm = sbse + (uint32_t)((w * 16 + (lane & 15)) * AP + (lane >> 4) * 16);
    const uint32_t o_lm = (uint32_t)((lane & 15) * AP + (lane >> 4) * 16);

    float oacc[8][4];
#pragma unroll
    for (int f = 0; f < 8; f++)
#pragma unroll
        for (int k = 0; k < 4; k++) oacc[f][k] = 0.f;
    float m0 = -1e30f, m1 = -1e30f, l0 = 0.f, l1 = 0.f;
    uint32_t qf[4][4];

    int ntiles = qt + 1;
    for (int kt = 0; kt < ntiles; kt++) {
        int buf = kt & 1;
        if (kt + 1 < ntiles) {
            ldkv(kt + 1, buf ^ 1);
            cp_commit();
            cp_wait1();
        } else {
            cp_wait0();
        }
        __syncthreads();
        if (kt == 0) {
#pragma unroll
            for (int kf = 0; kf < 4; kf++) ldsm_x4(qf[kf], q_lm + kf * 32);
        }

        uint32_t kb = sbse + QTILE + (uint32_t)(buf * KVSTAGE) + o_lm;
        float sacc[8][4];
#pragma unroll
        for (int f = 0; f < 8; f++)
#pragma unroll
            for (int k = 0; k < 4; k++) sacc[f][k] = 0.f;
#pragma unroll
        for (int ng = 0; ng < 4; ng++) {
#pragma unroll
            for (int s = 0; s < 4; s++) {
                uint32_t bf[4];
                ldsm_x4(bf, kb + (uint32_t)(ng * 16 * AP + s * 32));
                uint32_t b2a[2] = {bf[0], bf[2]};
                uint32_t b2b[2] = {bf[1], bf[3]};
                mma16816(sacc[2 * ng], qf[s], b2a);
                mma16816(sacc[2 * ng + 1], qf[s], b2b);
            }
        }
        int rloc = w * 16 + (lane >> 2);
#pragma unroll
        for (int f = 0; f < 8; f++) {
#pragma unroll
            for (int k = 0; k < 4; k++) sacc[f][k] *= 0.125f;
            if (kt == qt) {
                int colb = f * 8 + 2 * (lane & 3);
                if (colb > rloc) sacc[f][0] = -1e30f;
                if (colb + 1 > rloc) sacc[f][1] = -1e30f;
                if (colb > rloc + 8) sacc[f][2] = -1e30f;
                if (colb + 1 > rloc + 8) sacc[f][3] = -1e30f;
            }
        }
        float t0 = -1e30f, t1 = -1e30f;
#pragma unroll
        for (int f = 0; f < 8; f++) {
            t0 = fmaxf(t0, fmaxf(sacc[f][0], sacc[f][1]));
            t1 = fmaxf(t1, fmaxf(sacc[f][2], sacc[f][3]));
        }
        t0 = fmaxf(t0, __shfl_xor_sync(0xffffffffu, t0, 1));
        t0 = fmaxf(t0, __shfl_xor_sync(0xffffffffu, t0, 2));
        t1 = fmaxf(t1, __shfl_xor_sync(0xffffffffu, t1, 1));
        t1 = fmaxf(t1, __shfl_xor_sync(0xffffffffu, t1, 2));
        float nm0 = fmaxf(m0, t0), nm1 = fmaxf(m1, t1);
        float f0 = __expf(m0 - nm0), f1 = __expf(m1 - nm1);
        m0 = nm0; m1 = nm1;
        l0 *= f0; l1 *= f1;
#pragma unroll
        for (int f = 0; f < 8; f++) {
            oacc[f][0] *= f0; oacc[f][1] *= f0;
            oacc[f][2] *= f1; oacc[f][3] *= f1;
        }
        float al0 = 0.f, al1 = 0.f;
#pragma unroll
        for (int f = 0; f < 8; f++) {
            sacc[f][0] = __expf(sacc[f][0] - nm0);
            sacc[f][1] = __expf(sacc[f][1] - nm0);
            sacc[f][2] = __expf(sacc[f][2] - nm1);
            sacc[f][3] = __expf(sacc[f][3] - nm1);
            al0 += sacc[f][0] + sacc[f][1];
            al1 += sacc[f][2] + sacc[f][3];
        }
        al0 += __shfl_xor_sync(0xffffffffu, al0, 1);
        al0 += __shfl_xor_sync(0xffffffffu, al0, 2);
        al1 += __shfl_xor_sync(0xffffffffu, al1, 1);
        al1 += __shfl_xor_sync(0xffffffffu, al1, 2);
        l0 += al0; l1 += al1;

        uint32_t vb = sbse + QTILE + (uint32_t)(buf * KVSTAGE) + QTILE + o_lm;
#pragma unroll
        for (int s = 0; s < 4; s++) {
            uint32_t pah[4], pal[4];
            {
                float p00 = sacc[2 * s][0], p01 = sacc[2 * s][1];
                float p10 = sacc[2 * s][2], p11 = sacc[2 * s][3];
                float p20 = sacc[2 * s + 1][0], p21 = sacc[2 * s + 1][1];
                float p30 = sacc[2 * s + 1][2], p31 = sacc[2 * s + 1][3];
                __half h00 = __float2half(p00), h01 = __float2half(p01);
                __half h10 = __float2half(p10), h11 = __float2half(p11);
                __half h20 = __float2half(p20), h21 = __float2half(p21);
                __half h30 = __float2half(p30), h31 = __float2half(p31);
                pah[0] = pack_h2(p00, p01); pah[1] = pack_h2(p10, p11);
                pah[2] = pack_h2(p20, p21); pah[3] = pack_h2(p30, p31);
                pal[0] = pack_h2(p00 - __half2float(h00), p01 - __half2float(h01));
                pal[1] = pack_h2(p10 - __half2float(h10), p11 - __half2float(h11));
                pal[2] = pack_h2(p20 - __half2float(h20), p21 - __half2float(h21));
                pal[3] = pack_h2(p30 - __half2float(h30), p31 - __half2float(h31));
            }
#pragma unroll
            for (int ng = 0; ng < 4; ng++) {
                uint32_t vh4[4], vl4[4];
                ldsm_x4_t(vh4, vb + (uint32_t)(s * 16 * AP + ng * 32));
                ldsm_x4_t(vl4, vb + QTILE + (uint32_t)(s * 16 * AP + ng * 32));
                uint32_t bh0[2] = {vh4[0], vh4[1]};
                uint32_t bh1[2] = {vh4[2], vh4[3]};
                uint32_t bl0[2] = {vl4[0], vl4[1]};
                uint32_t bl1[2] = {vl4[2], vl4[3]};
                mma16816(oacc[2 * ng], pah, bh0);
                mma16816(oacc[2 * ng + 1], pah, bh1);
                mma16816(oacc[2 * ng], pah, bl0);
                mma16816(oacc[2 * ng + 1], pah, bl1);
                mma16816(oacc[2 * ng], pal, bh0);
                mma16816(oacc[2 * ng + 1], pal, bh1);
            }
        }
        __syncthreads();
    }

    // epilogue: write 64*attn as single fp16 (logits GEMM is single-pass now)
    float inv0 = 1.f / l0, inv1 = 1.f / l1;
    int s0 = qt * 64 + w * 16 + (lane >> 2);
    int s1 = s0 + 8;
    size_t d0 = (size_t)(b * S_SZ + s0) * D_SZ + h * HS_SZ + 2 * (lane & 3);
    size_t d1 = (size_t)(b * S_SZ + s1) * D_SZ + h * HS_SZ + 2 * (lane & 3);
#pragma unroll
    for (int f = 0; f < 8; f++) {
        *(uint32_t*)(g_a_hi + d0 + f * 8) = pack_h2(oacc[f][0] * inv0, oacc[f][1] * inv0);
        *(uint32_t*)(g_a_hi + d1 + f * 8) = pack_h2(oacc[f][2] * inv1, oacc[f][3] * inv1);
    }
}

// ---------------- 7) combine partial lse + target pick ---------------------
__global__ void lse_combine_kernel(const float* __restrict__ C,
                                   const int* __restrict__ target) {
    int m = blockIdx.x * 8 + (threadIdx.x >> 5);
    int lane = threadIdx.x & 31;
    const float2* p = g_part + (size_t)m * NCOLB;
    float M = -1e30f, S = 0.f;
    for (int i = lane; i < NCOLB; i += 32) {
        float2 q = p[i];
        float nm = fmaxf(M, q.x);
        S = S * __expf(M - nm) + q.y * __expf(q.x - nm);
        M = nm;
    }
#pragma unroll
    for (int off = 16; off > 0; off >>= 1) {
        float m2 = __shfl_xor_sync(0xffffffffu, M, off);
        float s2 = __shfl_xor_sync(0xffffffffu, S, off);
        float nm = fmaxf(M, m2);
        S = S * __expf(M - nm) + s2 * __expf(m2 - nm);
        M = nm;
    }
    if (lane == 0)
        g_rowloss[m] = M + logf(S) - C[(size_t)m * V_SZ + target[m]];
}

// ---------------- 8) deterministic mean reduction --------------------------
__global__ void loss_reduce_kernel(float* __restrict__ out, int loss_idx) {
    __shared__ float red[256];
    int tid = threadIdx.x;
    float s = 0.f;
    for (int i = tid; i < M_SZ; i += 256) s += g_rowloss[i];
    red[tid] = s;
    __syncthreads();
    for (int k = 128; k > 0; k >>= 1) {
        if (tid < k) red[tid] += red[tid + k];
        __syncthreads();
    }
    if (tid == 0) out[loss_idx] = red[0] / (float)M_SZ;
}

// ---------------- launch ----------------------------------------------------
extern "C" void kernel_launch(void* const* d_in, const int* in_sizes, int n_in,
                              void* d_out, int out_size) {
    const int* index = (const int*)d_in[0];
    const int* target = (const int*)d_in[1];
    const float* tok_emb = (const float*)d_in[2];
    const float* pos_emb = (const float*)d_in[3];
    const float* Wq = (const float*)d_in[4];
    const float* Wk = (const float*)d_in[5];
    const float* Wv = (const float*)d_in[6];
    const float* Wout = (const float*)d_in[7];
    float* out = (float*)d_out;

    cudaFuncSetAttribute(qkv_gemm_kernel,
                         cudaFuncAttributeMaxDynamicSharedMemorySize, GEMM_DSMEM);
    cudaFuncSetAttribute(logits_gemm_kernel,
                         cudaFuncAttributeMaxDynamicSharedMemorySize, GEMM_DSMEM);
    cudaFuncSetAttribute(attn_kernel,
                         cudaFuncAttributeMaxDynamicSharedMemorySize, ATTN_SMEM);

    embed_kernel<<<M_SZ, 128>>>(index, tok_emb, pos_emb);
    wt_kernel<<<NQKV, 128>>>(Wq, Wk, Wv);
    convB_kernel<<<dim3(V_SZ / 32, D_SZ / 32), 256>>>(Wout);
    qkv_gemm_kernel<<<dim3(NQKV / BN, M_SZ / BM), 512, GEMM_DSMEM>>>();
    attn_kernel<<<dim3(S_SZ / 64, H_SZ, B_SZ), 128, ATTN_SMEM>>>();
    logits_gemm_kernel<<<dim3(V_SZ / BN, M_SZ / BM), 512, GEMM_DSMEM>>>(out);
    lse_combine_kernel<<<M_SZ / 8, 256>>>(out, target);
    loss_reduce_kernel<<<1, 256>>>(out, out_size - 1);
}

// round 8
// speedup vs baseline: 6.0850x; 1.0719x over previous
#include <cuda_runtime.h>
#include <cuda_fp16.h>
#include <math.h>
#include <cstdint>

#define V_SZ 32000
#define D_SZ 512
#define S_SZ 2048
#define H_SZ 8
#define HS_SZ 64
#define B_SZ 4
#define M_SZ (B_SZ * S_SZ)   // 8192 rows
#define NQKV (3 * D_SZ)      // 1536 stacked qkv cols
#define NCOLB (V_SZ / 256)   // 125 col blocks for partial lse

// scales (exact powers of two; cancel exactly)
#define X_SCALE 16.f
#define X_INV   0.0625f
#define V_SCALE 4.f          // v64 = (16x*w)*4 = 64*v

// ---------------- scratch (device globals; no runtime allocation) ----------
__device__ __half g_x_hi[M_SZ * D_SZ];                   // 16*x hi
__device__ __half g_x_lo[M_SZ * D_SZ];                   // 16*x lo
__device__ __half g_wt[NQKV * D_SZ];                     // qkv weights^T [1536, 512]
__device__ __half g_qh[B_SZ * H_SZ * S_SZ * HS_SZ];      // q fp16 [B,H,S,HS]
__device__ __half g_kh[B_SZ * H_SZ * S_SZ * HS_SZ];      // k fp16
__device__ __half g_vh[B_SZ * H_SZ * S_SZ * HS_SZ];      // 64*v hi
__device__ __half g_vl[B_SZ * H_SZ * S_SZ * HS_SZ];      // 64*v lo
__device__ __half g_a_hi[M_SZ * D_SZ];                   // 64*attn fp16 [B*S, D]
__device__ __half g_bt[(size_t)V_SZ * D_SZ];             // W_out^T fp16 [32000, 512]
__device__ float2 g_part[(size_t)M_SZ * NCOLB];          // per (row, colblock) (max, sumexp)
__device__ float g_rowloss[M_SZ];

// =================== PTX helpers (portable, compute_103-legal) =============
__device__ __forceinline__ uint32_t smem_u32(const void* p) {
    uint32_t a;
    asm("{ .reg .u64 t; cvta.to.shared.u64 t, %1; cvt.u32.u64 %0, t; }" : "=r"(a) : "l"(p));
    return a;
}
__device__ __forceinline__ void cp16(uint32_t dst, const void* src) {
    asm volatile("cp.async.cg.shared.global [%0], [%1], 16;" :: "r"(dst), "l"(src));
}
__device__ __forceinline__ void cp_commit() {
    asm volatile("cp.async.commit_group;" ::: "memory");
}
__device__ __forceinline__ void cp_wait0() {
    asm volatile("cp.async.wait_group 0;" ::: "memory");
}
__device__ __forceinline__ void ldsm_x4(uint32_t* r, uint32_t addr) {
    asm volatile("ldmatrix.sync.aligned.m8n8.x4.shared.b16 {%0,%1,%2,%3}, [%4];"
                 : "=r"(r[0]), "=r"(r[1]), "=r"(r[2]), "=r"(r[3]) : "r"(addr));
}
__device__ __forceinline__ void ldsm_x4_t(uint32_t* r, uint32_t addr) {
    asm volatile("ldmatrix.sync.aligned.m8n8.x4.trans.shared.b16 {%0,%1,%2,%3}, [%4];"
                 : "=r"(r[0]), "=r"(r[1]), "=r"(r[2]), "=r"(r[3]) : "r"(addr));
}
__device__ __forceinline__ void mma16816(float* c, const uint32_t* a, const uint32_t* b) {
    asm volatile("mma.sync.aligned.m16n8k16.row.col.f32.f16.f16.f32 "
                 "{%0,%1,%2,%3}, {%4,%5,%6,%7}, {%8,%9}, {%0,%1,%2,%3};"
                 : "+f"(c[0]), "+f"(c[1]), "+f"(c[2]), "+f"(c[3])
                 : "r"(a[0]), "r"(a[1]), "r"(a[2]), "r"(a[3]),
                   "r"(b[0]), "r"(b[1]));
}
__device__ __forceinline__ uint32_t pack_h2(float a, float b) {
    __half2 h = __halves2half2(__float2half(a), __float2half(b));
    return *(uint32_t*)&h;
}

// ---------------- 1) embeddings -> fp16 hi/lo (scaled x16) -----------------
__global__ void embed_kernel(const int* __restrict__ index,
                             const float* __restrict__ tok_emb,
                             const float* __restrict__ pos_emb) {
    int m = blockIdx.x;
    int s = m % S_SZ;
    int tok = index[m];
    const float4* te = (const float4*)(tok_emb + (size_t)tok * D_SZ);
    const float4* pe = (const float4*)(pos_emb + (size_t)s * D_SZ);
    int i = threadIdx.x;            // 128 threads, 4 floats each
    float4 a = te[i], b = pe[i];
    float x[4] = {(a.x + b.x) * X_SCALE, (a.y + b.y) * X_SCALE,
                  (a.z + b.z) * X_SCALE, (a.w + b.w) * X_SCALE};
    __half h[4], l[4];
#pragma unroll
    for (int j = 0; j < 4; j++) {
        h[j] = __float2half(x[j]);
        l[j] = __float2half(x[j] - __half2float(h[j]));
    }
    size_t o = (size_t)m * D_SZ + i * 4;
    *(uint2*)(g_x_hi + o) = *(uint2*)h;
    *(uint2*)(g_x_lo + o) = *(uint2*)l;
}

// ---------------- 2) qkv weight transpose: [H,D,HS]x3 -> [1536,512] fp16 ---
__global__ void wt_kernel(const float* __restrict__ Wq,
                          const float* __restrict__ Wk,
                          const float* __restrict__ Wv) {
    int n = blockIdx.x;                       // 0..1535
    int which = n >> 9;
    int h = (n >> 6) & 7;
    int e = n & 63;
    const float* W = (which == 0 ? Wq : which == 1 ? Wk : Wv) + (size_t)h * D_SZ * HS_SZ + e;
    __half* dst = g_wt + (size_t)n * D_SZ;
    int t = threadIdx.x;                      // 128 threads, 4 k's each
#pragma unroll
    for (int j = 0; j < 4; j++) {
        int k = t * 4 + j;
        dst[k] = __float2half(W[(size_t)k * HS_SZ]);
    }
}

// ---------------- 3) W_out transpose+convert: [512,V] -> [V,512] fp16 ------
__global__ void convB_kernel(const float* __restrict__ W) {
    __shared__ float tbuf[32][33];
    int v0 = blockIdx.x * 32, k0 = blockIdx.y * 32;
    int tx = threadIdx.x & 31;
    int ty4 = (threadIdx.x >> 5) * 4;
#pragma unroll
    for (int j = 0; j < 4; j++)
        tbuf[ty4 + j][tx] = W[(size_t)(k0 + ty4 + j) * V_SZ + v0 + tx];
    __syncthreads();
#pragma unroll
    for (int j = 0; j < 4; j++)
        g_bt[(size_t)(v0 + ty4 + j) * D_SZ + k0 + tx] = __float2half(tbuf[tx][ty4 + j]);
}

// ---------------- shared GEMM machinery -------------------------------------
// Tile 128x256, BK=64, 512 threads (16 warps 4m x 4n), warp tile 32x64.
// 2-stage, load-after-sync pipeline: 8 syncs per CTA.
// PITCH 144 = 128B data + 16B pad; row shift 4 banks -> conflict-free ldsm.
#define BM 128
#define BN 256
#define BKQ 64
#define PITCH 144
#define OPA (BM * PITCH)          // 18432
#define OPBX (BN * PITCH)         // 36864
#define QKV_DSMEM (2 * (2 * OPA + OPBX))   // 147456
#define LOG_DSMEM (2 * (OPA + OPBX))       // 110592

template <bool LO>
struct GemmCore {
    static constexpr int SS = (LO ? 2 : 1) * OPA + OPBX;   // stage bytes
    uint32_t sa;
    uint32_t a_lm, b_lm;
    int row0, col0, m_base, n_base, lane, wid;
    float acc[2][8][4];

    __device__ __forceinline__ void init(char* dsm) {
        int tid = threadIdx.x;
        lane = tid & 31;
        wid = tid >> 5;
        m_base = (wid & 3) * 32;
        n_base = (wid >> 2) * 64;
        sa = smem_u32(dsm);
        a_lm = (uint32_t)((m_base + (lane & 15)) * PITCH + (lane >> 4) * 16);
        b_lm = (uint32_t)((n_base + (lane & 15)) * PITCH + (lane >> 4) * 16);
#pragma unroll
        for (int i = 0; i < 2; i++)
#pragma unroll
            for (int j = 0; j < 8; j++)
#pragma unroll
                for (int k = 0; k < 4; k++) acc[i][j][k] = 0.f;
    }

    __device__ __forceinline__ void load_tile(const __half* Ah, const __half* Al,
                                              const __half* Bt, int kk, int stage) {
        int tid = threadIdx.x;
        // A: 128 rows x 8 chunks = 1024 chunks of 16B
#pragma unroll
        for (int it = 0; it < 2; it++) {
            int idx = it * 512 + tid;
            int r = idx >> 3, c = idx & 7;
            uint32_t d = (uint32_t)(stage * SS + r * PITCH + c * 16);
            cp16(sa + d, Ah + (size_t)(row0 + r) * D_SZ + kk + c * 8);
            if (LO)
                cp16(sa + OPA + d, Al + (size_t)(row0 + r) * D_SZ + kk + c * 8);
        }
        // B: 256 rows x 8 chunks = 2048 chunks
#pragma unroll
        for (int it = 0; it < 4; it++) {
            int idx = it * 512 + tid;
            int r = idx >> 3, c = idx & 7;
            uint32_t d = (uint32_t)(stage * SS + (LO ? 2 : 1) * OPA + r * PITCH + c * 16);
            cp16(sa + d, Bt + (size_t)(col0 + r) * D_SZ + kk + c * 8);
        }
    }

    __device__ __forceinline__ void mma_tile(int stage) {
        uint32_t ah = sa + (uint32_t)(stage * SS) + a_lm;
        uint32_t bb = sa + (uint32_t)(stage * SS + (LO ? 2 : 1) * OPA) + b_lm;
#pragma unroll
        for (int s = 0; s < 4; s++) {   // 4 k16-steps per BK=64
            uint32_t ahf[2][4], alf[2][4], bfr[4][4];
#pragma unroll
            for (int mf = 0; mf < 2; mf++) {
                ldsm_x4(ahf[mf], ah + (uint32_t)(mf * 16 * PITCH + s * 32));
                if (LO)
                    ldsm_x4(alf[mf], ah + OPA + (uint32_t)(mf * 16 * PITCH + s * 32));
            }
#pragma unroll
            for (int nf2 = 0; nf2 < 4; nf2++)
                ldsm_x4(bfr[nf2], bb + (uint32_t)(nf2 * 16 * PITCH + s * 32));
#pragma unroll
            for (int mf = 0; mf < 2; mf++)
#pragma unroll
                for (int nf = 0; nf < 8; nf++) {
                    uint32_t b2[2] = {bfr[nf >> 1][nf & 1], bfr[nf >> 1][(nf & 1) + 2]};
                    mma16816(acc[mf][nf], ahf[mf], b2);
                }
            if (LO) {
#pragma unroll
                for (int mf = 0; mf < 2; mf++)
#pragma unroll
                    for (int nf = 0; nf < 8; nf++) {
                        uint32_t b2[2] = {bfr[nf >> 1][nf & 1], bfr[nf >> 1][(nf & 1) + 2]};
                        mma16816(acc[mf][nf], alf[mf], b2);
                    }
            }
        }
    }

    __device__ __forceinline__ void run(const __half* Ah, const __half* Al,
                                        const __half* Bt) {
        const int NITER = D_SZ / BKQ;   // 8
        load_tile(Ah, Al, Bt, 0, 0);
        cp_commit();
        for (int kt = 0; kt < NITER; kt++) {
            cp_wait0();          // drain load(kt) — the only group in flight
            __syncthreads();     // all warps done reading stage kt-1 & see kt
            if (kt + 1 < NITER) {
                load_tile(Ah, Al, Bt, (kt + 1) * BKQ, (kt + 1) & 1);
                cp_commit();
            }
            mma_tile(kt & 1);    // overlaps with load(kt+1)
        }
        __syncthreads();         // before epilogue smem reuse
    }
};

// ---------------- 4) qkv GEMM: [8192,512] x [512,1536] ---------------------
__global__ void __launch_bounds__(512, 1) qkv_gemm_kernel() {
    extern __shared__ __align__(16) char dsm[];
    GemmCore<true> g;
    g.init(dsm);
    g.row0 = blockIdx.y * BM;
    g.col0 = blockIdx.x * BN;
    g.run(g_x_hi, g_x_lo, g_wt);

    int n_gb = g.col0 + g.n_base;
    int which = n_gb >> 9;
    int hh = (n_gb >> 6) & 7;
    int rb = g.row0 + g.m_base + (g.lane >> 2);
#pragma unroll
    for (int mf = 0; mf < 2; mf++) {
#pragma unroll
        for (int nf = 0; nf < 8; nf++) {
            int e = (g.lane & 3) * 2 + nf * 8;
            int m0 = rb + mf * 16;
            int m1 = m0 + 8;
            size_t o0 = ((size_t)((m0 >> 11) * H_SZ + hh) * S_SZ + (m0 & 2047)) * HS_SZ + e;
            size_t o1 = ((size_t)((m1 >> 11) * H_SZ + hh) * S_SZ + (m1 & 2047)) * HS_SZ + e;
            float a0 = g.acc[mf][nf][0], a1 = g.acc[mf][nf][1];
            float a2 = g.acc[mf][nf][2], a3 = g.acc[mf][nf][3];
            if (which < 2) {
                __half* dst = which == 0 ? g_qh : g_kh;
                *(uint32_t*)(dst + o0) = pack_h2(a0 * X_INV, a1 * X_INV);
                *(uint32_t*)(dst + o1) = pack_h2(a2 * X_INV, a3 * X_INV);
            } else {
                float v0 = a0 * V_SCALE, v1 = a1 * V_SCALE;
                float v2 = a2 * V_SCALE, v3 = a3 * V_SCALE;
                __half h0 = __float2half(v0), h1 = __float2half(v1);
                __half h2v = __float2half(v2), h3 = __float2half(v3);
                *(uint32_t*)(g_vh + o0) = pack_h2(v0, v1);
                *(uint32_t*)(g_vh + o1) = pack_h2(v2, v3);
                *(uint32_t*)(g_vl + o0) = pack_h2(v0 - __half2float(h0), v1 - __half2float(h1));
                *(uint32_t*)(g_vl + o1) = pack_h2(v2 - __half2float(h2v), v3 - __half2float(h3));
            }
        }
    }
}

// ---------------- 5) logits GEMM (single-pass fp16) + fused partial lse ----
__global__ void __launch_bounds__(512, 1) logits_gemm_kernel(float* __restrict__ C) {
    extern __shared__ __align__(16) char dsm[];
    GemmCore<false> g;
    g.init(dsm);
    g.row0 = blockIdx.y * BM;
    g.col0 = blockIdx.x * BN;
    g.run(g_a_hi, nullptr, g_bt);

    const float ds = 1.f / 64.f;   // remove 64x A scale
    int rb = g.row0 + g.m_base + (g.lane >> 2);
    int cb = g.col0 + g.n_base + (g.lane & 3) * 2;
#pragma unroll
    for (int mf = 0; mf < 2; mf++)
#pragma unroll
        for (int nf = 0; nf < 8; nf++)
#pragma unroll
            for (int k = 0; k < 4; k++) g.acc[mf][nf][k] *= ds;

#pragma unroll
    for (int mf = 0; mf < 2; mf++) {
#pragma unroll
        for (int nf = 0; nf < 8; nf++) {
            size_t o0 = (size_t)(rb + mf * 16) * V_SZ + cb + nf * 8;
            size_t o1 = o0 + (size_t)8 * V_SZ;
            *(float2*)(C + o0) = make_float2(g.acc[mf][nf][0], g.acc[mf][nf][1]);
            *(float2*)(C + o1) = make_float2(g.acc[mf][nf][2], g.acc[mf][nf][3]);
        }
    }

    // partial (max, sumexp) over this CTA's 256 cols, per row
    float pm[2][2], ps[2][2];
#pragma unroll
    for (int mf = 0; mf < 2; mf++) {
#pragma unroll
        for (int h = 0; h < 2; h++) {
            float mx = -1e30f;
#pragma unroll
            for (int nf = 0; nf < 8; nf++)
                mx = fmaxf(mx, fmaxf(g.acc[mf][nf][h * 2], g.acc[mf][nf][h * 2 + 1]));
            mx = fmaxf(mx, __shfl_xor_sync(0xffffffffu, mx, 1));
            mx = fmaxf(mx, __shfl_xor_sync(0xffffffffu, mx, 2));
            float sm = 0.f;
#pragma unroll
            for (int nf = 0; nf < 8; nf++)
                sm += __expf(g.acc[mf][nf][h * 2] - mx) + __expf(g.acc[mf][nf][h * 2 + 1] - mx);
            sm += __shfl_xor_sync(0xffffffffu, sm, 1);
            sm += __shfl_xor_sync(0xffffffffu, sm, 2);
            pm[mf][h] = mx;
            ps[mf][h] = sm;
        }
    }
    float2* part = (float2*)dsm;   // [128][4]
    if ((g.lane & 3) == 0) {
#pragma unroll
        for (int mf = 0; mf < 2; mf++)
#pragma unroll
            for (int h = 0; h < 2; h++) {
                int rt = g.m_base + mf * 16 + h * 8 + (g.lane >> 2);
                part[rt * 4 + (g.wid >> 2)] = make_float2(pm[mf][h], ps[mf][h]);
            }
    }
    __syncthreads();
    int tid = threadIdx.x;
    if (tid < 128) {
        float M = -1e30f, S = 0.f;
#pragma unroll
        for (int qd = 0; qd < 4; qd++) {
            float2 p = part[tid * 4 + qd];
            float nm = fmaxf(M, p.x);
            S = S * __expf(M - nm) + p.y * __expf(p.x - nm);
            M = nm;
        }
        g_part[(size_t)(g.row0 + tid) * NCOLB + blockIdx.x] = make_float2(M, S);
    }
}

// ---------------- 6) tensor-core flash attention ----------------------------
// Block 128 thr (4 warps), 64 queries per block. 1 sync per KV tile.
#define AP 144
#define QTILE (64 * AP)
#define KVSTAGE (3 * QTILE)
#define ATTN_SMEM (QTILE + 2 * KVSTAGE)

__global__ void attn_kernel() {
    extern __shared__ __align__(16) char smema[];
    uint32_t sbse = smem_u32(smema);

    int qt = (int)gridDim.x - 1 - (int)blockIdx.x;   // longest first
    int h = blockIdx.y, b = blockIdx.z;
    int tid = threadIdx.x;
    int lane = tid & 31;
    int w = tid >> 5;
    size_t base = (size_t)(b * H_SZ + h) * S_SZ * HS_SZ;

    auto ldkv = [&](int kt, int buf) {
        uint32_t db = sbse + QTILE + (uint32_t)(buf * KVSTAGE);
#pragma unroll
        for (int it = 0; it < 4; it++) {
            int idx = it * 128 + tid;
            int r = idx >> 3, c = idx & 7;
            uint32_t off = (uint32_t)(r * AP + c * 16);
            size_t src = base + (size_t)(kt * 64 + r) * HS_SZ + c * 8;
            cp16(db + off, g_kh + src);
            cp16(db + QTILE + off, g_vh + src);
            cp16(db + 2 * QTILE + off, g_vl + src);
        }
    };

    // prologue: Q tile + KV tile 0 (one group)
    {
#pragma unroll
        for (int it = 0; it < 4; it++) {
            int idx = it * 128 + tid;
            int r = idx >> 3, c = idx & 7;
            cp16(sbse + (uint32_t)(r * AP + c * 16),
                 g_qh + base + (size_t)(qt * 64 + r) * HS_SZ + c * 8);
        }
        ldkv(0, 0);
        cp_commit();
    }

    const uint32_t q_lm = sbse + (uint32_t)((w * 16 + (lane & 15)) * AP + (lane >> 4) * 16);
    const uint32_t o_lm = (uint32_t)((lane & 15) * AP + (lane >> 4) * 16);

    float oacc[8][4];
#pragma unroll
    for (int f = 0; f < 8; f++)
#pragma unroll
        for (int k = 0; k < 4; k++) oacc[f][k] = 0.f;
    float m0 = -1e30f, m1 = -1e30f, l0 = 0.f, l1 = 0.f;
    uint32_t qf[4][4];

    int ntiles = qt + 1;
    for (int kt = 0; kt < ntiles; kt++) {
        int buf = kt & 1;
        cp_wait0();           // drain load(kt)
        __syncthreads();      // everyone done with buf^1 from iter kt-1
        if (kt == 0) {
#pragma unroll
            for (int kf = 0; kf < 4; kf++) ldsm_x4(qf[kf], q_lm + kf * 32);
        }
        if (kt + 1 < ntiles) {
            ldkv(kt + 1, buf ^ 1);
            cp_commit();
        }

        uint32_t kb = sbse + QTILE + (uint32_t)(buf * KVSTAGE) + o_lm;
        float sacc[8][4];
#pragma unroll
        for (int f = 0; f < 8; f++)
#pragma unroll
            for (int k = 0; k < 4; k++) sacc[f][k] = 0.f;
#pragma unroll
        for (int ng = 0; ng < 4; ng++) {
#pragma unroll
            for (int s = 0; s < 4; s++) {
                uint32_t bf[4];
                ldsm_x4(bf, kb + (uint32_t)(ng * 16 * AP + s * 32));
                uint32_t b2a[2] = {bf[0], bf[2]};
                uint32_t b2b[2] = {bf[1], bf[3]};
                mma16816(sacc[2 * ng], qf[s], b2a);
                mma16816(sacc[2 * ng + 1], qf[s], b2b);
            }
        }
        int rloc = w * 16 + (lane >> 2);
#pragma unroll
        for (int f = 0; f < 8; f++) {
#pragma unroll
            for (int k = 0; k < 4; k++) sacc[f][k] *= 0.125f;
            if (kt == qt) {
                int colb = f * 8 + 2 * (lane & 3);
                if (colb > rloc) sacc[f][0] = -1e30f;
                if (colb + 1 > rloc) sacc[f][1] = -1e30f;
                if (colb > rloc + 8) sacc[f][2] = -1e30f;
                if (colb + 1 > rloc + 8) sacc[f][3] = -1e30f;
            }
        }
        float t0 = -1e30f, t1 = -1e30f;
#pragma unroll
        for (int f = 0; f < 8; f++) {
            t0 = fmaxf(t0, fmaxf(sacc[f][0], sacc[f][1]));
            t1 = fmaxf(t1, fmaxf(sacc[f][2], sacc[f][3]));
        }
        t0 = fmaxf(t0, __shfl_xor_sync(0xffffffffu, t0, 1));
        t0 = fmaxf(t0, __shfl_xor_sync(0xffffffffu, t0, 2));
        t1 = fmaxf(t1, __shfl_xor_sync(0xffffffffu, t1, 1));
        t1 = fmaxf(t1, __shfl_xor_sync(0xffffffffu, t1, 2));
        float nm0 = fmaxf(m0, t0), nm1 = fmaxf(m1, t1);
        float f0 = __expf(m0 - nm0), f1 = __expf(m1 - nm1);
        m0 = nm0; m1 = nm1;
        l0 *= f0; l1 *= f1;
#pragma unroll
        for (int f = 0; f < 8; f++) {
            oacc[f][0] *= f0; oacc[f][1] *= f0;
            oacc[f][2] *= f1; oacc[f][3] *= f1;
        }
        float al0 = 0.f, al1 = 0.f;
#pragma unroll
        for (int f = 0; f < 8; f++) {
            sacc[f][0] = __expf(sacc[f][0] - nm0);
            sacc[f][1] = __expf(sacc[f][1] - nm0);
            sacc[f][2] = __expf(sacc[f][2] - nm1);
            sacc[f][3] = __expf(sacc[f][3] - nm1);
            al0 += sacc[f][0] + sacc[f][1];
            al1 += sacc[f][2] + sacc[f][3];
        }
        al0 += __shfl_xor_sync(0xffffffffu, al0, 1);
        al0 += __shfl_xor_sync(0xffffffffu, al0, 2);
        al1 += __shfl_xor_sync(0xffffffffu, al1, 1);
        al1 += __shfl_xor_sync(0xffffffffu, al1, 2);
        l0 += al0; l1 += al1;

        uint32_t vb = sbse + QTILE + (uint32_t)(buf * KVSTAGE) + QTILE + o_lm;
#pragma unroll
        for (int s = 0; s < 4; s++) {
            uint32_t pah[4], pal[4];
            {
                float p00 = sacc[2 * s][0], p01 = sacc[2 * s][1];
                float p10 = sacc[2 * s][2], p11 = sacc[2 * s][3];
                float p20 = sacc[2 * s + 1][0], p21 = sacc[2 * s + 1][1];
                float p30 = sacc[2 * s + 1][2], p31 = sacc[2 * s + 1][3];
                __half h00 = __float2half(p00), h01 = __float2half(p01);
                __half h10 = __float2half(p10), h11 = __float2half(p11);
                __half h20 = __float2half(p20), h21 = __float2half(p21);
                __half h30 = __float2half(p30), h31 = __float2half(p31);
                pah[0] = pack_h2(p00, p01); pah[1] = pack_h2(p10, p11);
                pah[2] = pack_h2(p20, p21); pah[3] = pack_h2(p30, p31);
                pal[0] = pack_h2(p00 - __half2float(h00), p01 - __half2float(h01));
                pal[1] = pack_h2(p10 - __half2float(h10), p11 - __half2float(h11));
                pal[2] = pack_h2(p20 - __half2float(h20), p21 - __half2float(h21));
                pal[3] = pack_h2(p30 - __half2float(h30), p31 - __half2float(h31));
            }
#pragma unroll
            for (int ng = 0; ng < 4; ng++) {
                uint32_t vh4[4], vl4[4];
                ldsm_x4_t(vh4, vb + (uint32_t)(s * 16 * AP + ng * 32));
                ldsm_x4_t(vl4, vb + QTILE + (uint32_t)(s * 16 * AP + ng * 32));
                uint32_t bh0[2] = {vh4[0], vh4[1]};
                uint32_t bh1[2] = {vh4[2], vh4[3]};
                uint32_t bl0[2] = {vl4[0], vl4[1]};
                uint32_t bl1[2] = {vl4[2], vl4[3]};
                mma16816(oacc[2 * ng], pah, bh0);
                mma16816(oacc[2 * ng + 1], pah, bh1);
                mma16816(oacc[2 * ng], pah, bl0);
                mma16816(oacc[2 * ng + 1], pah, bl1);
                mma16816(oacc[2 * ng], pal, bh0);
                mma16816(oacc[2 * ng + 1], pal, bh1);
            }
        }
        // no trailing sync: next iter's top sync orders buf reuse
    }

    float inv0 = 1.f / l0, inv1 = 1.f / l1;
    int s0 = qt * 64 + w * 16 + (lane >> 2);
    int s1 = s0 + 8;
    size_t d0 = (size_t)(b * S_SZ + s0) * D_SZ + h * HS_SZ + 2 * (lane & 3);
    size_t d1 = (size_t)(b * S_SZ + s1) * D_SZ + h * HS_SZ + 2 * (lane & 3);
#pragma unroll
    for (int f = 0; f < 8; f++) {
        *(uint32_t*)(g_a_hi + d0 + f * 8) = pack_h2(oacc[f][0] * inv0, oacc[f][1] * inv0);
        *(uint32_t*)(g_a_hi + d1 + f * 8) = pack_h2(oacc[f][2] * inv1, oacc[f][3] * inv1);
    }
}

// ---------------- 7) combine partial lse + target pick ---------------------
__global__ void lse_combine_kernel(const float* __restrict__ C,
                                   const int* __restrict__ target) {
    int m = blockIdx.x * 8 + (threadIdx.x >> 5);
    int lane = threadIdx.x & 31;
    const float2* p = g_part + (size_t)m * NCOLB;
    float M = -1e30f, S = 0.f;
    for (int i = lane; i < NCOLB; i += 32) {
        float2 q = p[i];
        float nm = fmaxf(M, q.x);
        S = S * __expf(M - nm) + q.y * __expf(q.x - nm);
        M = nm;
    }
#pragma unroll
    for (int off = 16; off > 0; off >>= 1) {
        float m2 = __shfl_xor_sync(0xffffffffu, M, off);
        float s2 = __shfl_xor_sync(0xffffffffu, S, off);
        float nm = fmaxf(M, m2);
        S = S * __expf(M - nm) + s2 * __expf(m2 - nm);
        M = nm;
    }
    if (lane == 0)
        g_rowloss[m] = M + logf(S) - C[(size_t)m * V_SZ + target[m]];
}

// ---------------- 8) deterministic mean reduction --------------------------
__global__ void loss_reduce_kernel(float* __restrict__ out, int loss_idx) {
    __shared__ float red[256];
    int tid = threadIdx.x;
    float s = 0.f;
    for (int i = tid; i < M_SZ; i += 256) s += g_rowloss[i];
    red[tid] = s;
    __syncthreads();
    for (int k = 128; k > 0; k >>= 1) {
        if (tid < k) red[tid] += red[tid + k];
        __syncthreads();
    }
    if (tid == 0) out[loss_idx] = red[0] / (float)M_SZ;
}

// ---------------- launch ----------------------------------------------------
extern "C" void kernel_launch(void* const* d_in, const int* in_sizes, int n_in,
                              void* d_out, int out_size) {
    const int* index = (const int*)d_in[0];
    const int* target = (const int*)d_in[1];
    const float* tok_emb = (const float*)d_in[2];
    const float* pos_emb = (const float*)d_in[3];
    const float* Wq = (const float*)d_in[4];
    const float* Wk = (const float*)d_in[5];
    const float* Wv = (const float*)d_in[6];
    const float* Wout = (const float*)d_in[7];
    float* out = (float*)d_out;

    cudaFuncSetAttribute(qkv_gemm_kernel,
                         cudaFuncAttributeMaxDynamicSharedMemorySize, QKV_DSMEM);
    cudaFuncSetAttribute(logits_gemm_kernel,
                         cudaFuncAttributeMaxDynamicSharedMemorySize, LOG_DSMEM);
    cudaFuncSetAttribute(attn_kernel,
                         cudaFuncAttributeMaxDynamicSharedMemorySize, ATTN_SMEM);

    embed_kernel<<<M_SZ, 128>>>(index, tok_emb, pos_emb);
    wt_kernel<<<NQKV, 128>>>(Wq, Wk, Wv);
    convB_kernel<<<dim3(V_SZ / 32, D_SZ / 32), 256>>>(Wout);
    qkv_gemm_kernel<<<dim3(NQKV / BN, M_SZ / BM), 512, QKV_DSMEM>>>();
    attn_kernel<<<dim3(S_SZ / 64, H_SZ, B_SZ), 128, ATTN_SMEM>>>();
    logits_gemm_kernel<<<dim3(V_SZ / BN, M_SZ / BM), 512, LOG_DSMEM>>>(out);
    lse_combine_kernel<<<M_SZ / 8, 256>>>(out, target);
    loss_reduce_kernel<<<1, 256>>>(out, out_size - 1);
}

// round 9
// speedup vs baseline: 6.0856x; 1.0001x over previous
#include <cuda_runtime.h>
#include <cuda_fp16.h>
#include <math.h>
#include <cstdint>

#define V_SZ 32000
#define D_SZ 512
#define S_SZ 2048
#define H_SZ 8
#define HS_SZ 64
#define B_SZ 4
#define M_SZ (B_SZ * S_SZ)   // 8192 rows
#define NQKV (3 * D_SZ)      // 1536 stacked qkv cols
#define NCOLB (V_SZ / 256)   // 125 col blocks for partial lse

// scales (exact powers of two; cancel exactly)
#define X_SCALE 16.f
#define X_INV   0.0625f
#define V_SCALE 4.f          // v64 = (16x*w)*4 = 64*v

// ---------------- scratch (device globals; no runtime allocation) ----------
__device__ __half g_x_hi[M_SZ * D_SZ];                   // 16*x hi
__device__ __half g_x_lo[M_SZ * D_SZ];                   // 16*x lo
__device__ __half g_wt[NQKV * D_SZ];                     // qkv weights^T [1536, 512]
__device__ __half g_qh[B_SZ * H_SZ * S_SZ * HS_SZ];      // q fp16 [B,H,S,HS]
__device__ __half g_kh[B_SZ * H_SZ * S_SZ * HS_SZ];      // k fp16
__device__ __half g_vh[B_SZ * H_SZ * S_SZ * HS_SZ];      // 64*v hi
__device__ __half g_vl[B_SZ * H_SZ * S_SZ * HS_SZ];      // 64*v lo
__device__ __half g_a_hi[M_SZ * D_SZ];                   // 64*attn fp16 [B*S, D]
__device__ __half g_bt[(size_t)V_SZ * D_SZ];             // W_out^T fp16 [32000, 512]
__device__ float2 g_part[(size_t)M_SZ * NCOLB];          // per (row, colblock) (max, sumexp)
__device__ float g_rowloss[M_SZ];

// =================== PTX helpers (portable, compute_103-legal) =============
__device__ __forceinline__ uint32_t smem_u32(const void* p) {
    uint32_t a;
    asm("{ .reg .u64 t; cvta.to.shared.u64 t, %1; cvt.u32.u64 %0, t; }" : "=r"(a) : "l"(p));
    return a;
}
__device__ __forceinline__ void cp16(uint32_t dst, const void* src) {
    asm volatile("cp.async.cg.shared.global [%0], [%1], 16;" :: "r"(dst), "l"(src));
}
__device__ __forceinline__ void cp_commit() {
    asm volatile("cp.async.commit_group;" ::: "memory");
}
__device__ __forceinline__ void cp_wait0() {
    asm volatile("cp.async.wait_group 0;" ::: "memory");
}
__device__ __forceinline__ void ldsm_x4(uint32_t* r, uint32_t addr) {
    asm volatile("ldmatrix.sync.aligned.m8n8.x4.shared.b16 {%0,%1,%2,%3}, [%4];"
                 : "=r"(r[0]), "=r"(r[1]), "=r"(r[2]), "=r"(r[3]) : "r"(addr));
}
__device__ __forceinline__ void ldsm_x4_t(uint32_t* r, uint32_t addr) {
    asm volatile("ldmatrix.sync.aligned.m8n8.x4.trans.shared.b16 {%0,%1,%2,%3}, [%4];"
                 : "=r"(r[0]), "=r"(r[1]), "=r"(r[2]), "=r"(r[3]) : "r"(addr));
}
__device__ __forceinline__ void mma16816(float* c, const uint32_t* a, const uint32_t* b) {
    asm volatile("mma.sync.aligned.m16n8k16.row.col.f32.f16.f16.f32 "
                 "{%0,%1,%2,%3}, {%4,%5,%6,%7}, {%8,%9}, {%0,%1,%2,%3};"
                 : "+f"(c[0]), "+f"(c[1]), "+f"(c[2]), "+f"(c[3])
                 : "r"(a[0]), "r"(a[1]), "r"(a[2]), "r"(a[3]),
                   "r"(b[0]), "r"(b[1]));
}
__device__ __forceinline__ uint32_t pack_h2(float a, float b) {
    __half2 h = __halves2half2(__float2half(a), __float2half(b));
    return *(uint32_t*)&h;
}

// ---------------- 1) embeddings -> fp16 hi/lo (scaled x16) -----------------
__global__ void embed_kernel(const int* __restrict__ index,
                             const float* __restrict__ tok_emb,
                             const float* __restrict__ pos_emb) {
    int m = blockIdx.x;
    int s = m % S_SZ;
    int tok = index[m];
    const float4* te = (const float4*)(tok_emb + (size_t)tok * D_SZ);
    const float4* pe = (const float4*)(pos_emb + (size_t)s * D_SZ);
    int i = threadIdx.x;            // 128 threads, 4 floats each
    float4 a = te[i], b = pe[i];
    float x[4] = {(a.x + b.x) * X_SCALE, (a.y + b.y) * X_SCALE,
                  (a.z + b.z) * X_SCALE, (a.w + b.w) * X_SCALE};
    __half h[4], l[4];
#pragma unroll
    for (int j = 0; j < 4; j++) {
        h[j] = __float2half(x[j]);
        l[j] = __float2half(x[j] - __half2float(h[j]));
    }
    size_t o = (size_t)m * D_SZ + i * 4;
    *(uint2*)(g_x_hi + o) = *(uint2*)h;
    *(uint2*)(g_x_lo + o) = *(uint2*)l;
}

// ---------------- 2) qkv weight transpose: [H,D,HS]x3 -> [1536,512] fp16 ---
__global__ void wt_kernel(const float* __restrict__ Wq,
                          const float* __restrict__ Wk,
                          const float* __restrict__ Wv) {
    int n = blockIdx.x;                       // 0..1535
    int which = n >> 9;
    int h = (n >> 6) & 7;
    int e = n & 63;
    const float* W = (which == 0 ? Wq : which == 1 ? Wk : Wv) + (size_t)h * D_SZ * HS_SZ + e;
    __half* dst = g_wt + (size_t)n * D_SZ;
    int t = threadIdx.x;                      // 128 threads, 4 k's each
#pragma unroll
    for (int j = 0; j < 4; j++) {
        int k = t * 4 + j;
        dst[k] = __float2half(W[(size_t)k * HS_SZ]);
    }
}

// ---------------- 3) W_out transpose+convert: [512,V] -> [V,512] fp16 ------
__global__ void convB_kernel(const float* __restrict__ W) {
    __shared__ float tbuf[32][33];
    int v0 = blockIdx.x * 32, k0 = blockIdx.y * 32;
    int tx = threadIdx.x & 31;
    int ty4 = (threadIdx.x >> 5) * 4;
#pragma unroll
    for (int j = 0; j < 4; j++)
        tbuf[ty4 + j][tx] = W[(size_t)(k0 + ty4 + j) * V_SZ + v0 + tx];
    __syncthreads();
#pragma unroll
    for (int j = 0; j < 4; j++)
        g_bt[(size_t)(v0 + ty4 + j) * D_SZ + k0 + tx] = __float2half(tbuf[tx][ty4 + j]);
}

// ---------------- shared GEMM machinery -------------------------------------
// Tile 128x256, BK=64, 256 threads (8 warps 2m x 4n), warp tile 64x64.
// 2-stage, load-after-sync pipeline. MMA:LDSM = 4.0 (was 2.67).
// PITCH 144 = 128B row + 16B pad; row shift 4 banks -> conflict-free ldsm.
#define BM 128
#define BN 256
#define BKQ 64
#define PITCH 144
#define OPA (BM * PITCH)          // 18432
#define OPBX (BN * PITCH)         // 36864
#define QKV_DSMEM (2 * (2 * OPA + OPBX))   // 147456
#define LOG_DSMEM (2 * (OPA + OPBX))       // 110592

template <bool LO>
struct GemmCore {
    static constexpr int SS = (LO ? 2 : 1) * OPA + OPBX;   // stage bytes
    uint32_t sa;
    uint32_t a_lm, b_lm;
    int row0, col0, m_base, n_base, lane, wid;
    float acc[4][8][4];                 // 64x64 warp tile

    __device__ __forceinline__ void init(char* dsm) {
        int tid = threadIdx.x;
        lane = tid & 31;
        wid = tid >> 5;
        m_base = (wid & 1) * 64;
        n_base = (wid >> 1) * 64;
        sa = smem_u32(dsm);
        a_lm = (uint32_t)((m_base + (lane & 15)) * PITCH + (lane >> 4) * 16);
        b_lm = (uint32_t)((n_base + (lane & 15)) * PITCH + (lane >> 4) * 16);
#pragma unroll
        for (int i = 0; i < 4; i++)
#pragma unroll
            for (int j = 0; j < 8; j++)
#pragma unroll
                for (int k = 0; k < 4; k++) acc[i][j][k] = 0.f;
    }

    __device__ __forceinline__ void load_tile(const __half* Ah, const __half* Al,
                                              const __half* Bt, int kk, int stage) {
        int tid = threadIdx.x;
        // A: 128 rows x 8 chunks = 1024 chunks of 16B
#pragma unroll
        for (int it = 0; it < 4; it++) {
            int idx = it * 256 + tid;
            int r = idx >> 3, c = idx & 7;
            uint32_t d = (uint32_t)(stage * SS + r * PITCH + c * 16);
            cp16(sa + d, Ah + (size_t)(row0 + r) * D_SZ + kk + c * 8);
            if (LO)
                cp16(sa + OPA + d, Al + (size_t)(row0 + r) * D_SZ + kk + c * 8);
        }
        // B: 256 rows x 8 chunks = 2048 chunks
#pragma unroll
        for (int it = 0; it < 8; it++) {
            int idx = it * 256 + tid;
            int r = idx >> 3, c = idx & 7;
            uint32_t d = (uint32_t)(stage * SS + (LO ? 2 : 1) * OPA + r * PITCH + c * 16);
            cp16(sa + d, Bt + (size_t)(col0 + r) * D_SZ + kk + c * 8);
        }
    }

    __device__ __forceinline__ void mma_tile(int stage) {
        uint32_t ah = sa + (uint32_t)(stage * SS) + a_lm;
        uint32_t bb = sa + (uint32_t)(stage * SS + (LO ? 2 : 1) * OPA) + b_lm;
#pragma unroll
        for (int s = 0; s < 4; s++) {   // 4 k16-steps per BK=64
            uint32_t ahf[4][4], alf[4][4], bfr[4][4];
#pragma unroll
            for (int mf = 0; mf < 4; mf++) {
                ldsm_x4(ahf[mf], ah + (uint32_t)(mf * 16 * PITCH + s * 32));
                if (LO)
                    ldsm_x4(alf[mf], ah + OPA + (uint32_t)(mf * 16 * PITCH + s * 32));
            }
#pragma unroll
            for (int nf2 = 0; nf2 < 4; nf2++)
                ldsm_x4(bfr[nf2], bb + (uint32_t)(nf2 * 16 * PITCH + s * 32));
#pragma unroll
            for (int mf = 0; mf < 4; mf++)
#pragma unroll
                for (int nf = 0; nf < 8; nf++) {
                    uint32_t b2[2] = {bfr[nf >> 1][nf & 1], bfr[nf >> 1][(nf & 1) + 2]};
                    mma16816(acc[mf][nf], ahf[mf], b2);
                }
            if (LO) {
#pragma unroll
                for (int mf = 0; mf < 4; mf++)
#pragma unroll
                    for (int nf = 0; nf < 8; nf++) {
                        uint32_t b2[2] = {bfr[nf >> 1][nf & 1], bfr[nf >> 1][(nf & 1) + 2]};
                        mma16816(acc[mf][nf], alf[mf], b2);
                    }
            }
        }
    }

    __device__ __forceinline__ void run(const __half* Ah, const __half* Al,
                                        const __half* Bt) {
        const int NITER = D_SZ / BKQ;   // 8
        load_tile(Ah, Al, Bt, 0, 0);
        cp_commit();
        for (int kt = 0; kt < NITER; kt++) {
            cp_wait0();          // drain load(kt)
            __syncthreads();     // all warps done reading stage kt-1 & see kt
            if (kt + 1 < NITER) {
                load_tile(Ah, Al, Bt, (kt + 1) * BKQ, (kt + 1) & 1);
                cp_commit();
            }
            mma_tile(kt & 1);    // overlaps with load(kt+1)
        }
        __syncthreads();         // before epilogue smem reuse
    }
};

// ---------------- 4) qkv GEMM: [8192,512] x [512,1536] ---------------------
__global__ void __launch_bounds__(256, 1) qkv_gemm_kernel() {
    extern __shared__ __align__(16) char dsm[];
    GemmCore<true> g;
    g.init(dsm);
    g.row0 = blockIdx.y * BM;
    g.col0 = blockIdx.x * BN;
    g.run(g_x_hi, g_x_lo, g_wt);

    // epilogue: warp spans 64 cols aligned to one head of one of q/k/v
    int n_gb = g.col0 + g.n_base;
    int which = n_gb >> 9;
    int hh = (n_gb >> 6) & 7;
    int rb = g.row0 + g.m_base + (g.lane >> 2);
#pragma unroll
    for (int mf = 0; mf < 4; mf++) {
#pragma unroll
        for (int nf = 0; nf < 8; nf++) {
            int e = (g.lane & 3) * 2 + nf * 8;
            int m0 = rb + mf * 16;
            int m1 = m0 + 8;
            size_t o0 = ((size_t)((m0 >> 11) * H_SZ + hh) * S_SZ + (m0 & 2047)) * HS_SZ + e;
            size_t o1 = ((size_t)((m1 >> 11) * H_SZ + hh) * S_SZ + (m1 & 2047)) * HS_SZ + e;
            float a0 = g.acc[mf][nf][0], a1 = g.acc[mf][nf][1];
            float a2 = g.acc[mf][nf][2], a3 = g.acc[mf][nf][3];
            if (which < 2) {
                __half* dst = which == 0 ? g_qh : g_kh;
                *(uint32_t*)(dst + o0) = pack_h2(a0 * X_INV, a1 * X_INV);
                *(uint32_t*)(dst + o1) = pack_h2(a2 * X_INV, a3 * X_INV);
            } else {
                float v0 = a0 * V_SCALE, v1 = a1 * V_SCALE;
                float v2 = a2 * V_SCALE, v3 = a3 * V_SCALE;
                __half h0 = __float2half(v0), h1 = __float2half(v1);
                __half h2v = __float2half(v2), h3 = __float2half(v3);
                *(uint32_t*)(g_vh + o0) = pack_h2(v0, v1);
                *(uint32_t*)(g_vh + o1) = pack_h2(v2, v3);
                *(uint32_t*)(g_vl + o0) = pack_h2(v0 - __half2float(h0), v1 - __half2float(h1));
                *(uint32_t*)(g_vl + o1) = pack_h2(v2 - __half2float(h2v), v3 - __half2float(h3));
            }
        }
    }
}

// ---------------- 5) logits GEMM (single-pass fp16) + fused partial lse ----
__global__ void __launch_bounds__(256, 1) logits_gemm_kernel(float* __restrict__ C) {
    extern __shared__ __align__(16) char dsm[];
    GemmCore<false> g;
    g.init(dsm);
    g.row0 = blockIdx.y * BM;
    g.col0 = blockIdx.x * BN;
    g.run(g_a_hi, nullptr, g_bt);

    const float ds = 1.f / 64.f;   // remove 64x A scale
    int rb = g.row0 + g.m_base + (g.lane >> 2);
    int cb = g.col0 + g.n_base + (g.lane & 3) * 2;
#pragma unroll
    for (int mf = 0; mf < 4; mf++)
#pragma unroll
        for (int nf = 0; nf < 8; nf++)
#pragma unroll
            for (int k = 0; k < 4; k++) g.acc[mf][nf][k] *= ds;

#pragma unroll
    for (int mf = 0; mf < 4; mf++) {
#pragma unroll
        for (int nf = 0; nf < 8; nf++) {
            size_t o0 = (size_t)(rb + mf * 16) * V_SZ + cb + nf * 8;
            size_t o1 = o0 + (size_t)8 * V_SZ;
            *(float2*)(C + o0) = make_float2(g.acc[mf][nf][0], g.acc[mf][nf][1]);
            *(float2*)(C + o1) = make_float2(g.acc[mf][nf][2], g.acc[mf][nf][3]);
        }
    }

    // partial (max, sumexp): warp covers 64 rows x 64 cols; 4 col-groups/CTA
    float2* part = (float2*)dsm;   // [128 rows][4 colgroups]
#pragma unroll
    for (int mf = 0; mf < 4; mf++) {
#pragma unroll
        for (int h = 0; h < 2; h++) {
            float mx = -1e30f;
#pragma unroll
            for (int nf = 0; nf < 8; nf++)
                mx = fmaxf(mx, fmaxf(g.acc[mf][nf][h * 2], g.acc[mf][nf][h * 2 + 1]));
            mx = fmaxf(mx, __shfl_xor_sync(0xffffffffu, mx, 1));
            mx = fmaxf(mx, __shfl_xor_sync(0xffffffffu, mx, 2));
            float sm = 0.f;
#pragma unroll
            for (int nf = 0; nf < 8; nf++)
                sm += __expf(g.acc[mf][nf][h * 2] - mx) + __expf(g.acc[mf][nf][h * 2 + 1] - mx);
            sm += __shfl_xor_sync(0xffffffffu, sm, 1);
            sm += __shfl_xor_sync(0xffffffffu, sm, 2);
            if ((g.lane & 3) == 0) {
                int rt = g.m_base + mf * 16 + h * 8 + (g.lane >> 2);
                part[rt * 4 + (g.wid >> 1)] = make_float2(mx, sm);
            }
        }
    }
    __syncthreads();
    int tid = threadIdx.x;
    if (tid < 128) {
        float M = -1e30f, S = 0.f;
#pragma unroll
        for (int qd = 0; qd < 4; qd++) {
            float2 p = part[tid * 4 + qd];
            float nm = fmaxf(M, p.x);
            S = S * __expf(M - nm) + p.y * __expf(p.x - nm);
            M = nm;
        }
        g_part[(size_t)(g.row0 + tid) * NCOLB + blockIdx.x] = make_float2(M, S);
    }
}

// ---------------- 6) tensor-core flash attention ----------------------------
// Block 128 thr (4 warps), 64 queries per block. PV: P fp16 x (Vh+Vl).
#define AP 144
#define QTILE (64 * AP)
#define KVSTAGE (3 * QTILE)
#define ATTN_SMEM (QTILE + 2 * KVSTAGE)

__global__ void attn_kernel() {
    extern __shared__ __align__(16) char smema[];
    uint32_t sbse = smem_u32(smema);

    int qt = (int)gridDim.x - 1 - (int)blockIdx.x;   // longest first
    int h = blockIdx.y, b = blockIdx.z;
    int tid = threadIdx.x;
    int lane = tid & 31;
    int w = tid >> 5;
    size_t base = (size_t)(b * H_SZ + h) * S_SZ * HS_SZ;

    auto ldkv = [&](int kt, int buf) {
        uint32_t db = sbse + QTILE + (uint32_t)(buf * KVSTAGE);
#pragma unroll
        for (int it = 0; it < 4; it++) {
            int idx = it * 128 + tid;
            int r = idx >> 3, c = idx & 7;
            uint32_t off = (uint32_t)(r * AP + c * 16);
            size_t src = base + (size_t)(kt * 64 + r) * HS_SZ + c * 8;
            cp16(db + off, g_kh + src);
            cp16(db + QTILE + off, g_vh + src);
            cp16(db + 2 * QTILE + off, g_vl + src);
        }
    };

    {
#pragma unroll
        for (int it = 0; it < 4; it++) {
            int idx = it * 128 + tid;
            int r = idx >> 3, c = idx & 7;
            cp16(sbse + (uint32_t)(r * AP + c * 16),
                 g_qh + base + (size_t)(qt * 64 + r) * HS_SZ + c * 8);
        }
        ldkv(0, 0);
        cp_commit();
    }

    const uint32_t q_lm = sbse + (uint32_t)((w * 16 + (lane & 15)) * AP + (lane >> 4) * 16);
    const uint32_t o_lm = (uint32_t)((lane & 15) * AP + (lane >> 4) * 16);

    float oacc[8][4];
#pragma unroll
    for (int f = 0; f < 8; f++)
#pragma unroll
        for (int k = 0; k < 4; k++) oacc[f][k] = 0.f;
    float m0 = -1e30f, m1 = -1e30f, l0 = 0.f, l1 = 0.f;
    uint32_t qf[4][4];

    int ntiles = qt + 1;
    for (int kt = 0; kt < ntiles; kt++) {
        int buf = kt & 1;
        cp_wait0();
        __syncthreads();
        if (kt == 0) {
#pragma unroll
            for (int kf = 0; kf < 4; kf++) ldsm_x4(qf[kf], q_lm + kf * 32);
        }
        if (kt + 1 < ntiles) {
            ldkv(kt + 1, buf ^ 1);
            cp_commit();
        }

        uint32_t kb = sbse + QTILE + (uint32_t)(buf * KVSTAGE) + o_lm;
        float sacc[8][4];
#pragma unroll
        for (int f = 0; f < 8; f++)
#pragma unroll
            for (int k = 0; k < 4; k++) sacc[f][k] = 0.f;
#pragma unroll
        for (int ng = 0; ng < 4; ng++) {
#pragma unroll
            for (int s = 0; s < 4; s++) {
                uint32_t bf[4];
                ldsm_x4(bf, kb + (uint32_t)(ng * 16 * AP + s * 32));
                uint32_t b2a[2] = {bf[0], bf[2]};
                uint32_t b2b[2] = {bf[1], bf[3]};
                mma16816(sacc[2 * ng], qf[s], b2a);
                mma16816(sacc[2 * ng + 1], qf[s], b2b);
            }
        }
        int rloc = w * 16 + (lane >> 2);
#pragma unroll
        for (int f = 0; f < 8; f++) {
#pragma unroll
            for (int k = 0; k < 4; k++) sacc[f][k] *= 0.125f;
            if (kt == qt) {
                int colb = f * 8 + 2 * (lane & 3);
                if (colb > rloc) sacc[f][0] = -1e30f;
                if (colb + 1 > rloc) sacc[f][1] = -1e30f;
                if (colb > rloc + 8) sacc[f][2] = -1e30f;
                if (colb + 1 > rloc + 8) sacc[f][3] = -1e30f;
            }
        }
        float t0 = -1e30f, t1 = -1e30f;
#pragma unroll
        for (int f = 0; f < 8; f++) {
            t0 = fmaxf(t0, fmaxf(sacc[f][0], sacc[f][1]));
            t1 = fmaxf(t1, fmaxf(sacc[f][2], sacc[f][3]));
        }
        t0 = fmaxf(t0, __shfl_xor_sync(0xffffffffu, t0, 1));
        t0 = fmaxf(t0, __shfl_xor_sync(0xffffffffu, t0, 2));
        t1 = fmaxf(t1, __shfl_xor_sync(0xffffffffu, t1, 1));
        t1 = fmaxf(t1, __shfl_xor_sync(0xffffffffu, t1, 2));
        float nm0 = fmaxf(m0, t0), nm1 = fmaxf(m1, t1);
        float f0 = __expf(m0 - nm0), f1 = __expf(m1 - nm1);
        m0 = nm0; m1 = nm1;
        l0 *= f0; l1 *= f1;
#pragma unroll
        for (int f = 0; f < 8; f++) {
            oacc[f][0] *= f0; oacc[f][1] *= f0;
            oacc[f][2] *= f1; oacc[f][3] *= f1;
        }
        float al0 = 0.f, al1 = 0.f;
#pragma unroll
        for (int f = 0; f < 8; f++) {
            sacc[f][0] = __expf(sacc[f][0] - nm0);
            sacc[f][1] = __expf(sacc[f][1] - nm0);
            sacc[f][2] = __expf(sacc[f][2] - nm1);
            sacc[f][3] = __expf(sacc[f][3] - nm1);
            al0 += sacc[f][0] + sacc[f][1];
            al1 += sacc[f][2] + sacc[f][3];
        }
        al0 += __shfl_xor_sync(0xffffffffu, al0, 1);
        al0 += __shfl_xor_sync(0xffffffffu, al0, 2);
        al1 += __shfl_xor_sync(0xffffffffu, al1, 1);
        al1 += __shfl_xor_sync(0xffffffffu, al1, 2);
        l0 += al0; l1 += al1;

        uint32_t vb = sbse + QTILE + (uint32_t)(buf * KVSTAGE) + QTILE + o_lm;
#pragma unroll
        for (int s = 0; s < 4; s++) {
            uint32_t pah[4];
            pah[0] = pack_h2(sacc[2 * s][0], sacc[2 * s][1]);
            pah[1] = pack_h2(sacc[2 * s][2], sacc[2 * s][3]);
            pah[2] = pack_h2(sacc[2 * s + 1][0], sacc[2 * s + 1][1]);
            pah[3] = pack_h2(sacc[2 * s + 1][2], sacc[2 * s + 1][3]);
#pragma unroll
            for (int ng = 0; ng < 4; ng++) {
                uint32_t vh4[4], vl4[4];
                ldsm_x4_t(vh4, vb + (uint32_t)(s * 16 * AP + ng * 32));
                ldsm_x4_t(vl4, vb + QTILE + (uint32_t)(s * 16 * AP + ng * 32));
                uint32_t bh0[2] = {vh4[0], vh4[1]};
                uint32_t bh1[2] = {vh4[2], vh4[3]};
                uint32_t bl0[2] = {vl4[0], vl4[1]};
                uint32_t bl1[2] = {vl4[2], vl4[3]};
                mma16816(oacc[2 * ng], pah, bh0);
                mma16816(oacc[2 * ng + 1], pah, bh1);
                mma16816(oacc[2 * ng], pah, bl0);
                mma16816(oacc[2 * ng + 1], pah, bl1);
            }
        }
        // next iter's top sync orders buf reuse
    }

    float inv0 = 1.f / l0, inv1 = 1.f / l1;
    int s0 = qt * 64 + w * 16 + (lane >> 2);
    int s1 = s0 + 8;
    size_t d0 = (size_t)(b * S_SZ + s0) * D_SZ + h * HS_SZ + 2 * (lane & 3);
    size_t d1 = (size_t)(b * S_SZ + s1) * D_SZ + h * HS_SZ + 2 * (lane & 3);
#pragma unroll
    for (int f = 0; f < 8; f++) {
        *(uint32_t*)(g_a_hi + d0 + f * 8) = pack_h2(oacc[f][0] * inv0, oacc[f][1] * inv0);
        *(uint32_t*)(g_a_hi + d1 + f * 8) = pack_h2(oacc[f][2] * inv1, oacc[f][3] * inv1);
    }
}

// ---------------- 7) combine partial lse + target pick ---------------------
__global__ void lse_combine_kernel(const float* __restrict__ C,
                                   const int* __restrict__ target) {
    int m = blockIdx.x * 8 + (threadIdx.x >> 5);
    int lane = threadIdx.x & 31;
    const float2* p = g_part + (size_t)m * NCOLB;
    float M = -1e30f, S = 0.f;
    for (int i = lane; i < NCOLB; i += 32) {
        float2 q = p[i];
        float nm = fmaxf(M, q.x);
        S = S * __expf(M - nm) + q.y * __expf(q.x - nm);
        M = nm;
    }
#pragma unroll
    for (int off = 16; off > 0; off >>= 1) {
        float m2 = __shfl_xor_sync(0xffffffffu, M, off);
        float s2 = __shfl_xor_sync(0xffffffffu, S, off);
        float nm = fmaxf(M, m2);
        S = S * __expf(M - nm) + s2 * __expf(m2 - nm);
        M = nm;
    }
    if (lane == 0)
        g_rowloss[m] = M + logf(S) - C[(size_t)m * V_SZ + target[m]];
}

// ---------------- 8) deterministic mean reduction --------------------------
__global__ void loss_reduce_kernel(float* __restrict__ out, int loss_idx) {
    __shared__ float red[256];
    int tid = threadIdx.x;
    float s = 0.f;
    for (int i = tid; i < M_SZ; i += 256) s += g_rowloss[i];
    red[tid] = s;
    __syncthreads();
    for (int k = 128; k > 0; k >>= 1) {
        if (tid < k) red[tid] += red[tid + k];
        __syncthreads();
    }
    if (tid == 0) out[loss_idx] = red[0] / (float)M_SZ;
}

// ---------------- launch ----------------------------------------------------
extern "C" void kernel_launch(void* const* d_in, const int* in_sizes, int n_in,
                              void* d_out, int out_size) {
    const int* index = (const int*)d_in[0];
    const int* target = (const int*)d_in[1];
    const float* tok_emb = (const float*)d_in[2];
    const float* pos_emb = (const float*)d_in[3];
    const float* Wq = (const float*)d_in[4];
    const float* Wk = (const float*)d_in[5];
    const float* Wv = (const float*)d_in[6];
    const float* Wout = (const float*)d_in[7];
    float* out = (float*)d_out;

    cudaFuncSetAttribute(qkv_gemm_kernel,
                         cudaFuncAttributeMaxDynamicSharedMemorySize, QKV_DSMEM);
    cudaFuncSetAttribute(logits_gemm_kernel,
                         cudaFuncAttributeMaxDynamicSharedMemorySize, LOG_DSMEM);
    cudaFuncSetAttribute(attn_kernel,
                         cudaFuncAttributeMaxDynamicSharedMemorySize, ATTN_SMEM);

    embed_kernel<<<M_SZ, 128>>>(index, tok_emb, pos_emb);
    wt_kernel<<<NQKV, 128>>>(Wq, Wk, Wv);
    convB_kernel<<<dim3(V_SZ / 32, D_SZ / 32), 256>>>(Wout);
    qkv_gemm_kernel<<<dim3(NQKV / BN, M_SZ / BM), 256, QKV_DSMEM>>>();
    attn_kernel<<<dim3(S_SZ / 64, H_SZ, B_SZ), 128, ATTN_SMEM>>>();
    logits_gemm_kernel<<<dim3(V_SZ / BN, M_SZ / BM), 256, LOG_DSMEM>>>(out);
    lse_combine_kernel<<<M_SZ / 8, 256>>>(out, target);
    loss_reduce_kernel<<<1, 256>>>(out, out_size - 1);
}